// round 1
// baseline (speedup 1.0000x reference)
#include <cuda_runtime.h>
#include <math.h>

#define BB 16
#define CC 512
#define HWDIM 1024
#define NN 16384            // B*H*W
#define MM 1024
#define NSPLIT 64
#define UQ_STRIDE (2*CC*HWDIM)          // per-batch stride of updated_query = 1048576

// output offsets (floats)
#define OFF_UQ   ((size_t)0)
#define OFF_UMEM ((size_t)BB*UQ_STRIDE)                  // 16777216
#define OFF_SQ   (OFF_UMEM + (size_t)MM*CC)              // 17301504
#define OFF_SM   (OFF_SQ + (size_t)NN*MM)                // 34078720
#define OFF_DIV  (OFF_SM + (size_t)NN*MM)                // 50855936
#define OFF_SIM  (OFF_DIV + 1)

// ---------------- scratch (static device globals; no runtime alloc) ----------------
__device__ float g_v[(size_t)NN*MM];     // exp(score), 64 MB
__device__ float g_rnorm[NN];
__device__ float g_rowmaxv[NN];
__device__ float g_rrowsum[NN];
__device__ int   g_argm[NN];
__device__ float g_w[NN];
__device__ float g_colmaxv[MM];
__device__ float g_rcolsum[MM];
__device__ float g_keynorm[MM];
__device__ float g_pmax[NSPLIT*MM];
__device__ float g_psum[NSPLIT*MM];
__device__ float g_qupd[MM*CC];
__device__ unsigned g_entmax_bits;

// ---------------- small kernels ----------------

__global__ void k_zero(float* out) {
    int i = blockIdx.x * blockDim.x + threadIdx.x;
    if (i < MM*CC) g_qupd[i] = 0.f;
    if (i == 0) {
        g_entmax_bits = 0u;
        out[OFF_DIV] = 0.f;
        out[OFF_SIM] = 0.f;
    }
}

__global__ void k_entmax(const float* __restrict__ ent) {
    int i = blockIdx.x * blockDim.x + threadIdx.x;
    if (i < NN) atomicMax(&g_entmax_bits, __float_as_uint(ent[i])); // entropy > 0
}

__global__ void k_keynorm(const float* __restrict__ keys) {
    int m = blockIdx.x;
    int t = threadIdx.x;   // 128 threads
    float s = 0.f;
    #pragma unroll
    for (int i = 0; i < 4; i++) {
        float v = keys[(size_t)m*CC + t + i*128];
        s += v*v;
    }
    // warp + smem reduce
    for (int o = 16; o > 0; o >>= 1) s += __shfl_down_sync(0xffffffffu, s, o);
    __shared__ float red[4];
    if ((t & 31) == 0) red[t >> 5] = s;
    __syncthreads();
    if (t == 0) g_keynorm[m] = sqrtf(red[0] + red[1] + red[2] + red[3]);
}

__global__ void k_rnorm(const float* __restrict__ q) {
    int n = blockIdx.x * blockDim.x + threadIdx.x;
    if (n >= NN) return;
    int b = n >> 10, hw = n & 1023;
    const float* base = q + (size_t)b*CC*HWDIM + hw;
    float s = 0.f;
    #pragma unroll 4
    for (int c = 0; c < CC; c++) {
        float v = base[(size_t)c*HWDIM];
        s += v*v;
    }
    g_rnorm[n] = 1.f / fmaxf(sqrtf(s), 1e-12f);
}

// qr written directly into updated_query channels [0, C) — same BCHW layout
__global__ void k_write_qr(const float* __restrict__ q, float* __restrict__ out) {
    int idx = blockIdx.x * blockDim.x + threadIdx.x;
    if (idx >= BB*CC*HWDIM) return;
    int b = idx >> 19;                 // / (C*HW) = /524288
    int rem = idx & ((CC*HWDIM) - 1);
    int hw = idx & 1023;
    int n = (b << 10) | hw;
    out[(size_t)b*UQ_STRIDE + rem] = q[idx] * g_rnorm[n];
}

// ---------------- score GEMM:  v[n,m] = exp( sum_k qr[n,k]*keys[m,k] ) ----------------
__global__ void __launch_bounds__(256) k_gemm_score(const float* __restrict__ uq,
                                                    const float* __restrict__ keys) {
    __shared__ float As[8][128];
    __shared__ float Bs[8][132];
    int t  = threadIdx.x;
    int m0 = blockIdx.x * 128;
    int n0 = blockIdx.y * 128;
    int b  = n0 >> 10;
    int hw0 = n0 & 1023;
    const float* Abase = uq + (size_t)b*UQ_STRIDE + hw0;
    int tx = t & 15, ty = t >> 4;

    float acc[8][8];
    #pragma unroll
    for (int i = 0; i < 8; i++)
        #pragma unroll
        for (int j = 0; j < 8; j++) acc[i][j] = 0.f;

    int akk = t >> 5;           // 0..7
    int ar  = (t & 31) << 2;    // 0..124
    int bm  = t >> 1;           // 0..127
    int bk4 = (t & 1) << 2;     // 0 or 4

    for (int k0 = 0; k0 < CC; k0 += 8) {
        float4 av = *reinterpret_cast<const float4*>(Abase + (size_t)(k0+akk)*HWDIM + ar);
        *reinterpret_cast<float4*>(&As[akk][ar]) = av;
        float4 bv = *reinterpret_cast<const float4*>(keys + (size_t)(m0+bm)*CC + k0 + bk4);
        Bs[bk4+0][bm] = bv.x; Bs[bk4+1][bm] = bv.y;
        Bs[bk4+2][bm] = bv.z; Bs[bk4+3][bm] = bv.w;
        __syncthreads();
        #pragma unroll
        for (int kk = 0; kk < 8; kk++) {
            float a[8], bb[8];
            #pragma unroll
            for (int i = 0; i < 8; i++) a[i]  = As[kk][ty*8 + i];
            #pragma unroll
            for (int j = 0; j < 8; j++) bb[j] = Bs[kk][tx*8 + j];
            #pragma unroll
            for (int i = 0; i < 8; i++)
                #pragma unroll
                for (int j = 0; j < 8; j++) acc[i][j] = fmaf(a[i], bb[j], acc[i][j]);
        }
        __syncthreads();
    }
    // epilogue: exp fused here (only place exp is computed per element)
    #pragma unroll
    for (int i = 0; i < 8; i++) {
        size_t row = (size_t)(n0 + ty*8 + i) * MM + m0 + tx*8;
        float4 o0, o1;
        o0.x = __expf(acc[i][0]); o0.y = __expf(acc[i][1]);
        o0.z = __expf(acc[i][2]); o0.w = __expf(acc[i][3]);
        o1.x = __expf(acc[i][4]); o1.y = __expf(acc[i][5]);
        o1.z = __expf(acc[i][6]); o1.w = __expf(acc[i][7]);
        *reinterpret_cast<float4*>(&g_v[row])     = o0;
        *reinterpret_cast<float4*>(&g_v[row + 4]) = o1;
    }
}

// ---------------- row reductions over v: rowmax, argmax (first-tie), rowsum ----------------
__global__ void k_rowreduce() {
    int n = blockIdx.x;
    int t = threadIdx.x;   // 256
    float4 v = reinterpret_cast<const float4*>(g_v + (size_t)n*MM)[t];
    float mx = v.x; int ix = t*4;
    if (v.y > mx) { mx = v.y; ix = t*4+1; }
    if (v.z > mx) { mx = v.z; ix = t*4+2; }
    if (v.w > mx) { mx = v.w; ix = t*4+3; }
    float s = v.x + v.y + v.z + v.w;
    __shared__ float smx[256]; __shared__ int six[256]; __shared__ float ssm[256];
    smx[t] = mx; six[t] = ix; ssm[t] = s;
    __syncthreads();
    for (int o = 128; o > 0; o >>= 1) {
        if (t < o) {
            float om = smx[t+o]; int oi = six[t+o];
            if (om > smx[t] || (om == smx[t] && oi < six[t])) { smx[t] = om; six[t] = oi; }
            ssm[t] += ssm[t+o];
        }
        __syncthreads();
    }
    if (t == 0) {
        g_rowmaxv[n] = smx[0];
        g_argm[n]    = six[0];
        g_rrowsum[n] = 1.f / ssm[0];
    }
}

// ---------------- column reductions (split over n, then merge) ----------------
__global__ void k_colpartial() {
    int m = blockIdx.x * 256 + threadIdx.x;
    int nbase = blockIdx.y * 256;
    float mx = 0.f, s = 0.f;
    #pragma unroll 4
    for (int r = 0; r < 256; r++) {
        float v = g_v[(size_t)(nbase + r)*MM + m];
        mx = fmaxf(mx, v);
        s += v;
    }
    g_pmax[blockIdx.y*MM + m] = mx;
    g_psum[blockIdx.y*MM + m] = s;
}

__global__ void k_colmerge() {
    int m = blockIdx.x * 256 + threadIdx.x;
    float mx = 0.f, s = 0.f;
    #pragma unroll 4
    for (int p = 0; p < NSPLIT; p++) {
        mx = fmaxf(mx, g_pmax[p*MM + m]);
        s += g_psum[p*MM + m];
    }
    g_colmaxv[m] = mx;
    g_rcolsum[m] = 1.f / s;
}

// ---------------- write sq & sm outputs ----------------
__global__ void k_sqsm(float* __restrict__ out) {
    int i = blockIdx.x * blockDim.x + threadIdx.x;   // float4 index
    size_t base = (size_t)i * 4;
    int n = (int)(base >> 10);
    int m = (int)(base & 1023);
    float4 v  = reinterpret_cast<const float4*>(g_v)[i];
    float4 rc = reinterpret_cast<const float4*>(g_rcolsum)[m >> 2];
    float  rr = g_rrowsum[n];
    float4 sq = make_float4(v.x*rc.x, v.y*rc.y, v.z*rc.z, v.w*rc.w);
    float4 sm = make_float4(v.x*rr,  v.y*rr,  v.z*rr,  v.w*rr);
    reinterpret_cast<float4*>(out + OFF_SQ)[i] = sq;
    reinterpret_cast<float4*>(out + OFF_SM)[i] = sm;
}

// ---------------- w[n] and similarity loss ----------------
__global__ void k_wsim(const float* __restrict__ ent, float* __restrict__ out) {
    int n = blockIdx.x * blockDim.x + threadIdx.x;
    float local = 0.f;
    if (n < NN) {
        int g = g_argm[n];
        float en = ent[n];
        float entmax = __uint_as_float(g_entmax_bits);
        g_w[n] = (g_rowmaxv[n] / g_colmaxv[g]) * (en / entmax);
        float smax = logf(g_rowmaxv[n]);                  // = max score of row n
        float cosv = smax / fmaxf(g_keynorm[g], 1e-8f);   // ||qr|| == 1
        local = (1.f - cosv) * en;
    }
    __shared__ float red[256];
    red[threadIdx.x] = local;
    __syncthreads();
    for (int o = 128; o > 0; o >>= 1) {
        if (threadIdx.x < o) red[threadIdx.x] += red[threadIdx.x + o];
        __syncthreads();
    }
    if (threadIdx.x == 0) atomicAdd(out + OFF_SIM, red[0]);
}

// ---------------- segment-sum: qupd[g[n], c] += w[n]*qr[n,c] ----------------
__global__ void k_segsum(const float* __restrict__ out) {
    int idx = blockIdx.x * blockDim.x + threadIdx.x;
    if (idx >= BB*CC*HWDIM) return;
    int b = idx >> 19;
    int rem = idx & ((CC*HWDIM) - 1);
    int c = rem >> 10;
    int hw = idx & 1023;
    int n = (b << 10) | hw;
    float val = out[(size_t)b*UQ_STRIDE + rem];           // qr in BCHW layout
    atomicAdd(&g_qupd[(size_t)g_argm[n]*CC + c], g_w[n] * val);
}

// ---------------- updated memory: l2norm(qupd + keys) ----------------
__global__ void k_umem(const float* __restrict__ keys, float* __restrict__ out) {
    int m = blockIdx.x;
    int t = threadIdx.x;   // 128
    float vals[4]; float s = 0.f;
    #pragma unroll
    for (int i = 0; i < 4; i++) {
        int c = t + i*128;
        vals[i] = g_qupd[(size_t)m*CC + c] + keys[(size_t)m*CC + c];
        s += vals[i]*vals[i];
    }
    for (int o = 16; o > 0; o >>= 1) s += __shfl_down_sync(0xffffffffu, s, o);
    __shared__ float red[4]; __shared__ float srn;
    if ((t & 31) == 0) red[t >> 5] = s;
    __syncthreads();
    if (t == 0) srn = 1.f / fmaxf(sqrtf(red[0]+red[1]+red[2]+red[3]), 1e-12f);
    __syncthreads();
    float rn = srn;
    #pragma unroll
    for (int i = 0; i < 4; i++) {
        int c = t + i*128;
        out[OFF_UMEM + (size_t)m*CC + c] = vals[i] * rn;
    }
}

// ---------------- gram(updated_memory) -> diversity loss ----------------
__global__ void __launch_bounds__(256) k_gram(const float* __restrict__ outRO,
                                              float* __restrict__ out) {
    const float* U = outRO + OFF_UMEM;
    __shared__ float As[8][132];
    __shared__ float Bs[8][132];
    int t = threadIdx.x;
    int j0 = blockIdx.x * 128;
    int i0 = blockIdx.y * 128;
    int tx = t & 15, ty = t >> 4;
    float acc[8][8];
    #pragma unroll
    for (int i = 0; i < 8; i++)
        #pragma unroll
        for (int j = 0; j < 8; j++) acc[i][j] = 0.f;

    int r  = t >> 1;
    int k4 = (t & 1) << 2;
    for (int k0 = 0; k0 < CC; k0 += 8) {
        float4 av = *reinterpret_cast<const float4*>(U + (size_t)(i0+r)*CC + k0 + k4);
        As[k4+0][r]=av.x; As[k4+1][r]=av.y; As[k4+2][r]=av.z; As[k4+3][r]=av.w;
        float4 bv = *reinterpret_cast<const float4*>(U + (size_t)(j0+r)*CC + k0 + k4);
        Bs[k4+0][r]=bv.x; Bs[k4+1][r]=bv.y; Bs[k4+2][r]=bv.z; Bs[k4+3][r]=bv.w;
        __syncthreads();
        #pragma unroll
        for (int kk = 0; kk < 8; kk++) {
            float a[8], bb[8];
            #pragma unroll
            for (int i = 0; i < 8; i++) a[i]  = As[kk][ty*8 + i];
            #pragma unroll
            for (int j = 0; j < 8; j++) bb[j] = Bs[kk][tx*8 + j];
            #pragma unroll
            for (int i = 0; i < 8; i++)
                #pragma unroll
                for (int j = 0; j < 8; j++) acc[i][j] = fmaf(a[i], bb[j], acc[i][j]);
        }
        __syncthreads();
    }
    float local = 0.f;
    #pragma unroll
    for (int i = 0; i < 8; i++) {
        int gi = i0 + ty*8 + i;
        #pragma unroll
        for (int j = 0; j < 8; j++) {
            int gj = j0 + tx*8 + j;
            float gv = acc[i][j];
            if (gi != gj) local += gv*gv;
        }
    }
    __shared__ float red[256];
    red[t] = local;
    __syncthreads();
    for (int o = 128; o > 0; o >>= 1) {
        if (t < o) red[t] += red[t + o];
        __syncthreads();
    }
    if (t == 0) atomicAdd(out + OFF_DIV, red[0] * (1.f / (float)(MM*MM - MM)));
}

// ---------------- read GEMM: concat[n,c] = sum_m sm[n,m]*keys[m,c] ----------------
// writes into updated_query channels [C, 2C) in BCHW layout
__global__ void __launch_bounds__(256) k_gemm_read(const float* __restrict__ outRO,
                                                   const float* __restrict__ keys,
                                                   float* __restrict__ out) {
    const float* smat = outRO + OFF_SM;
    __shared__ float As[8][132];   // As[kk][n]
    __shared__ float Bs[8][128];   // Bs[kk][c]
    int t = threadIdx.x;
    int c0 = blockIdx.x * 128;
    int n0 = blockIdx.y * 128;
    int b = n0 >> 10;
    int hw0 = n0 & 1023;
    int tx = t & 15, ty = t >> 4;

    float acc[8][8];   // [ic][in]
    #pragma unroll
    for (int i = 0; i < 8; i++)
        #pragma unroll
        for (int j = 0; j < 8; j++) acc[i][j] = 0.f;

    int ar  = t >> 1;
    int ak4 = (t & 1) << 2;
    int bkk = t >> 5;
    int bc4 = (t & 31) << 2;

    for (int k0 = 0; k0 < MM; k0 += 8) {
        float4 av = *reinterpret_cast<const float4*>(smat + (size_t)(n0+ar)*MM + k0 + ak4);
        As[ak4+0][ar]=av.x; As[ak4+1][ar]=av.y; As[ak4+2][ar]=av.z; As[ak4+3][ar]=av.w;
        float4 bv = *reinterpret_cast<const float4*>(keys + (size_t)(k0+bkk)*CC + c0 + bc4);
        *reinterpret_cast<float4*>(&Bs[bkk][bc4]) = bv;
        __syncthreads();
        #pragma unroll
        for (int kk = 0; kk < 8; kk++) {
            float a[8], bb[8];
            #pragma unroll
            for (int j = 0; j < 8; j++) a[j]  = As[kk][tx*8 + j];  // n frag
            #pragma unroll
            for (int i = 0; i < 8; i++) bb[i] = Bs[kk][ty*8 + i];  // c frag
            #pragma unroll
            for (int i = 0; i < 8; i++)
                #pragma unroll
                for (int j = 0; j < 8; j++) acc[i][j] = fmaf(bb[i], a[j], acc[i][j]);
        }
        __syncthreads();
    }
    // epilogue: out[b, C + c, hw] -> coalesced along n (= hw)
    float* obase = out + (size_t)b*UQ_STRIDE + hw0 + tx*8;
    #pragma unroll
    for (int i = 0; i < 8; i++) {
        size_t row = (size_t)(CC + c0 + ty*8 + i) * HWDIM;
        float4 o0 = make_float4(acc[i][0], acc[i][1], acc[i][2], acc[i][3]);
        float4 o1 = make_float4(acc[i][4], acc[i][5], acc[i][6], acc[i][7]);
        *reinterpret_cast<float4*>(obase + row)     = o0;
        *reinterpret_cast<float4*>(obase + row + 4) = o1;
    }
}

// ---------------- launch ----------------
extern "C" void kernel_launch(void* const* d_in, const int* in_sizes, int n_in,
                              void* d_out, int out_size) {
    const float* q    = (const float*)d_in[0];
    const float* keys = (const float*)d_in[1];
    const float* ent  = (const float*)d_in[2];
    float* out = (float*)d_out;

    k_zero<<<(MM*CC + 255)/256, 256>>>(out);
    k_entmax<<<NN/256, 256>>>(ent);
    k_keynorm<<<MM, 128>>>(keys);
    k_rnorm<<<NN/256, 256>>>(q);
    k_write_qr<<<(BB*CC*HWDIM)/256, 256>>>(q, out);
    k_gemm_score<<<dim3(MM/128, NN/128), 256>>>(out, keys);
    k_rowreduce<<<NN, 256>>>();
    k_colpartial<<<dim3(MM/256, NSPLIT), 256>>>();
    k_colmerge<<<MM/256, 256>>>();
    k_sqsm<<<(NN*MM/4)/256, 256>>>(out);
    k_wsim<<<NN/256, 256>>>(ent, out);
    k_segsum<<<(BB*CC*HWDIM)/256, 256>>>(out);
    k_umem<<<MM, 128>>>(keys, out);
    k_gram<<<dim3(MM/128, MM/128), 256>>>(out, out);
    k_gemm_read<<<dim3(CC/128, NN/128), 256>>>(out, keys, out);
}

// round 4
// speedup vs baseline: 1.7965x; 1.7965x over previous
#include <cuda_runtime.h>
#include <cuda_bf16.h>
#include <math.h>
#include <stdint.h>

#define BB 16
#define CC 512
#define HWDIM 1024
#define NN 16384            // B*H*W
#define MM 1024
#define NSPLIT 64
#define UQ_STRIDE (2*CC*HWDIM)          // per-batch stride of updated_query = 1048576

// output offsets (floats)
#define OFF_UQ   ((size_t)0)
#define OFF_UMEM ((size_t)BB*UQ_STRIDE)                  // 16777216
#define OFF_SQ   (OFF_UMEM + (size_t)MM*CC)              // 17301504
#define OFF_SM   (OFF_SQ + (size_t)NN*MM)                // 34078720
#define OFF_DIV  (OFF_SM + (size_t)NN*MM)                // 50855936
#define OFF_SIM  (OFF_DIV + 1)

// ---------------- scratch (static device globals; no runtime alloc) ----------------
__device__ float g_v[(size_t)NN*MM];     // exp(score), 64 MB
__device__ float g_rnacc[NN];
__device__ float g_rnorm[NN];
__device__ float g_rowmaxv[NN];
__device__ float g_rrowsum[NN];
__device__ int   g_argm[NN];
__device__ float g_w[NN];
__device__ float g_colmaxv[MM];
__device__ float g_rcolsum[MM];
__device__ float g_keynorm[MM];
__device__ float g_pmax[NSPLIT*MM];
__device__ float g_psum[NSPLIT*MM];
__device__ float g_qupd[MM*CC];
__device__ unsigned g_entmax_bits;
// bf16 split operands
__device__ __nv_bfloat16 g_qhi[(size_t)NN*CC];   // qr [N][C] K-major
__device__ __nv_bfloat16 g_qlo[(size_t)NN*CC];
__device__ __nv_bfloat16 g_khi[(size_t)MM*CC];   // keys [M][C]
__device__ __nv_bfloat16 g_klo[(size_t)MM*CC];
__device__ __nv_bfloat16 g_kThi[(size_t)CC*MM];  // keys^T [C][M]
__device__ __nv_bfloat16 g_kTlo[(size_t)CC*MM];
__device__ __nv_bfloat16 g_vhi[(size_t)NN*MM];   // v split [N][M]
__device__ __nv_bfloat16 g_vlo[(size_t)NN*MM];

// ---------------- PTX helpers (base sm_103-legal only) ----------------
__device__ __forceinline__ uint32_t smem_u32(const void* p) {
    uint32_t a;
    asm("{ .reg .u64 t; cvta.to.shared.u64 t, %1; cvt.u32.u64 %0, t; }" : "=r"(a) : "l"(p));
    return a;
}
__device__ __forceinline__ void ldm_x4(uint32_t* r, uint32_t a) {
    asm volatile("ldmatrix.sync.aligned.m8n8.x4.shared.b16 {%0,%1,%2,%3}, [%4];"
        : "=r"(r[0]), "=r"(r[1]), "=r"(r[2]), "=r"(r[3]) : "r"(a));
}
__device__ __forceinline__ void mma_bf16(float* c, const uint32_t* a, const uint32_t* b) {
    asm volatile("mma.sync.aligned.m16n8k16.row.col.f32.bf16.bf16.f32 "
        "{%0,%1,%2,%3}, {%4,%5,%6,%7}, {%8,%9}, {%0,%1,%2,%3};"
        : "+f"(c[0]), "+f"(c[1]), "+f"(c[2]), "+f"(c[3])
        : "r"(a[0]), "r"(a[1]), "r"(a[2]), "r"(a[3]), "r"(b[0]), "r"(b[1]));
}
__device__ __forceinline__ void cpa16(uint32_t dst, const void* src) {
    asm volatile("cp.async.ca.shared.global [%0], [%1], 16;" :: "r"(dst), "l"(src));
}
#define CP_COMMIT asm volatile("cp.async.commit_group;" ::: "memory")
#define CP_WAIT1  asm volatile("cp.async.wait_group 1;" ::: "memory")
#define CP_WAIT0  asm volatile("cp.async.wait_group 0;" ::: "memory")

// ---------------- small kernels ----------------

__global__ void k_init(float* out) {
    int i = blockIdx.x * blockDim.x + threadIdx.x;
    if (i < MM*CC) g_qupd[i] = 0.f;
    if (i < NN) g_rnacc[i] = 0.f;
    if (i == 0) {
        g_entmax_bits = 0u;
        out[OFF_DIV] = 0.f;
        out[OFF_SIM] = 0.f;
    }
}

__global__ void k_entmax(const float* __restrict__ ent) {
    int i = blockIdx.x * blockDim.x + threadIdx.x;
    if (i < NN) atomicMax(&g_entmax_bits, __float_as_uint(ent[i])); // entropy > 0
}

__global__ void k_keynorm(const float* __restrict__ keys) {
    int m = blockIdx.x;
    int t = threadIdx.x;   // 128 threads
    float s = 0.f;
    #pragma unroll
    for (int i = 0; i < 4; i++) {
        float v = keys[(size_t)m*CC + t + i*128];
        s += v*v;
    }
    for (int o = 16; o > 0; o >>= 1) s += __shfl_down_sync(0xffffffffu, s, o);
    __shared__ float red[4];
    if ((t & 31) == 0) red[t >> 5] = s;
    __syncthreads();
    if (t == 0) g_keynorm[m] = sqrtf(red[0] + red[1] + red[2] + red[3]);
}

// keys -> bf16 hi/lo split ([M][C] K-major for score B)
__global__ void k_ksplit(const float* __restrict__ keys) {
    int i = blockIdx.x * blockDim.x + threadIdx.x;   // over M*C
    float v = keys[i];
    __nv_bfloat16 hi = __float2bfloat16(v);
    float lo = v - __bfloat162float(hi);
    g_khi[i] = hi;
    g_klo[i] = __float2bfloat16(lo);
}

// keys^T split ([C][M] K-major-in-m for read B)
__global__ void k_ktrans(const float* __restrict__ keys) {
    __shared__ float t[32][33];
    int m0 = blockIdx.x * 32, c0 = blockIdx.y * 32;
    int tx = threadIdx.x, ty = threadIdx.y;  // 32 x 8
    #pragma unroll
    for (int i = 0; i < 4; i++)
        t[ty + i*8][tx] = keys[(size_t)(m0 + ty + i*8)*CC + c0 + tx];
    __syncthreads();
    #pragma unroll
    for (int i = 0; i < 4; i++) {
        float v = t[tx][ty + i*8];        // = keys[m0+tx][c0+ty+i*8]
        __nv_bfloat16 hi = __float2bfloat16(v);
        float lo = v - __bfloat162float(hi);
        size_t o = (size_t)(c0 + ty + i*8)*MM + m0 + tx;
        g_kThi[o] = hi;
        g_kTlo[o] = __float2bfloat16(lo);
    }
}

// partial sum-of-squares over 64-channel chunks (grid 64 x 8)
__global__ void k_rnorm_part(const float* __restrict__ q) {
    int n = blockIdx.x * 256 + threadIdx.x;
    int b = n >> 10, hw = n & 1023;
    const float* base = q + (size_t)b*CC*HWDIM + (size_t)(blockIdx.y*64)*HWDIM + hw;
    float s = 0.f;
    #pragma unroll 8
    for (int c = 0; c < 64; c++) {
        float v = base[(size_t)c*HWDIM];
        s += v*v;
    }
    atomicAdd(&g_rnacc[n], s);
}

__global__ void k_rnorm_fin() {
    int n = blockIdx.x * blockDim.x + threadIdx.x;
    if (n < NN) g_rnorm[n] = 1.f / fmaxf(sqrtf(g_rnacc[n]), 1e-12f);
}

// normalize q, write fp32 qr into out (BCHW) AND transposed bf16 hi/lo [N][C]
__global__ void k_qsplit(const float* __restrict__ q, float* __restrict__ out) {
    __shared__ float tile[32][33];
    int b  = blockIdx.z;
    int c0 = blockIdx.y * 32, hw0 = blockIdx.x * 32;
    int tx = threadIdx.x, ty = threadIdx.y;   // 32 x 8
    const float* src = q + (size_t)b*CC*HWDIM;
    float* dst = out + (size_t)b*UQ_STRIDE;
    #pragma unroll
    for (int i = 0; i < 4; i++) {
        int c  = c0 + ty + i*8;
        int hw = hw0 + tx;
        float v = src[(size_t)c*HWDIM + hw] * g_rnorm[(b<<10) | hw];
        dst[(size_t)c*HWDIM + hw] = v;
        tile[ty + i*8][tx] = v;
    }
    __syncthreads();
    #pragma unroll
    for (int i = 0; i < 4; i++) {
        int hw = hw0 + ty + i*8;
        int n  = (b<<10) | hw;
        float v = tile[tx][ty + i*8];
        __nv_bfloat16 hi = __float2bfloat16(v);
        float lo = v - __bfloat162float(hi);
        g_qhi[(size_t)n*CC + c0 + tx] = hi;
        g_qlo[(size_t)n*CC + c0 + tx] = __float2bfloat16(lo);
    }
}

// ---------------- HMMA score GEMM: v[n,m] = exp(qr . keys^T), bf16 3-term split ----------------
// block 128x128, warp grid 2x4 (warp tile 64x32), stage K=32, 48 stages (3 segs x 16)
#define GBUF 10240      // 128 rows * 80B (32 bf16 + 16B pad)

__global__ void __launch_bounds__(256, 2) k_score_mma() {
    __shared__ __align__(16) char As[2][GBUF];
    __shared__ __align__(16) char Bs[2][GBUF];
    int tid = threadIdx.x, l = tid & 31, w = tid >> 5;
    int wr = w >> 2, wc = w & 3;
    int m0 = blockIdx.x * 128, n0 = blockIdx.y * 128;
    const __nv_bfloat16* Ap[3] = {g_qhi, g_qhi, g_qlo};
    const __nv_bfloat16* Bp[3] = {g_khi, g_klo, g_khi};
    uint32_t as0 = smem_u32(As), bs0 = smem_u32(Bs);

    float acc[4][4][4];
    #pragma unroll
    for (int i = 0; i < 4; i++)
        #pragma unroll
        for (int j = 0; j < 4; j++)
            #pragma unroll
            for (int k = 0; k < 4; k++) acc[i][j][k] = 0.f;

    int row2 = tid >> 2, ch = tid & 3;
    auto stage = [&](int it, int buf) {
        int seg = it >> 4;
        int k0b = (it & 15) * 64;                       // 32 bf16 = 64B
        const char* Ab = (const char*)Ap[seg] + (size_t)n0*1024 + k0b;
        const char* Bb = (const char*)Bp[seg] + (size_t)m0*1024 + k0b;
        #pragma unroll
        for (int t = 0; t < 2; t++) {
            int r = row2 + t*64;
            cpa16(as0 + buf*GBUF + r*80 + ch*16, Ab + (size_t)r*1024 + ch*16);
            cpa16(bs0 + buf*GBUF + r*80 + ch*16, Bb + (size_t)r*1024 + ch*16);
        }
        CP_COMMIT;
    };

    uint32_t a_off = (uint32_t)((l & 15)*80 + (l >> 4)*16);
    uint32_t b_off = (uint32_t)(((((l >> 4) & 1)*8) + (l & 7))*80 + ((l >> 3) & 1)*16);

    stage(0, 0);
    for (int it = 0; it < 48; it++) {
        int buf = it & 1;
        if (it + 1 < 48) { stage(it + 1, buf ^ 1); CP_WAIT1; }
        else             { CP_WAIT0; }
        __syncthreads();
        #pragma unroll
        for (int h = 0; h < 2; h++) {
            uint32_t a[4][4];
            #pragma unroll
            for (int fi = 0; fi < 4; fi++)
                ldm_x4(a[fi], as0 + buf*GBUF + (wr*64 + fi*16)*80 + h*32 + a_off);
            uint32_t bfr[2][4];
            #pragma unroll
            for (int jp = 0; jp < 2; jp++)
                ldm_x4(bfr[jp], bs0 + buf*GBUF + (wc*32 + jp*16)*80 + h*32 + b_off);
            #pragma unroll
            for (int fi = 0; fi < 4; fi++)
                #pragma unroll
                for (int fj = 0; fj < 4; fj++)
                    mma_bf16(acc[fi][fj], a[fi], &bfr[fj >> 1][(fj & 1)*2]);
        }
        __syncthreads();
    }

    // epilogue: exp + v fp32 + bf16 hi/lo split of v
    int g = l >> 2, t2 = (l & 3)*2;
    #pragma unroll
    for (int fi = 0; fi < 4; fi++) {
        int r0 = n0 + wr*64 + fi*16 + g;
        #pragma unroll
        for (int fj = 0; fj < 4; fj++) {
            int c = m0 + wc*32 + fj*8 + t2;
            float* p = acc[fi][fj];
            #pragma unroll
            for (int hh = 0; hh < 2; hh++) {
                int r = r0 + hh*8;
                float e0 = __expf(p[hh*2 + 0]);
                float e1 = __expf(p[hh*2 + 1]);
                size_t o = (size_t)r*MM + c;
                *(float2*)(g_v + o) = make_float2(e0, e1);
                __nv_bfloat16 h0 = __float2bfloat16(e0);
                __nv_bfloat16 h1 = __float2bfloat16(e1);
                __nv_bfloat162 hv; hv.x = h0; hv.y = h1;
                *(__nv_bfloat162*)(g_vhi + o) = hv;
                __nv_bfloat162 lv;
                lv.x = __float2bfloat16(e0 - __bfloat162float(h0));
                lv.y = __float2bfloat16(e1 - __bfloat162float(h1));
                *(__nv_bfloat162*)(g_vlo + o) = lv;
            }
        }
    }
}

// ---------------- HMMA read GEMM: concat[n,c] = rrowsum[n] * sum_m v[n,m]*keys[m,c] ----------------
// block 128(n) x 128(c), K=1024 per seg, 3 segs x 32 stages = 96
__global__ void __launch_bounds__(256, 2) k_read_mma(float* __restrict__ out) {
    __shared__ __align__(16) char As[2][GBUF];
    __shared__ __align__(16) char Bs[2][GBUF];
    int tid = threadIdx.x, l = tid & 31, w = tid >> 5;
    int wr = w >> 2, wc = w & 3;
    int c0 = blockIdx.x * 128, n0 = blockIdx.y * 128;
    const __nv_bfloat16* Ap[3] = {g_vhi, g_vhi, g_vlo};
    const __nv_bfloat16* Bp[3] = {g_kThi, g_kTlo, g_kThi};
    uint32_t as0 = smem_u32(As), bs0 = smem_u32(Bs);

    float acc[4][4][4];
    #pragma unroll
    for (int i = 0; i < 4; i++)
        #pragma unroll
        for (int j = 0; j < 4; j++)
            #pragma unroll
            for (int k = 0; k < 4; k++) acc[i][j][k] = 0.f;

    int row2 = tid >> 2, ch = tid & 3;
    auto stage = [&](int it, int buf) {
        int seg = it >> 5;
        int k0b = (it & 31) * 64;
        const char* Ab = (const char*)Ap[seg] + (size_t)n0*2048 + k0b;
        const char* Bb = (const char*)Bp[seg] + (size_t)c0*2048 + k0b;
        #pragma unroll
        for (int t = 0; t < 2; t++) {
            int r = row2 + t*64;
            cpa16(as0 + buf*GBUF + r*80 + ch*16, Ab + (size_t)r*2048 + ch*16);
            cpa16(bs0 + buf*GBUF + r*80 + ch*16, Bb + (size_t)r*2048 + ch*16);
        }
        CP_COMMIT;
    };

    uint32_t a_off = (uint32_t)((l & 15)*80 + (l >> 4)*16);
    uint32_t b_off = (uint32_t)(((((l >> 4) & 1)*8) + (l & 7))*80 + ((l >> 3) & 1)*16);

    stage(0, 0);
    for (int it = 0; it < 96; it++) {
        int buf = it & 1;
        if (it + 1 < 96) { stage(it + 1, buf ^ 1); CP_WAIT1; }
        else             { CP_WAIT0; }
        __syncthreads();
        #pragma unroll
        for (int h = 0; h < 2; h++) {
            uint32_t a[4][4];
            #pragma unroll
            for (int fi = 0; fi < 4; fi++)
                ldm_x4(a[fi], as0 + buf*GBUF + (wr*64 + fi*16)*80 + h*32 + a_off);
            uint32_t bfr[2][4];
            #pragma unroll
            for (int jp = 0; jp < 2; jp++)
                ldm_x4(bfr[jp], bs0 + buf*GBUF + (wc*32 + jp*16)*80 + h*32 + b_off);
            #pragma unroll
            for (int fi = 0; fi < 4; fi++)
                #pragma unroll
                for (int fj = 0; fj < 4; fj++)
                    mma_bf16(acc[fi][fj], a[fi], &bfr[fj >> 1][(fj & 1)*2]);
        }
        __syncthreads();
    }

    // epilogue: scale by rrowsum, write BCHW channels [C, 2C)
    int g = l >> 2, t2 = (l & 3)*2;
    int b = n0 >> 10;
    int hwb = n0 & 1023;
    float* obase = out + (size_t)b*UQ_STRIDE;
    #pragma unroll
    for (int fi = 0; fi < 4; fi++) {
        int rl0 = wr*64 + fi*16 + g;
        float rs0 = g_rrowsum[n0 + rl0];
        float rs1 = g_rrowsum[n0 + rl0 + 8];
        #pragma unroll
        for (int fj = 0; fj < 4; fj++) {
            int c = c0 + wc*32 + fj*8 + t2;
            float* p = acc[fi][fj];
            size_t a0 = (size_t)(CC + c)*HWDIM + hwb + rl0;
            obase[a0]              = p[0] * rs0;
            obase[a0 + HWDIM]      = p[1] * rs0;
            obase[a0 + 8]          = p[2] * rs1;
            obase[a0 + HWDIM + 8]  = p[3] * rs1;
        }
    }
}

// ---------------- row reductions over v: rowmax, argmax (first-tie), rowsum ----------------
__global__ void k_rowreduce() {
    int n = blockIdx.x;
    int t = threadIdx.x;   // 256
    float4 v = reinterpret_cast<const float4*>(g_v + (size_t)n*MM)[t];
    float mx = v.x; int ix = t*4;
    if (v.y > mx) { mx = v.y; ix = t*4+1; }
    if (v.z > mx) { mx = v.z; ix = t*4+2; }
    if (v.w > mx) { mx = v.w; ix = t*4+3; }
    float s = v.x + v.y + v.z + v.w;
    __shared__ float smx[256]; __shared__ int six[256]; __shared__ float ssm[256];
    smx[t] = mx; six[t] = ix; ssm[t] = s;
    __syncthreads();
    for (int o = 128; o > 0; o >>= 1) {
        if (t < o) {
            float om = smx[t+o]; int oi = six[t+o];
            if (om > smx[t] || (om == smx[t] && oi < six[t])) { smx[t] = om; six[t] = oi; }
            ssm[t] += ssm[t+o];
        }
        __syncthreads();
    }
    if (t == 0) {
        g_rowmaxv[n] = smx[0];
        g_argm[n]    = six[0];
        g_rrowsum[n] = 1.f / ssm[0];
    }
}

// ---------------- column reductions (split over n, then merge) ----------------
__global__ void k_colpartial() {
    int m = blockIdx.x * 256 + threadIdx.x;
    int nbase = blockIdx.y * 256;
    float mx = 0.f, s = 0.f;
    #pragma unroll 4
    for (int r = 0; r < 256; r++) {
        float v = g_v[(size_t)(nbase + r)*MM + m];
        mx = fmaxf(mx, v);
        s += v;
    }
    g_pmax[blockIdx.y*MM + m] = mx;
    g_psum[blockIdx.y*MM + m] = s;
}

__global__ void k_colmerge() {
    int m = blockIdx.x * 256 + threadIdx.x;
    float mx = 0.f, s = 0.f;
    #pragma unroll 4
    for (int p = 0; p < NSPLIT; p++) {
        mx = fmaxf(mx, g_pmax[p*MM + m]);
        s += g_psum[p*MM + m];
    }
    g_colmaxv[m] = mx;
    g_rcolsum[m] = 1.f / s;
}

// ---------------- write sq & sm outputs ----------------
__global__ void k_sqsm(float* __restrict__ out) {
    int i = blockIdx.x * blockDim.x + threadIdx.x;   // float4 index
    size_t base = (size_t)i * 4;
    int n = (int)(base >> 10);
    int m = (int)(base & 1023);
    float4 v  = reinterpret_cast<const float4*>(g_v)[i];
    float4 rc = reinterpret_cast<const float4*>(g_rcolsum)[m >> 2];
    float  rr = g_rrowsum[n];
    float4 sq = make_float4(v.x*rc.x, v.y*rc.y, v.z*rc.z, v.w*rc.w);
    float4 sm = make_float4(v.x*rr,  v.y*rr,  v.z*rr,  v.w*rr);
    reinterpret_cast<float4*>(out + OFF_SQ)[i] = sq;
    reinterpret_cast<float4*>(out + OFF_SM)[i] = sm;
}

// ---------------- w[n] and similarity loss ----------------
__global__ void k_wsim(const float* __restrict__ ent, float* __restrict__ out) {
    int n = blockIdx.x * blockDim.x + threadIdx.x;
    float local = 0.f;
    if (n < NN) {
        int g = g_argm[n];
        float en = ent[n];
        float entmax = __uint_as_float(g_entmax_bits);
        g_w[n] = (g_rowmaxv[n] / g_colmaxv[g]) * (en / entmax);
        float smax = logf(g_rowmaxv[n]);                  // = max score of row n
        float cosv = smax / fmaxf(g_keynorm[g], 1e-8f);   // ||qr|| == 1
        local = (1.f - cosv) * en;
    }
    __shared__ float red[256];
    red[threadIdx.x] = local;
    __syncthreads();
    for (int o = 128; o > 0; o >>= 1) {
        if (threadIdx.x < o) red[threadIdx.x] += red[threadIdx.x + o];
        __syncthreads();
    }
    if (threadIdx.x == 0) atomicAdd(out + OFF_SIM, red[0]);
}

// ---------------- segment-sum: qupd[g[n], c] += w[n]*qr[n,c] ----------------
__global__ void k_segsum(const float* __restrict__ out) {
    int idx = blockIdx.x * blockDim.x + threadIdx.x;
    if (idx >= BB*CC*HWDIM) return;
    int b = idx >> 19;
    int rem = idx & ((CC*HWDIM) - 1);
    int c = rem >> 10;
    int hw = idx & 1023;
    int n = (b << 10) | hw;
    float val = out[(size_t)b*UQ_STRIDE + rem];           // qr in BCHW layout
    atomicAdd(&g_qupd[(size_t)g_argm[n]*CC + c], g_w[n] * val);
}

// ---------------- updated memory: l2norm(qupd + keys) ----------------
__global__ void k_umem(const float* __restrict__ keys, float* __restrict__ out) {
    int m = blockIdx.x;
    int t = threadIdx.x;   // 128
    float vals[4]; float s = 0.f;
    #pragma unroll
    for (int i = 0; i < 4; i++) {
        int c = t + i*128;
        vals[i] = g_qupd[(size_t)m*CC + c] + keys[(size_t)m*CC + c];
        s += vals[i]*vals[i];
    }
    for (int o = 16; o > 0; o >>= 1) s += __shfl_down_sync(0xffffffffu, s, o);
    __shared__ float red[4]; __shared__ float srn;
    if ((t & 31) == 0) red[t >> 5] = s;
    __syncthreads();
    if (t == 0) srn = 1.f / fmaxf(sqrtf(red[0]+red[1]+red[2]+red[3]), 1e-12f);
    __syncthreads();
    float rn = srn;
    #pragma unroll
    for (int i = 0; i < 4; i++) {
        int c = t + i*128;
        out[OFF_UMEM + (size_t)m*CC + c] = vals[i] * rn;
    }
}

// ---------------- gram(updated_memory) -> diversity loss ----------------
__global__ void __launch_bounds__(256) k_gram(const float* __restrict__ outRO,
                                              float* __restrict__ out) {
    const float* U = outRO + OFF_UMEM;
    __shared__ float As[8][132];
    __shared__ float Bs[8][132];
    int t = threadIdx.x;
    int j0 = blockIdx.x * 128;
    int i0 = blockIdx.y * 128;
    int tx = t & 15, ty = t >> 4;
    float acc[8][8];
    #pragma unroll
    for (int i = 0; i < 8; i++)
        #pragma unroll
        for (int j = 0; j < 8; j++) acc[i][j] = 0.f;

    int r  = t >> 1;
    int k4 = (t & 1) << 2;
    for (int k0 = 0; k0 < CC; k0 += 8) {
        float4 av = *reinterpret_cast<const float4*>(U + (size_t)(i0+r)*CC + k0 + k4);
        As[k4+0][r]=av.x; As[k4+1][r]=av.y; As[k4+2][r]=av.z; As[k4+3][r]=av.w;
        float4 bv = *reinterpret_cast<const float4*>(U + (size_t)(j0+r)*CC + k0 + k4);
        Bs[k4+0][r]=bv.x; Bs[k4+1][r]=bv.y; Bs[k4+2][r]=bv.z; Bs[k4+3][r]=bv.w;
        __syncthreads();
        #pragma unroll
        for (int kk = 0; kk < 8; kk++) {
            float a[8], bb[8];
            #pragma unroll
            for (int i = 0; i < 8; i++) a[i]  = As[kk][ty*8 + i];
            #pragma unroll
            for (int j = 0; j < 8; j++) bb[j] = Bs[kk][tx*8 + j];
            #pragma unroll
            for (int i = 0; i < 8; i++)
                #pragma unroll
                for (int j = 0; j < 8; j++) acc[i][j] = fmaf(a[i], bb[j], acc[i][j]);
        }
        __syncthreads();
    }
    float local = 0.f;
    #pragma unroll
    for (int i = 0; i < 8; i++) {
        int gi = i0 + ty*8 + i;
        #pragma unroll
        for (int j = 0; j < 8; j++) {
            int gj = j0 + tx*8 + j;
            float gv = acc[i][j];
            if (gi != gj) local += gv*gv;
        }
    }
    __shared__ float red[256];
    red[t] = local;
    __syncthreads();
    for (int o = 128; o > 0; o >>= 1) {
        if (t < o) red[t] += red[t + o];
        __syncthreads();
    }
    if (t == 0) atomicAdd(out + OFF_DIV, red[0] * (1.f / (float)(MM*MM - MM)));
}

// ---------------- launch ----------------
extern "C" void kernel_launch(void* const* d_in, const int* in_sizes, int n_in,
                              void* d_out, int out_size) {
    const float* q    = (const float*)d_in[0];
    const float* keys = (const float*)d_in[1];
    const float* ent  = (const float*)d_in[2];
    float* out = (float*)d_out;

    k_init<<<(MM*CC + 255)/256, 256>>>(out);
    k_entmax<<<NN/256, 256>>>(ent);
    k_keynorm<<<MM, 128>>>(keys);
    k_ksplit<<<(MM*CC)/256, 256>>>(keys);
    k_ktrans<<<dim3(MM/32, CC/32), dim3(32, 8)>>>(keys);
    k_rnorm_part<<<dim3(64, 8), 256>>>(q);
    k_rnorm_fin<<<NN/256, 256>>>();
    k_qsplit<<<dim3(HWDIM/32, CC/32, BB), dim3(32, 8)>>>(q, out);
    k_score_mma<<<dim3(MM/128, NN/128), 256>>>();
    k_rowreduce<<<NN, 256>>>();
    k_colpartial<<<dim3(MM/256, NSPLIT), 256>>>();
    k_colmerge<<<MM/256, 256>>>();
    k_sqsm<<<(NN*MM/4)/256, 256>>>(out);
    k_wsim<<<NN/256, 256>>>(ent, out);
    k_segsum<<<(BB*CC*HWDIM)/256, 256>>>(out);
    k_umem<<<MM, 128>>>(keys, out);
    k_gram<<<dim3(MM/128, MM/128), 256>>>(out, out);
    k_read_mma<<<dim3(CC/128, NN/128), 256>>>(out);
}

// round 5
// speedup vs baseline: 2.0517x; 1.1420x over previous
#include <cuda_runtime.h>
#include <cuda_bf16.h>
#include <math.h>
#include <stdint.h>

#define BB 16
#define CC 512
#define HWDIM 1024
#define NN 16384            // B*H*W
#define MM 1024
#define NSPLIT 128
#define UQ_STRIDE (2*CC*HWDIM)          // per-batch stride of updated_query = 1048576

// output offsets (floats)
#define OFF_UQ   ((size_t)0)
#define OFF_UMEM ((size_t)BB*UQ_STRIDE)                  // 16777216
#define OFF_SQ   (OFF_UMEM + (size_t)MM*CC)              // 17301504
#define OFF_SM   (OFF_SQ + (size_t)NN*MM)                // 34078720
#define OFF_DIV  (OFF_SM + (size_t)NN*MM)                // 50855936
#define OFF_SIM  (OFF_DIV + 1)

// ---------------- scratch (static device globals; no runtime alloc) ----------------
__device__ float g_rnacc[NN];
__device__ float g_rnorm[NN];
__device__ float g_rowmaxv[NN];
__device__ float g_rrowsum[NN];
__device__ int   g_argm[NN];
__device__ float g_w[NN];
__device__ float g_colmaxv[MM];
__device__ float g_rcolsum[MM];
__device__ float g_keynorm[MM];
__device__ float g_pmax[NSPLIT*MM];
__device__ float g_psum[NSPLIT*MM];
__device__ float g_qupd[MM*CC];
__device__ unsigned g_entmax_bits;
// bf16 split operands
__device__ __nv_bfloat16 g_qhi[(size_t)NN*CC];   // qr [N][C] K-major
__device__ __nv_bfloat16 g_qlo[(size_t)NN*CC];
__device__ __nv_bfloat16 g_khi[(size_t)MM*CC];   // keys [M][C]
__device__ __nv_bfloat16 g_klo[(size_t)MM*CC];
__device__ __nv_bfloat16 g_kThi[(size_t)CC*MM];  // keys^T [C][M]
__device__ __nv_bfloat16 g_kTlo[(size_t)CC*MM];
__device__ __nv_bfloat16 g_vhi[(size_t)NN*MM];   // v split [N][M]
__device__ __nv_bfloat16 g_vlo[(size_t)NN*MM];
__device__ __nv_bfloat16 g_uhi[(size_t)MM*CC];   // updated_memory split
__device__ __nv_bfloat16 g_ulo[(size_t)MM*CC];

// ---------------- PTX helpers (base sm_103-legal only) ----------------
__device__ __forceinline__ uint32_t smem_u32(const void* p) {
    uint32_t a;
    asm("{ .reg .u64 t; cvta.to.shared.u64 t, %1; cvt.u32.u64 %0, t; }" : "=r"(a) : "l"(p));
    return a;
}
__device__ __forceinline__ void ldm_x4(uint32_t* r, uint32_t a) {
    asm volatile("ldmatrix.sync.aligned.m8n8.x4.shared.b16 {%0,%1,%2,%3}, [%4];"
        : "=r"(r[0]), "=r"(r[1]), "=r"(r[2]), "=r"(r[3]) : "r"(a));
}
__device__ __forceinline__ void mma_bf16(float* c, const uint32_t* a, const uint32_t* b) {
    asm volatile("mma.sync.aligned.m16n8k16.row.col.f32.bf16.bf16.f32 "
        "{%0,%1,%2,%3}, {%4,%5,%6,%7}, {%8,%9}, {%0,%1,%2,%3};"
        : "+f"(c[0]), "+f"(c[1]), "+f"(c[2]), "+f"(c[3])
        : "r"(a[0]), "r"(a[1]), "r"(a[2]), "r"(a[3]), "r"(b[0]), "r"(b[1]));
}
__device__ __forceinline__ void cpa16(uint32_t dst, const void* src) {
    asm volatile("cp.async.ca.shared.global [%0], [%1], 16;" :: "r"(dst), "l"(src));
}
#define CP_COMMIT asm volatile("cp.async.commit_group;" ::: "memory")
#define CP_WAIT1  asm volatile("cp.async.wait_group 1;" ::: "memory")
#define CP_WAIT0  asm volatile("cp.async.wait_group 0;" ::: "memory")

// ---------------- small kernels ----------------

__global__ void k_init(float* out) {
    int i = blockIdx.x * blockDim.x + threadIdx.x;
    if (i < MM*CC) g_qupd[i] = 0.f;
    if (i < NN) g_rnacc[i] = 0.f;
    if (i == 0) {
        g_entmax_bits = 0u;
        out[OFF_DIV] = 0.f;
        out[OFF_SIM] = 0.f;
    }
}

__global__ void k_entmax(const float* __restrict__ ent) {
    int i = blockIdx.x * blockDim.x + threadIdx.x;
    if (i < NN) atomicMax(&g_entmax_bits, __float_as_uint(ent[i])); // entropy > 0
}

__global__ void k_keynorm(const float* __restrict__ keys) {
    int m = blockIdx.x;
    int t = threadIdx.x;   // 128 threads
    float s = 0.f;
    #pragma unroll
    for (int i = 0; i < 4; i++) {
        float v = keys[(size_t)m*CC + t + i*128];
        s += v*v;
    }
    for (int o = 16; o > 0; o >>= 1) s += __shfl_down_sync(0xffffffffu, s, o);
    __shared__ float red[4];
    if ((t & 31) == 0) red[t >> 5] = s;
    __syncthreads();
    if (t == 0) g_keynorm[m] = sqrtf(red[0] + red[1] + red[2] + red[3]);
}

// keys -> bf16 hi/lo split ([M][C] K-major for score B)
__global__ void k_ksplit(const float* __restrict__ keys) {
    int i = blockIdx.x * blockDim.x + threadIdx.x;   // over M*C
    float v = keys[i];
    __nv_bfloat16 hi = __float2bfloat16(v);
    float lo = v - __bfloat162float(hi);
    g_khi[i] = hi;
    g_klo[i] = __float2bfloat16(lo);
}

// keys^T split ([C][M] K-major-in-m for read B)
__global__ void k_ktrans(const float* __restrict__ keys) {
    __shared__ float t[32][33];
    int m0 = blockIdx.x * 32, c0 = blockIdx.y * 32;
    int tx = threadIdx.x, ty = threadIdx.y;  // 32 x 8
    #pragma unroll
    for (int i = 0; i < 4; i++)
        t[ty + i*8][tx] = keys[(size_t)(m0 + ty + i*8)*CC + c0 + tx];
    __syncthreads();
    #pragma unroll
    for (int i = 0; i < 4; i++) {
        float v = t[tx][ty + i*8];        // = keys[m0+tx][c0+ty+i*8]
        __nv_bfloat16 hi = __float2bfloat16(v);
        float lo = v - __bfloat162float(hi);
        size_t o = (size_t)(c0 + ty + i*8)*MM + m0 + tx;
        g_kThi[o] = hi;
        g_kTlo[o] = __float2bfloat16(lo);
    }
}

// partial sum-of-squares over 64-channel chunks (grid 64 x 8)
__global__ void k_rnorm_part(const float* __restrict__ q) {
    int n = blockIdx.x * 256 + threadIdx.x;
    int b = n >> 10, hw = n & 1023;
    const float* base = q + (size_t)b*CC*HWDIM + (size_t)(blockIdx.y*64)*HWDIM + hw;
    float s = 0.f;
    #pragma unroll 8
    for (int c = 0; c < 64; c++) {
        float v = base[(size_t)c*HWDIM];
        s += v*v;
    }
    atomicAdd(&g_rnacc[n], s);
}

__global__ void k_rnorm_fin() {
    int n = blockIdx.x * blockDim.x + threadIdx.x;
    if (n < NN) g_rnorm[n] = 1.f / fmaxf(sqrtf(g_rnacc[n]), 1e-12f);
}

// normalize q, write fp32 qr into out (BCHW) AND transposed bf16 hi/lo [N][C]
__global__ void k_qsplit(const float* __restrict__ q, float* __restrict__ out) {
    __shared__ float tile[32][33];
    int b  = blockIdx.z;
    int c0 = blockIdx.y * 32, hw0 = blockIdx.x * 32;
    int tx = threadIdx.x, ty = threadIdx.y;   // 32 x 8
    const float* src = q + (size_t)b*CC*HWDIM;
    float* dst = out + (size_t)b*UQ_STRIDE;
    #pragma unroll
    for (int i = 0; i < 4; i++) {
        int c  = c0 + ty + i*8;
        int hw = hw0 + tx;
        float v = src[(size_t)c*HWDIM + hw] * g_rnorm[(b<<10) | hw];
        dst[(size_t)c*HWDIM + hw] = v;
        tile[ty + i*8][tx] = v;
    }
    __syncthreads();
    #pragma unroll
    for (int i = 0; i < 4; i++) {
        int hw = hw0 + ty + i*8;
        int n  = (b<<10) | hw;
        float v = tile[tx][ty + i*8];
        __nv_bfloat16 hi = __float2bfloat16(v);
        float lo = v - __bfloat162float(hi);
        g_qhi[(size_t)n*CC + c0 + tx] = hi;
        g_qlo[(size_t)n*CC + c0 + tx] = __float2bfloat16(lo);
    }
}

// ---------------- HMMA score GEMM: v[n,m] = exp(qr . keys^T), bf16 3-term split ----------------
// block 128x128, warp grid 2x4 (warp tile 64x32), stage K=32, ring of 3 buffers
#define GBUF 10240      // 128 rows * 80B (32 bf16 + 16B pad)
#define DSMEM (6*GBUF)  // 3 A bufs + 3 B bufs = 61440

__global__ void __launch_bounds__(256, 2) k_score_mma() {
    extern __shared__ __align__(16) char dsm[];
    int tid = threadIdx.x, l = tid & 31, w = tid >> 5;
    int wr = w >> 2, wc = w & 3;
    int m0 = blockIdx.x * 128, n0 = blockIdx.y * 128;
    const __nv_bfloat16* Ap[3] = {g_qhi, g_qhi, g_qlo};
    const __nv_bfloat16* Bp[3] = {g_khi, g_klo, g_khi};
    uint32_t as0 = smem_u32(dsm);
    uint32_t bs0 = as0 + 3*GBUF;

    float acc[4][4][4];
    #pragma unroll
    for (int i = 0; i < 4; i++)
        #pragma unroll
        for (int j = 0; j < 4; j++)
            #pragma unroll
            for (int k = 0; k < 4; k++) acc[i][j][k] = 0.f;

    int row2 = tid >> 2, ch = tid & 3;
    auto stage = [&](int it, int buf) {
        int seg = it >> 4;
        int k0b = (it & 15) * 64;                       // 32 bf16 = 64B
        const char* Ab = (const char*)Ap[seg] + (size_t)n0*1024 + k0b;
        const char* Bb = (const char*)Bp[seg] + (size_t)m0*1024 + k0b;
        #pragma unroll
        for (int t = 0; t < 2; t++) {
            int r = row2 + t*64;
            cpa16(as0 + buf*GBUF + r*80 + ch*16, Ab + (size_t)r*1024 + ch*16);
            cpa16(bs0 + buf*GBUF + r*80 + ch*16, Bb + (size_t)r*1024 + ch*16);
        }
        CP_COMMIT;
    };

    uint32_t a_off = (uint32_t)((l & 15)*80 + (l >> 4)*16);
    uint32_t b_off = (uint32_t)(((((l >> 4) & 1)*8) + (l & 7))*80 + ((l >> 3) & 1)*16);

    stage(0, 0); stage(1, 1);
    int buf = 0;
    for (int it = 0; it < 48; it++) {
        if (it < 47) CP_WAIT1; else CP_WAIT0;
        __syncthreads();
        if (it + 2 < 48) {
            int nb = buf + 2; if (nb >= 3) nb -= 3;
            stage(it + 2, nb);
        }
        #pragma unroll
        for (int h = 0; h < 2; h++) {
            uint32_t a[4][4];
            #pragma unroll
            for (int fi = 0; fi < 4; fi++)
                ldm_x4(a[fi], as0 + buf*GBUF + (wr*64 + fi*16)*80 + h*32 + a_off);
            uint32_t bfr[2][4];
            #pragma unroll
            for (int jp = 0; jp < 2; jp++)
                ldm_x4(bfr[jp], bs0 + buf*GBUF + (wc*32 + jp*16)*80 + h*32 + b_off);
            #pragma unroll
            for (int fi = 0; fi < 4; fi++)
                #pragma unroll
                for (int fj = 0; fj < 4; fj++)
                    mma_bf16(acc[fi][fj], a[fi], &bfr[fj >> 1][(fj & 1)*2]);
        }
        buf = (buf + 1 == 3) ? 0 : buf + 1;
    }

    // epilogue: exp + bf16 hi/lo split of v (no fp32 v store)
    int g = l >> 2, t2 = (l & 3)*2;
    #pragma unroll
    for (int fi = 0; fi < 4; fi++) {
        int r0 = n0 + wr*64 + fi*16 + g;
        #pragma unroll
        for (int fj = 0; fj < 4; fj++) {
            int c = m0 + wc*32 + fj*8 + t2;
            float* p = acc[fi][fj];
            #pragma unroll
            for (int hh = 0; hh < 2; hh++) {
                int r = r0 + hh*8;
                float e0 = __expf(p[hh*2 + 0]);
                float e1 = __expf(p[hh*2 + 1]);
                size_t o = (size_t)r*MM + c;
                __nv_bfloat16 h0 = __float2bfloat16(e0);
                __nv_bfloat16 h1 = __float2bfloat16(e1);
                __nv_bfloat162 hv; hv.x = h0; hv.y = h1;
                *(__nv_bfloat162*)(g_vhi + o) = hv;
                __nv_bfloat162 lv;
                lv.x = __float2bfloat16(e0 - __bfloat162float(h0));
                lv.y = __float2bfloat16(e1 - __bfloat162float(h1));
                *(__nv_bfloat162*)(g_vlo + o) = lv;
            }
        }
    }
}

// ---------------- HMMA read GEMM: concat[n,c] = rrowsum[n] * sum_m v[n,m]*keys[m,c] ----------------
__global__ void __launch_bounds__(256, 2) k_read_mma(float* __restrict__ out) {
    extern __shared__ __align__(16) char dsm[];
    int tid = threadIdx.x, l = tid & 31, w = tid >> 5;
    int wr = w >> 2, wc = w & 3;
    int c0 = blockIdx.x * 128, n0 = blockIdx.y * 128;
    const __nv_bfloat16* Ap[3] = {g_vhi, g_vhi, g_vlo};
    const __nv_bfloat16* Bp[3] = {g_kThi, g_kTlo, g_kThi};
    uint32_t as0 = smem_u32(dsm);
    uint32_t bs0 = as0 + 3*GBUF;

    float acc[4][4][4];
    #pragma unroll
    for (int i = 0; i < 4; i++)
        #pragma unroll
        for (int j = 0; j < 4; j++)
            #pragma unroll
            for (int k = 0; k < 4; k++) acc[i][j][k] = 0.f;

    int row2 = tid >> 2, ch = tid & 3;
    auto stage = [&](int it, int buf) {
        int seg = it >> 5;
        int k0b = (it & 31) * 64;
        const char* Ab = (const char*)Ap[seg] + (size_t)n0*2048 + k0b;
        const char* Bb = (const char*)Bp[seg] + (size_t)c0*2048 + k0b;
        #pragma unroll
        for (int t = 0; t < 2; t++) {
            int r = row2 + t*64;
            cpa16(as0 + buf*GBUF + r*80 + ch*16, Ab + (size_t)r*2048 + ch*16);
            cpa16(bs0 + buf*GBUF + r*80 + ch*16, Bb + (size_t)r*2048 + ch*16);
        }
        CP_COMMIT;
    };

    uint32_t a_off = (uint32_t)((l & 15)*80 + (l >> 4)*16);
    uint32_t b_off = (uint32_t)(((((l >> 4) & 1)*8) + (l & 7))*80 + ((l >> 3) & 1)*16);

    stage(0, 0); stage(1, 1);
    int buf = 0;
    for (int it = 0; it < 96; it++) {
        if (it < 95) CP_WAIT1; else CP_WAIT0;
        __syncthreads();
        if (it + 2 < 96) {
            int nb = buf + 2; if (nb >= 3) nb -= 3;
            stage(it + 2, nb);
        }
        #pragma unroll
        for (int h = 0; h < 2; h++) {
            uint32_t a[4][4];
            #pragma unroll
            for (int fi = 0; fi < 4; fi++)
                ldm_x4(a[fi], as0 + buf*GBUF + (wr*64 + fi*16)*80 + h*32 + a_off);
            uint32_t bfr[2][4];
            #pragma unroll
            for (int jp = 0; jp < 2; jp++)
                ldm_x4(bfr[jp], bs0 + buf*GBUF + (wc*32 + jp*16)*80 + h*32 + b_off);
            #pragma unroll
            for (int fi = 0; fi < 4; fi++)
                #pragma unroll
                for (int fj = 0; fj < 4; fj++)
                    mma_bf16(acc[fi][fj], a[fi], &bfr[fj >> 1][(fj & 1)*2]);
        }
        buf = (buf + 1 == 3) ? 0 : buf + 1;
    }

    // epilogue: scale by rrowsum, write BCHW channels [C, 2C)
    int g = l >> 2, t2 = (l & 3)*2;
    int b = n0 >> 10;
    int hwb = n0 & 1023;
    float* obase = out + (size_t)b*UQ_STRIDE;
    #pragma unroll
    for (int fi = 0; fi < 4; fi++) {
        int rl0 = wr*64 + fi*16 + g;
        float rs0 = g_rrowsum[n0 + rl0];
        float rs1 = g_rrowsum[n0 + rl0 + 8];
        #pragma unroll
        for (int fj = 0; fj < 4; fj++) {
            int c = c0 + wc*32 + fj*8 + t2;
            float* p = acc[fi][fj];
            size_t a0 = (size_t)(CC + c)*HWDIM + hwb + rl0;
            obase[a0]              = p[0] * rs0;
            obase[a0 + HWDIM]      = p[1] * rs0;
            obase[a0 + 8]          = p[2] * rs1;
            obase[a0 + HWDIM + 8]  = p[3] * rs1;
        }
    }
}

// ---------------- HMMA gram GEMM: diversity(updated_memory) ----------------
__global__ void __launch_bounds__(256, 2) k_gram_mma(float* __restrict__ out) {
    extern __shared__ __align__(16) char dsm[];
    __shared__ float red[256];
    int tid = threadIdx.x, l = tid & 31, w = tid >> 5;
    int wr = w >> 2, wc = w & 3;
    int j0 = blockIdx.x * 128, i0 = blockIdx.y * 128;
    const __nv_bfloat16* Ap[3] = {g_uhi, g_uhi, g_ulo};
    const __nv_bfloat16* Bp[3] = {g_uhi, g_ulo, g_uhi};
    uint32_t as0 = smem_u32(dsm);
    uint32_t bs0 = as0 + 3*GBUF;

    float acc[4][4][4];
    #pragma unroll
    for (int i = 0; i < 4; i++)
        #pragma unroll
        for (int j = 0; j < 4; j++)
            #pragma unroll
            for (int k = 0; k < 4; k++) acc[i][j][k] = 0.f;

    int row2 = tid >> 2, ch = tid & 3;
    auto stage = [&](int it, int buf) {
        int seg = it >> 4;
        int k0b = (it & 15) * 64;
        const char* Ab = (const char*)Ap[seg] + (size_t)i0*1024 + k0b;
        const char* Bb = (const char*)Bp[seg] + (size_t)j0*1024 + k0b;
        #pragma unroll
        for (int t = 0; t < 2; t++) {
            int r = row2 + t*64;
            cpa16(as0 + buf*GBUF + r*80 + ch*16, Ab + (size_t)r*1024 + ch*16);
            cpa16(bs0 + buf*GBUF + r*80 + ch*16, Bb + (size_t)r*1024 + ch*16);
        }
        CP_COMMIT;
    };

    uint32_t a_off = (uint32_t)((l & 15)*80 + (l >> 4)*16);
    uint32_t b_off = (uint32_t)(((((l >> 4) & 1)*8) + (l & 7))*80 + ((l >> 3) & 1)*16);

    stage(0, 0); stage(1, 1);
    int buf = 0;
    for (int it = 0; it < 48; it++) {
        if (it < 47) CP_WAIT1; else CP_WAIT0;
        __syncthreads();
        if (it + 2 < 48) {
            int nb = buf + 2; if (nb >= 3) nb -= 3;
            stage(it + 2, nb);
        }
        #pragma unroll
        for (int h = 0; h < 2; h++) {
            uint32_t a[4][4];
            #pragma unroll
            for (int fi = 0; fi < 4; fi++)
                ldm_x4(a[fi], as0 + buf*GBUF + (wr*64 + fi*16)*80 + h*32 + a_off);
            uint32_t bfr[2][4];
            #pragma unroll
            for (int jp = 0; jp < 2; jp++)
                ldm_x4(bfr[jp], bs0 + buf*GBUF + (wc*32 + jp*16)*80 + h*32 + b_off);
            #pragma unroll
            for (int fi = 0; fi < 4; fi++)
                #pragma unroll
                for (int fj = 0; fj < 4; fj++)
                    mma_bf16(acc[fi][fj], a[fi], &bfr[fj >> 1][(fj & 1)*2]);
        }
        buf = (buf + 1 == 3) ? 0 : buf + 1;
    }

    // epilogue: sum of squared off-diagonal gram entries
    int g = l >> 2, t2 = (l & 3)*2;
    float local = 0.f;
    #pragma unroll
    for (int fi = 0; fi < 4; fi++) {
        int r0 = i0 + wr*64 + fi*16 + g;
        #pragma unroll
        for (int fj = 0; fj < 4; fj++) {
            int c = j0 + wc*32 + fj*8 + t2;
            float* p = acc[fi][fj];
            if (r0 != c)         local += p[0]*p[0];
            if (r0 != c + 1)     local += p[1]*p[1];
            if (r0 + 8 != c)     local += p[2]*p[2];
            if (r0 + 8 != c + 1) local += p[3]*p[3];
        }
    }
    red[tid] = local;
    __syncthreads();
    for (int o = 128; o > 0; o >>= 1) {
        if (tid < o) red[tid] += red[tid + o];
        __syncthreads();
    }
    if (tid == 0) atomicAdd(out + OFF_DIV, red[0] * (1.f / (float)(MM*MM - MM)));
}

// ---------------- fused reductions over v: row max/argmax/sum + column partials ----------------
// grid 128 blocks x 128 rows; warp per row (16 rows/warp)
__global__ void __launch_bounds__(256) k_vreduce() {
    __shared__ float s_sum[1024];
    __shared__ float s_max[1024];
    int tid = threadIdx.x, l = tid & 31, w = tid >> 5;
    int rbase = blockIdx.x * 128;

    float colsum[8][4], colmax[8][4];
    #pragma unroll
    for (int i = 0; i < 8; i++)
        #pragma unroll
        for (int k = 0; k < 4; k++) { colsum[i][k] = 0.f; colmax[i][k] = 0.f; }

    for (int j = 0; j < 16; j++) {
        int r = rbase + w + j*8;
        const uint2* hp = (const uint2*)(g_vhi + (size_t)r*MM);
        const uint2* lp = (const uint2*)(g_vlo + (size_t)r*MM);
        float rmax = 0.f, rsum = 0.f; int rarg = 0;
        #pragma unroll
        for (int i = 0; i < 8; i++) {
            uint2 hu = hp[i*32 + l];
            uint2 lu = lp[i*32 + l];
            float2 ha = __bfloat1622float2(*(__nv_bfloat162*)&hu.x);
            float2 hb = __bfloat1622float2(*(__nv_bfloat162*)&hu.y);
            float2 la = __bfloat1622float2(*(__nv_bfloat162*)&lu.x);
            float2 lb = __bfloat1622float2(*(__nv_bfloat162*)&lu.y);
            float v0 = ha.x + la.x, v1 = ha.y + la.y;
            float v2 = hb.x + lb.x, v3 = hb.y + lb.y;
            int c0 = i*128 + l*4;
            rsum += (v0 + v1) + (v2 + v3);
            if (v0 > rmax) { rmax = v0; rarg = c0; }
            if (v1 > rmax) { rmax = v1; rarg = c0+1; }
            if (v2 > rmax) { rmax = v2; rarg = c0+2; }
            if (v3 > rmax) { rmax = v3; rarg = c0+3; }
            colsum[i][0] += v0; colmax[i][0] = fmaxf(colmax[i][0], v0);
            colsum[i][1] += v1; colmax[i][1] = fmaxf(colmax[i][1], v1);
            colsum[i][2] += v2; colmax[i][2] = fmaxf(colmax[i][2], v2);
            colsum[i][3] += v3; colmax[i][3] = fmaxf(colmax[i][3], v3);
        }
        #pragma unroll
        for (int o = 16; o > 0; o >>= 1) {
            float om = __shfl_down_sync(0xffffffffu, rmax, o);
            int   oi = __shfl_down_sync(0xffffffffu, rarg, o);
            float os = __shfl_down_sync(0xffffffffu, rsum, o);
            rsum += os;
            if (om > rmax || (om == rmax && oi < rarg)) { rmax = om; rarg = oi; }
        }
        if (l == 0) {
            g_rowmaxv[r] = rmax;
            g_argm[r]    = rarg;
            g_rrowsum[r] = 1.f / rsum;
        }
    }

    // merge column partials across the 8 warps (staged, conflict-light)
    for (int jj = tid; jj < 1024; jj += 256) { s_sum[jj] = 0.f; s_max[jj] = 0.f; }
    __syncthreads();
    for (int ws = 0; ws < 8; ws++) {
        if (w == ws) {
            #pragma unroll
            for (int i = 0; i < 8; i++)
                #pragma unroll
                for (int k = 0; k < 4; k++) {
                    int idx = i*128 + l*4 + k;
                    s_sum[idx] += colsum[i][k];
                    s_max[idx]  = fmaxf(s_max[idx], colmax[i][k]);
                }
        }
        __syncthreads();
    }
    for (int jj = tid; jj < 1024; jj += 256) {
        g_psum[blockIdx.x*MM + jj] = s_sum[jj];
        g_pmax[blockIdx.x*MM + jj] = s_max[jj];
    }
}

__global__ void k_colmerge() {
    int m = blockIdx.x * 256 + threadIdx.x;
    float mx = 0.f, s = 0.f;
    #pragma unroll 4
    for (int p = 0; p < NSPLIT; p++) {
        mx = fmaxf(mx, g_pmax[p*MM + m]);
        s += g_psum[p*MM + m];
    }
    g_colmaxv[m] = mx;
    g_rcolsum[m] = 1.f / s;
}

// ---------------- write sq & sm outputs (reconstruct v from split) ----------------
__global__ void k_sqsm(float* __restrict__ out) {
    int i = blockIdx.x * blockDim.x + threadIdx.x;   // float4 index
    size_t base = (size_t)i * 4;
    int n = (int)(base >> 10);
    int m = (int)(base & 1023);
    uint2 hu = ((const uint2*)g_vhi)[i];
    uint2 lu = ((const uint2*)g_vlo)[i];
    float2 ha = __bfloat1622float2(*(__nv_bfloat162*)&hu.x);
    float2 hb = __bfloat1622float2(*(__nv_bfloat162*)&hu.y);
    float2 la = __bfloat1622float2(*(__nv_bfloat162*)&lu.x);
    float2 lb = __bfloat1622float2(*(__nv_bfloat162*)&lu.y);
    float4 v = make_float4(ha.x + la.x, ha.y + la.y, hb.x + lb.x, hb.y + lb.y);
    float4 rc = reinterpret_cast<const float4*>(g_rcolsum)[m >> 2];
    float  rr = g_rrowsum[n];
    float4 sq = make_float4(v.x*rc.x, v.y*rc.y, v.z*rc.z, v.w*rc.w);
    float4 sm = make_float4(v.x*rr,  v.y*rr,  v.z*rr,  v.w*rr);
    reinterpret_cast<float4*>(out + OFF_SQ)[i] = sq;
    reinterpret_cast<float4*>(out + OFF_SM)[i] = sm;
}

// ---------------- w[n] and similarity loss ----------------
__global__ void k_wsim(const float* __restrict__ ent, float* __restrict__ out) {
    int n = blockIdx.x * blockDim.x + threadIdx.x;
    float local = 0.f;
    if (n < NN) {
        int g = g_argm[n];
        float en = ent[n];
        float entmax = __uint_as_float(g_entmax_bits);
        g_w[n] = (g_rowmaxv[n] / g_colmaxv[g]) * (en / entmax);
        float smax = logf(g_rowmaxv[n]);                  // = max score of row n
        float cosv = smax / fmaxf(g_keynorm[g], 1e-8f);   // ||qr|| == 1
        local = (1.f - cosv) * en;
    }
    __shared__ float red[256];
    red[threadIdx.x] = local;
    __syncthreads();
    for (int o = 128; o > 0; o >>= 1) {
        if (threadIdx.x < o) red[threadIdx.x] += red[threadIdx.x + o];
        __syncthreads();
    }
    if (threadIdx.x == 0) atomicAdd(out + OFF_SIM, red[0]);
}

// ---------------- segment-sum: qupd[g[n], c] += w[n]*qr[n,c] ----------------
__global__ void k_segsum(const float* __restrict__ out) {
    int idx = blockIdx.x * blockDim.x + threadIdx.x;
    if (idx >= BB*CC*HWDIM) return;
    int b = idx >> 19;
    int rem = idx & ((CC*HWDIM) - 1);
    int c = rem >> 10;
    int hw = idx & 1023;
    int n = (b << 10) | hw;
    float val = out[(size_t)b*UQ_STRIDE + rem];           // qr in BCHW layout
    atomicAdd(&g_qupd[(size_t)g_argm[n]*CC + c], g_w[n] * val);
}

// ---------------- updated memory: l2norm(qupd + keys), emit fp32 + bf16 split ----------------
__global__ void k_umem(const float* __restrict__ keys, float* __restrict__ out) {
    int m = blockIdx.x;
    int t = threadIdx.x;   // 128
    float vals[4]; float s = 0.f;
    #pragma unroll
    for (int i = 0; i < 4; i++) {
        int c = t + i*128;
        vals[i] = g_qupd[(size_t)m*CC + c] + keys[(size_t)m*CC + c];
        s += vals[i]*vals[i];
    }
    for (int o = 16; o > 0; o >>= 1) s += __shfl_down_sync(0xffffffffu, s, o);
    __shared__ float red[4]; __shared__ float srn;
    if ((t & 31) == 0) red[t >> 5] = s;
    __syncthreads();
    if (t == 0) srn = 1.f / fmaxf(sqrtf(red[0]+red[1]+red[2]+red[3]), 1e-12f);
    __syncthreads();
    float rn = srn;
    #pragma unroll
    for (int i = 0; i < 4; i++) {
        int c = t + i*128;
        float u = vals[i] * rn;
        out[OFF_UMEM + (size_t)m*CC + c] = u;
        __nv_bfloat16 hi = __float2bfloat16(u);
        g_uhi[(size_t)m*CC + c] = hi;
        g_ulo[(size_t)m*CC + c] = __float2bfloat16(u - __bfloat162float(hi));
    }
}

// ---------------- launch ----------------
extern "C" void kernel_launch(void* const* d_in, const int* in_sizes, int n_in,
                              void* d_out, int out_size) {
    const float* q    = (const float*)d_in[0];
    const float* keys = (const float*)d_in[1];
    const float* ent  = (const float*)d_in[2];
    float* out = (float*)d_out;

    cudaFuncSetAttribute(k_score_mma, cudaFuncAttributeMaxDynamicSharedMemorySize, DSMEM);
    cudaFuncSetAttribute(k_read_mma,  cudaFuncAttributeMaxDynamicSharedMemorySize, DSMEM);
    cudaFuncSetAttribute(k_gram_mma,  cudaFuncAttributeMaxDynamicSharedMemorySize, DSMEM);

    k_init<<<(MM*CC + 255)/256, 256>>>(out);
    k_entmax<<<NN/256, 256>>>(ent);
    k_keynorm<<<MM, 128>>>(keys);
    k_ksplit<<<(MM*CC)/256, 256>>>(keys);
    k_ktrans<<<dim3(MM/32, CC/32), dim3(32, 8)>>>(keys);
    k_rnorm_part<<<dim3(64, 8), 256>>>(q);
    k_rnorm_fin<<<NN/256, 256>>>();
    k_qsplit<<<dim3(HWDIM/32, CC/32, BB), dim3(32, 8)>>>(q, out);
    k_score_mma<<<dim3(MM/128, NN/128), 256, DSMEM>>>();
    k_vreduce<<<NN/128, 256>>>();
    k_colmerge<<<MM/256, 256>>>();
    k_sqsm<<<(NN*MM/4)/256, 256>>>(out);
    k_wsim<<<NN/256, 256>>>(ent, out);
    k_segsum<<<(BB*CC*HWDIM)/256, 256>>>(out);
    k_umem<<<MM, 128>>>(keys, out);
    k_gram_mma<<<dim3(MM/128, MM/128), 256, DSMEM>>>(out);
    k_read_mma<<<dim3(CC/128, NN/128), 256, DSMEM>>>(out);
}

// round 6
// speedup vs baseline: 2.2659x; 1.1044x over previous
#include <cuda_runtime.h>
#include <cuda_bf16.h>
#include <cuda_fp16.h>
#include <math.h>
#include <stdint.h>

#define BB 16
#define CC 512
#define HWDIM 1024
#define NN 16384            // B*H*W
#define MM 1024
#define NSPLIT 128
#define UQ_STRIDE (2*CC*HWDIM)          // per-batch stride of updated_query = 1048576

// output offsets (floats)
#define OFF_UQ   ((size_t)0)
#define OFF_UMEM ((size_t)BB*UQ_STRIDE)                  // 16777216
#define OFF_SQ   (OFF_UMEM + (size_t)MM*CC)              // 17301504
#define OFF_SM   (OFF_SQ + (size_t)NN*MM)                // 34078720
#define OFF_DIV  (OFF_SM + (size_t)NN*MM)                // 50855936
#define OFF_SIM  (OFF_DIV + 1)

// ---------------- scratch (static device globals; no runtime alloc) ----------------
__device__ float g_rnacc[NN];
__device__ float g_rnorm[NN];
__device__ float g_rowmaxv[NN];
__device__ float g_rrowsum[NN];
__device__ int   g_argm[NN];
__device__ float g_w[NN];
__device__ float g_colmaxv[MM];
__device__ float g_rcolsum[MM];
__device__ float g_keynorm[MM];
__device__ float g_pmax[NSPLIT*MM];
__device__ float g_psum[NSPLIT*MM];
__device__ float g_qupd[MM*CC];
__device__ unsigned g_entmax_bits;
// bf16 split operands (score GEMM, 3-term)
__device__ __nv_bfloat16 g_qhi[(size_t)NN*CC];   // qr [N][C] K-major
__device__ __nv_bfloat16 g_qlo[(size_t)NN*CC];
__device__ __nv_bfloat16 g_khi[(size_t)MM*CC];   // keys [M][C]
__device__ __nv_bfloat16 g_klo[(size_t)MM*CC];
// fp16 operands (read/gram GEMMs, 2-term)
__device__ __half g_kThi[(size_t)CC*MM];         // fp16(keys^T) [C][M]
__device__ __half g_vhi[(size_t)NN*MM];          // v split [N][M]
__device__ __half g_vlo[(size_t)NN*MM];
__device__ __half g_uhi[(size_t)MM*CC];          // updated_memory split
__device__ __half g_ulo[(size_t)MM*CC];

// ---------------- PTX helpers (base sm_103-legal only) ----------------
__device__ __forceinline__ uint32_t smem_u32(const void* p) {
    uint32_t a;
    asm("{ .reg .u64 t; cvta.to.shared.u64 t, %1; cvt.u32.u64 %0, t; }" : "=r"(a) : "l"(p));
    return a;
}
__device__ __forceinline__ void ldm_x4(uint32_t* r, uint32_t a) {
    asm volatile("ldmatrix.sync.aligned.m8n8.x4.shared.b16 {%0,%1,%2,%3}, [%4];"
        : "=r"(r[0]), "=r"(r[1]), "=r"(r[2]), "=r"(r[3]) : "r"(a));
}
__device__ __forceinline__ void mma_bf16(float* c, const uint32_t* a, const uint32_t* b) {
    asm volatile("mma.sync.aligned.m16n8k16.row.col.f32.bf16.bf16.f32 "
        "{%0,%1,%2,%3}, {%4,%5,%6,%7}, {%8,%9}, {%0,%1,%2,%3};"
        : "+f"(c[0]), "+f"(c[1]), "+f"(c[2]), "+f"(c[3])
        : "r"(a[0]), "r"(a[1]), "r"(a[2]), "r"(a[3]), "r"(b[0]), "r"(b[1]));
}
__device__ __forceinline__ void mma_f16(float* c, const uint32_t* a, const uint32_t* b) {
    asm volatile("mma.sync.aligned.m16n8k16.row.col.f32.f16.f16.f32 "
        "{%0,%1,%2,%3}, {%4,%5,%6,%7}, {%8,%9}, {%0,%1,%2,%3};"
        : "+f"(c[0]), "+f"(c[1]), "+f"(c[2]), "+f"(c[3])
        : "r"(a[0]), "r"(a[1]), "r"(a[2]), "r"(a[3]), "r"(b[0]), "r"(b[1]));
}
__device__ __forceinline__ void cpa16(uint32_t dst, const void* src) {
    asm volatile("cp.async.ca.shared.global [%0], [%1], 16;" :: "r"(dst), "l"(src));
}
#define CP_COMMIT asm volatile("cp.async.commit_group;" ::: "memory")
#define CP_WAIT2  asm volatile("cp.async.wait_group 2;" ::: "memory")
#define CP_WAIT1  asm volatile("cp.async.wait_group 1;" ::: "memory")
#define CP_WAIT0  asm volatile("cp.async.wait_group 0;" ::: "memory")

// ---------------- small kernels ----------------

__global__ void k_init(float* out) {
    int i = blockIdx.x * blockDim.x + threadIdx.x;
    if (i < MM*CC) g_qupd[i] = 0.f;
    if (i < NN) g_rnacc[i] = 0.f;
    if (i == 0) {
        g_entmax_bits = 0u;
        out[OFF_DIV] = 0.f;
        out[OFF_SIM] = 0.f;
    }
}

__global__ void k_entmax(const float* __restrict__ ent) {
    int i = blockIdx.x * blockDim.x + threadIdx.x;
    if (i < NN) atomicMax(&g_entmax_bits, __float_as_uint(ent[i])); // entropy > 0
}

__global__ void k_keynorm(const float* __restrict__ keys) {
    int m = blockIdx.x;
    int t = threadIdx.x;   // 128 threads
    float s = 0.f;
    #pragma unroll
    for (int i = 0; i < 4; i++) {
        float v = keys[(size_t)m*CC + t + i*128];
        s += v*v;
    }
    for (int o = 16; o > 0; o >>= 1) s += __shfl_down_sync(0xffffffffu, s, o);
    __shared__ float red[4];
    if ((t & 31) == 0) red[t >> 5] = s;
    __syncthreads();
    if (t == 0) g_keynorm[m] = sqrtf(red[0] + red[1] + red[2] + red[3]);
}

// keys -> bf16 hi/lo split ([M][C] K-major for score B)
__global__ void k_ksplit(const float* __restrict__ keys) {
    int i = blockIdx.x * blockDim.x + threadIdx.x;   // over M*C
    float v = keys[i];
    __nv_bfloat16 hi = __float2bfloat16(v);
    float lo = v - __bfloat162float(hi);
    g_khi[i] = hi;
    g_klo[i] = __float2bfloat16(lo);
}

// fp16(keys^T) ([C][M] K-major-in-m for read B)
__global__ void k_ktrans(const float* __restrict__ keys) {
    __shared__ float t[32][33];
    int m0 = blockIdx.x * 32, c0 = blockIdx.y * 32;
    int tx = threadIdx.x, ty = threadIdx.y;  // 32 x 8
    #pragma unroll
    for (int i = 0; i < 4; i++)
        t[ty + i*8][tx] = keys[(size_t)(m0 + ty + i*8)*CC + c0 + tx];
    __syncthreads();
    #pragma unroll
    for (int i = 0; i < 4; i++) {
        float v = t[tx][ty + i*8];        // = keys[m0+tx][c0+ty+i*8]
        g_kThi[(size_t)(c0 + ty + i*8)*MM + m0 + tx] = __float2half_rn(v);
    }
}

// partial sum-of-squares over 64-channel chunks (grid 64 x 8)
__global__ void k_rnorm_part(const float* __restrict__ q) {
    int n = blockIdx.x * 256 + threadIdx.x;
    int b = n >> 10, hw = n & 1023;
    const float* base = q + (size_t)b*CC*HWDIM + (size_t)(blockIdx.y*64)*HWDIM + hw;
    float s = 0.f;
    #pragma unroll 8
    for (int c = 0; c < 64; c++) {
        float v = base[(size_t)c*HWDIM];
        s += v*v;
    }
    atomicAdd(&g_rnacc[n], s);
}

__global__ void k_rnorm_fin() {
    int n = blockIdx.x * blockDim.x + threadIdx.x;
    if (n < NN) g_rnorm[n] = 1.f / fmaxf(sqrtf(g_rnacc[n]), 1e-12f);
}

// normalize q, write fp32 qr into out (BCHW) AND transposed bf16 hi/lo [N][C]
__global__ void k_qsplit(const float* __restrict__ q, float* __restrict__ out) {
    __shared__ float tile[32][33];
    int b  = blockIdx.z;
    int c0 = blockIdx.y * 32, hw0 = blockIdx.x * 32;
    int tx = threadIdx.x, ty = threadIdx.y;   // 32 x 8
    const float* src = q + (size_t)b*CC*HWDIM;
    float* dst = out + (size_t)b*UQ_STRIDE;
    #pragma unroll
    for (int i = 0; i < 4; i++) {
        int c  = c0 + ty + i*8;
        int hw = hw0 + tx;
        float v = src[(size_t)c*HWDIM + hw] * g_rnorm[(b<<10) | hw];
        dst[(size_t)c*HWDIM + hw] = v;
        tile[ty + i*8][tx] = v;
    }
    __syncthreads();
    #pragma unroll
    for (int i = 0; i < 4; i++) {
        int hw = hw0 + ty + i*8;
        int n  = (b<<10) | hw;
        float v = tile[tx][ty + i*8];
        __nv_bfloat16 hi = __float2bfloat16(v);
        float lo = v - __bfloat162float(hi);
        g_qhi[(size_t)n*CC + c0 + tx] = hi;
        g_qlo[(size_t)n*CC + c0 + tx] = __float2bfloat16(lo);
    }
}

// ---------------- HMMA score GEMM: v[n,m] = exp(qr . keys^T), bf16 3-term split ----------------
// block 128x128, warp grid 2x4 (warp tile 64x32), stage K=32, ring of 4 buffers
#define GBUF 10240      // 128 rows * 80B (32 bf16 + 16B pad)
#define DSMEM (8*GBUF)  // 4 A bufs + 4 B bufs = 81920

__global__ void __launch_bounds__(256, 2) k_score_mma() {
    extern __shared__ __align__(16) char dsm[];
    int tid = threadIdx.x, l = tid & 31, w = tid >> 5;
    int wr = w >> 2, wc = w & 3;
    int m0 = blockIdx.x * 128, n0 = blockIdx.y * 128;
    const __nv_bfloat16* Ap[3] = {g_qhi, g_qhi, g_qlo};
    const __nv_bfloat16* Bp[3] = {g_khi, g_klo, g_khi};
    uint32_t as0 = smem_u32(dsm);
    uint32_t bs0 = as0 + 4*GBUF;

    float acc[4][4][4];
    #pragma unroll
    for (int i = 0; i < 4; i++)
        #pragma unroll
        for (int j = 0; j < 4; j++)
            #pragma unroll
            for (int k = 0; k < 4; k++) acc[i][j][k] = 0.f;

    int row2 = tid >> 2, ch = tid & 3;
    auto stage = [&](int it, int buf) {
        int seg = it >> 4;
        int k0b = (it & 15) * 64;                       // 32 bf16 = 64B
        const char* Ab = (const char*)Ap[seg] + (size_t)n0*1024 + k0b;
        const char* Bb = (const char*)Bp[seg] + (size_t)m0*1024 + k0b;
        #pragma unroll
        for (int t = 0; t < 2; t++) {
            int r = row2 + t*64;
            cpa16(as0 + buf*GBUF + r*80 + ch*16, Ab + (size_t)r*1024 + ch*16);
            cpa16(bs0 + buf*GBUF + r*80 + ch*16, Bb + (size_t)r*1024 + ch*16);
        }
        CP_COMMIT;
    };

    uint32_t a_off = (uint32_t)((l & 15)*80 + (l >> 4)*16);
    uint32_t b_off = (uint32_t)(((((l >> 4) & 1)*8) + (l & 7))*80 + ((l >> 3) & 1)*16);

    stage(0, 0); stage(1, 1); stage(2, 2);
    const int NIT = 48;
    for (int it = 0; it < NIT; it++) {
        int buf = it & 3;
        int rem = NIT - 1 - it;
        if (rem >= 2) CP_WAIT2; else if (rem == 1) CP_WAIT1; else CP_WAIT0;
        __syncthreads();
        if (it + 3 < NIT) stage(it + 3, (it + 3) & 3);
        #pragma unroll
        for (int h = 0; h < 2; h++) {
            uint32_t a[4][4];
            #pragma unroll
            for (int fi = 0; fi < 4; fi++)
                ldm_x4(a[fi], as0 + buf*GBUF + (wr*64 + fi*16)*80 + h*32 + a_off);
            uint32_t bfr[2][4];
            #pragma unroll
            for (int jp = 0; jp < 2; jp++)
                ldm_x4(bfr[jp], bs0 + buf*GBUF + (wc*32 + jp*16)*80 + h*32 + b_off);
            #pragma unroll
            for (int fi = 0; fi < 4; fi++)
                #pragma unroll
                for (int fj = 0; fj < 4; fj++)
                    mma_bf16(acc[fi][fj], a[fi], &bfr[fj >> 1][(fj & 1)*2]);
        }
    }

    // epilogue: exp + fp16 hi/lo split of v
    int g = l >> 2, t2 = (l & 3)*2;
    #pragma unroll
    for (int fi = 0; fi < 4; fi++) {
        int r0 = n0 + wr*64 + fi*16 + g;
        #pragma unroll
        for (int fj = 0; fj < 4; fj++) {
            int c = m0 + wc*32 + fj*8 + t2;
            float* p = acc[fi][fj];
            #pragma unroll
            for (int hh = 0; hh < 2; hh++) {
                int r = r0 + hh*8;
                float e0 = __expf(p[hh*2 + 0]);
                float e1 = __expf(p[hh*2 + 1]);
                size_t o = (size_t)r*MM + c;
                __half h0 = __float2half_rn(e0);
                __half h1 = __float2half_rn(e1);
                __half2 hv; hv.x = h0; hv.y = h1;
                *(__half2*)(g_vhi + o) = hv;
                __half2 lv;
                lv.x = __float2half_rn(e0 - __half2float(h0));
                lv.y = __float2half_rn(e1 - __half2float(h1));
                *(__half2*)(g_vlo + o) = lv;
            }
        }
    }
}

// ---------------- HMMA read GEMM (fp16, 2-term): concat = rrowsum * (vhi+vlo) . fp16(k)^T ----------------
__global__ void __launch_bounds__(256, 2) k_read_mma(float* __restrict__ out) {
    extern __shared__ __align__(16) char dsm[];
    int tid = threadIdx.x, l = tid & 31, w = tid >> 5;
    int wr = w >> 2, wc = w & 3;
    int c0 = blockIdx.x * 128, n0 = blockIdx.y * 128;
    const __half* Ap[2] = {g_vhi, g_vlo};
    uint32_t as0 = smem_u32(dsm);
    uint32_t bs0 = as0 + 4*GBUF;

    float acc[4][4][4];
    #pragma unroll
    for (int i = 0; i < 4; i++)
        #pragma unroll
        for (int j = 0; j < 4; j++)
            #pragma unroll
            for (int k = 0; k < 4; k++) acc[i][j][k] = 0.f;

    int row2 = tid >> 2, ch = tid & 3;
    auto stage = [&](int it, int buf) {
        int seg = it >> 5;
        int k0b = (it & 31) * 64;
        const char* Ab = (const char*)Ap[seg] + (size_t)n0*2048 + k0b;
        const char* Bb = (const char*)g_kThi + (size_t)c0*2048 + k0b;
        #pragma unroll
        for (int t = 0; t < 2; t++) {
            int r = row2 + t*64;
            cpa16(as0 + buf*GBUF + r*80 + ch*16, Ab + (size_t)r*2048 + ch*16);
            cpa16(bs0 + buf*GBUF + r*80 + ch*16, Bb + (size_t)r*2048 + ch*16);
        }
        CP_COMMIT;
    };

    uint32_t a_off = (uint32_t)((l & 15)*80 + (l >> 4)*16);
    uint32_t b_off = (uint32_t)(((((l >> 4) & 1)*8) + (l & 7))*80 + ((l >> 3) & 1)*16);

    stage(0, 0); stage(1, 1); stage(2, 2);
    const int NIT = 64;
    for (int it = 0; it < NIT; it++) {
        int buf = it & 3;
        int rem = NIT - 1 - it;
        if (rem >= 2) CP_WAIT2; else if (rem == 1) CP_WAIT1; else CP_WAIT0;
        __syncthreads();
        if (it + 3 < NIT) stage(it + 3, (it + 3) & 3);
        #pragma unroll
        for (int h = 0; h < 2; h++) {
            uint32_t a[4][4];
            #pragma unroll
            for (int fi = 0; fi < 4; fi++)
                ldm_x4(a[fi], as0 + buf*GBUF + (wr*64 + fi*16)*80 + h*32 + a_off);
            uint32_t bfr[2][4];
            #pragma unroll
            for (int jp = 0; jp < 2; jp++)
                ldm_x4(bfr[jp], bs0 + buf*GBUF + (wc*32 + jp*16)*80 + h*32 + b_off);
            #pragma unroll
            for (int fi = 0; fi < 4; fi++)
                #pragma unroll
                for (int fj = 0; fj < 4; fj++)
                    mma_f16(acc[fi][fj], a[fi], &bfr[fj >> 1][(fj & 1)*2]);
        }
    }

    // epilogue: scale by rrowsum, write BCHW channels [C, 2C)
    int g = l >> 2, t2 = (l & 3)*2;
    int b = n0 >> 10;
    int hwb = n0 & 1023;
    float* obase = out + (size_t)b*UQ_STRIDE;
    #pragma unroll
    for (int fi = 0; fi < 4; fi++) {
        int rl0 = wr*64 + fi*16 + g;
        float rs0 = g_rrowsum[n0 + rl0];
        float rs1 = g_rrowsum[n0 + rl0 + 8];
        #pragma unroll
        for (int fj = 0; fj < 4; fj++) {
            int c = c0 + wc*32 + fj*8 + t2;
            float* p = acc[fi][fj];
            size_t a0 = (size_t)(CC + c)*HWDIM + hwb + rl0;
            obase[a0]              = p[0] * rs0;
            obase[a0 + HWDIM]      = p[1] * rs0;
            obase[a0 + 8]          = p[2] * rs1;
            obase[a0 + HWDIM + 8]  = p[3] * rs1;
        }
    }
}

// ---------------- HMMA gram GEMM (fp16, 2-term): diversity(updated_memory) ----------------
__global__ void __launch_bounds__(256, 2) k_gram_mma(float* __restrict__ out) {
    extern __shared__ __align__(16) char dsm[];
    __shared__ float red[256];
    int tid = threadIdx.x, l = tid & 31, w = tid >> 5;
    int wr = w >> 2, wc = w & 3;
    int j0 = blockIdx.x * 128, i0 = blockIdx.y * 128;
    const __half* Ap[2] = {g_uhi, g_ulo};
    uint32_t as0 = smem_u32(dsm);
    uint32_t bs0 = as0 + 4*GBUF;

    float acc[4][4][4];
    #pragma unroll
    for (int i = 0; i < 4; i++)
        #pragma unroll
        for (int j = 0; j < 4; j++)
            #pragma unroll
            for (int k = 0; k < 4; k++) acc[i][j][k] = 0.f;

    int row2 = tid >> 2, ch = tid & 3;
    auto stage = [&](int it, int buf) {
        int seg = it >> 4;
        int k0b = (it & 15) * 64;
        const char* Ab = (const char*)Ap[seg] + (size_t)i0*1024 + k0b;
        const char* Bb = (const char*)g_uhi + (size_t)j0*1024 + k0b;
        #pragma unroll
        for (int t = 0; t < 2; t++) {
            int r = row2 + t*64;
            cpa16(as0 + buf*GBUF + r*80 + ch*16, Ab + (size_t)r*1024 + ch*16);
            cpa16(bs0 + buf*GBUF + r*80 + ch*16, Bb + (size_t)r*1024 + ch*16);
        }
        CP_COMMIT;
    };

    uint32_t a_off = (uint32_t)((l & 15)*80 + (l >> 4)*16);
    uint32_t b_off = (uint32_t)(((((l >> 4) & 1)*8) + (l & 7))*80 + ((l >> 3) & 1)*16);

    stage(0, 0); stage(1, 1); stage(2, 2);
    const int NIT = 32;
    for (int it = 0; it < NIT; it++) {
        int buf = it & 3;
        int rem = NIT - 1 - it;
        if (rem >= 2) CP_WAIT2; else if (rem == 1) CP_WAIT1; else CP_WAIT0;
        __syncthreads();
        if (it + 3 < NIT) stage(it + 3, (it + 3) & 3);
        #pragma unroll
        for (int h = 0; h < 2; h++) {
            uint32_t a[4][4];
            #pragma unroll
            for (int fi = 0; fi < 4; fi++)
                ldm_x4(a[fi], as0 + buf*GBUF + (wr*64 + fi*16)*80 + h*32 + a_off);
            uint32_t bfr[2][4];
            #pragma unroll
            for (int jp = 0; jp < 2; jp++)
                ldm_x4(bfr[jp], bs0 + buf*GBUF + (wc*32 + jp*16)*80 + h*32 + b_off);
            #pragma unroll
            for (int fi = 0; fi < 4; fi++)
                #pragma unroll
                for (int fj = 0; fj < 4; fj++)
                    mma_f16(acc[fi][fj], a[fi], &bfr[fj >> 1][(fj & 1)*2]);
        }
    }

    // epilogue: sum of squared off-diagonal gram entries
    int g = l >> 2, t2 = (l & 3)*2;
    float local = 0.f;
    #pragma unroll
    for (int fi = 0; fi < 4; fi++) {
        int r0 = i0 + wr*64 + fi*16 + g;
        #pragma unroll
        for (int fj = 0; fj < 4; fj++) {
            int c = j0 + wc*32 + fj*8 + t2;
            float* p = acc[fi][fj];
            if (r0 != c)         local += p[0]*p[0];
            if (r0 != c + 1)     local += p[1]*p[1];
            if (r0 + 8 != c)     local += p[2]*p[2];
            if (r0 + 8 != c + 1) local += p[3]*p[3];
        }
    }
    red[tid] = local;
    __syncthreads();
    for (int o = 128; o > 0; o >>= 1) {
        if (tid < o) red[tid] += red[tid + o];
        __syncthreads();
    }
    if (tid == 0) atomicAdd(out + OFF_DIV, red[0] * (1.f / (float)(MM*MM - MM)));
}

// ---------------- fused reductions over v: row max/argmax/sum + column partials ----------------
__global__ void __launch_bounds__(256) k_vreduce() {
    __shared__ float s_sum[1024];
    __shared__ float s_max[1024];
    int tid = threadIdx.x, l = tid & 31, w = tid >> 5;
    int rbase = blockIdx.x * 128;

    float colsum[8][4], colmax[8][4];
    #pragma unroll
    for (int i = 0; i < 8; i++)
        #pragma unroll
        for (int k = 0; k < 4; k++) { colsum[i][k] = 0.f; colmax[i][k] = 0.f; }

    for (int j = 0; j < 16; j++) {
        int r = rbase + w + j*8;
        const uint2* hp = (const uint2*)(g_vhi + (size_t)r*MM);
        const uint2* lp = (const uint2*)(g_vlo + (size_t)r*MM);
        float rmax = 0.f, rsum = 0.f; int rarg = 0;
        #pragma unroll
        for (int i = 0; i < 8; i++) {
            uint2 hu = hp[i*32 + l];
            uint2 lu = lp[i*32 + l];
            float2 ha = __half22float2(*(__half2*)&hu.x);
            float2 hb = __half22float2(*(__half2*)&hu.y);
            float2 la = __half22float2(*(__half2*)&lu.x);
            float2 lb = __half22float2(*(__half2*)&lu.y);
            float v0 = ha.x + la.x, v1 = ha.y + la.y;
            float v2 = hb.x + lb.x, v3 = hb.y + lb.y;
            int c0 = i*128 + l*4;
            rsum += (v0 + v1) + (v2 + v3);
            if (v0 > rmax) { rmax = v0; rarg = c0; }
            if (v1 > rmax) { rmax = v1; rarg = c0+1; }
            if (v2 > rmax) { rmax = v2; rarg = c0+2; }
            if (v3 > rmax) { rmax = v3; rarg = c0+3; }
            colsum[i][0] += v0; colmax[i][0] = fmaxf(colmax[i][0], v0);
            colsum[i][1] += v1; colmax[i][1] = fmaxf(colmax[i][1], v1);
            colsum[i][2] += v2; colmax[i][2] = fmaxf(colmax[i][2], v2);
            colsum[i][3] += v3; colmax[i][3] = fmaxf(colmax[i][3], v3);
        }
        #pragma unroll
        for (int o = 16; o > 0; o >>= 1) {
            float om = __shfl_down_sync(0xffffffffu, rmax, o);
            int   oi = __shfl_down_sync(0xffffffffu, rarg, o);
            float os = __shfl_down_sync(0xffffffffu, rsum, o);
            rsum += os;
            if (om > rmax || (om == rmax && oi < rarg)) { rmax = om; rarg = oi; }
        }
        if (l == 0) {
            g_rowmaxv[r] = rmax;
            g_argm[r]    = rarg;
            g_rrowsum[r] = 1.f / rsum;
        }
    }

    for (int jj = tid; jj < 1024; jj += 256) { s_sum[jj] = 0.f; s_max[jj] = 0.f; }
    __syncthreads();
    for (int ws = 0; ws < 8; ws++) {
        if (w == ws) {
            #pragma unroll
            for (int i = 0; i < 8; i++)
                #pragma unroll
                for (int k = 0; k < 4; k++) {
                    int idx = i*128 + l*4 + k;
                    s_sum[idx] += colsum[i][k];
                    s_max[idx]  = fmaxf(s_max[idx], colmax[i][k]);
                }
        }
        __syncthreads();
    }
    for (int jj = tid; jj < 1024; jj += 256) {
        g_psum[blockIdx.x*MM + jj] = s_sum[jj];
        g_pmax[blockIdx.x*MM + jj] = s_max[jj];
    }
}

__global__ void k_colmerge() {
    int m = blockIdx.x * 256 + threadIdx.x;
    float mx = 0.f, s = 0.f;
    #pragma unroll 4
    for (int p = 0; p < NSPLIT; p++) {
        mx = fmaxf(mx, g_pmax[p*MM + m]);
        s += g_psum[p*MM + m];
    }
    g_colmaxv[m] = mx;
    g_rcolsum[m] = 1.f / s;
}

// ---------------- write sq & sm outputs (reconstruct v from split) ----------------
__global__ void k_sqsm(float* __restrict__ out) {
    int i = blockIdx.x * blockDim.x + threadIdx.x;   // 4-element group index
    size_t base = (size_t)i * 4;
    int n = (int)(base >> 10);
    int m = (int)(base & 1023);
    uint2 hu = ((const uint2*)g_vhi)[i];
    uint2 lu = ((const uint2*)g_vlo)[i];
    float2 ha = __half22float2(*(__half2*)&hu.x);
    float2 hb = __half22float2(*(__half2*)&hu.y);
    float2 la = __half22float2(*(__half2*)&lu.x);
    float2 lb = __half22float2(*(__half2*)&lu.y);
    float4 v = make_float4(ha.x + la.x, ha.y + la.y, hb.x + lb.x, hb.y + lb.y);
    float4 rc = reinterpret_cast<const float4*>(g_rcolsum)[m >> 2];
    float  rr = g_rrowsum[n];
    float4 sq = make_float4(v.x*rc.x, v.y*rc.y, v.z*rc.z, v.w*rc.w);
    float4 sm = make_float4(v.x*rr,  v.y*rr,  v.z*rr,  v.w*rr);
    reinterpret_cast<float4*>(out + OFF_SQ)[i] = sq;
    reinterpret_cast<float4*>(out + OFF_SM)[i] = sm;
}

// ---------------- w[n] and similarity loss ----------------
__global__ void k_wsim(const float* __restrict__ ent, float* __restrict__ out) {
    int n = blockIdx.x * blockDim.x + threadIdx.x;
    float local = 0.f;
    if (n < NN) {
        int g = g_argm[n];
        float en = ent[n];
        float entmax = __uint_as_float(g_entmax_bits);
        g_w[n] = (g_rowmaxv[n] / g_colmaxv[g]) * (en / entmax);
        float smax = logf(g_rowmaxv[n]);                  // = max score of row n
        float cosv = smax / fmaxf(g_keynorm[g], 1e-8f);   // ||qr|| == 1
        local = (1.f - cosv) * en;
    }
    __shared__ float red[256];
    red[threadIdx.x] = local;
    __syncthreads();
    for (int o = 128; o > 0; o >>= 1) {
        if (threadIdx.x < o) red[threadIdx.x] += red[threadIdx.x + o];
        __syncthreads();
    }
    if (threadIdx.x == 0) atomicAdd(out + OFF_SIM, red[0]);
}

// ---------------- segment-sum: qupd[g[n], c] += w[n]*qr[n,c] ----------------
__global__ void k_segsum(const float* __restrict__ out) {
    int idx = blockIdx.x * blockDim.x + threadIdx.x;
    if (idx >= BB*CC*HWDIM) return;
    int b = idx >> 19;
    int rem = idx & ((CC*HWDIM) - 1);
    int c = rem >> 10;
    int hw = idx & 1023;
    int n = (b << 10) | hw;
    float val = out[(size_t)b*UQ_STRIDE + rem];           // qr in BCHW layout
    atomicAdd(&g_qupd[(size_t)g_argm[n]*CC + c], g_w[n] * val);
}

// ---------------- updated memory: l2norm(qupd + keys), emit fp32 + fp16 split ----------------
__global__ void k_umem(const float* __restrict__ keys, float* __restrict__ out) {
    int m = blockIdx.x;
    int t = threadIdx.x;   // 128
    float vals[4]; float s = 0.f;
    #pragma unroll
    for (int i = 0; i < 4; i++) {
        int c = t + i*128;
        vals[i] = g_qupd[(size_t)m*CC + c] + keys[(size_t)m*CC + c];
        s += vals[i]*vals[i];
    }
    for (int o = 16; o > 0; o >>= 1) s += __shfl_down_sync(0xffffffffu, s, o);
    __shared__ float red[4]; __shared__ float srn;
    if ((t & 31) == 0) red[t >> 5] = s;
    __syncthreads();
    if (t == 0) srn = 1.f / fmaxf(sqrtf(red[0]+red[1]+red[2]+red[3]), 1e-12f);
    __syncthreads();
    float rn = srn;
    #pragma unroll
    for (int i = 0; i < 4; i++) {
        int c = t + i*128;
        float u = vals[i] * rn;
        out[OFF_UMEM + (size_t)m*CC + c] = u;
        __half hi = __float2half_rn(u);
        g_uhi[(size_t)m*CC + c] = hi;
        g_ulo[(size_t)m*CC + c] = __float2half_rn(u - __half2float(hi));
    }
}

// ---------------- launch ----------------
extern "C" void kernel_launch(void* const* d_in, const int* in_sizes, int n_in,
                              void* d_out, int out_size) {
    const float* q    = (const float*)d_in[0];
    const float* keys = (const float*)d_in[1];
    const float* ent  = (const float*)d_in[2];
    float* out = (float*)d_out;

    cudaFuncSetAttribute(k_score_mma, cudaFuncAttributeMaxDynamicSharedMemorySize, DSMEM);
    cudaFuncSetAttribute(k_read_mma,  cudaFuncAttributeMaxDynamicSharedMemorySize, DSMEM);
    cudaFuncSetAttribute(k_gram_mma,  cudaFuncAttributeMaxDynamicSharedMemorySize, DSMEM);

    k_init<<<(MM*CC + 255)/256, 256>>>(out);
    k_entmax<<<NN/256, 256>>>(ent);
    k_keynorm<<<MM, 128>>>(keys);
    k_ksplit<<<(MM*CC)/256, 256>>>(keys);
    k_ktrans<<<dim3(MM/32, CC/32), dim3(32, 8)>>>(keys);
    k_rnorm_part<<<dim3(64, 8), 256>>>(q);
    k_rnorm_fin<<<NN/256, 256>>>();
    k_qsplit<<<dim3(HWDIM/32, CC/32, BB), dim3(32, 8)>>>(q, out);
    k_score_mma<<<dim3(MM/128, NN/128), 256, DSMEM>>>();
    k_vreduce<<<NN/128, 256>>>();
    k_colmerge<<<MM/256, 256>>>();
    k_sqsm<<<(NN*MM/4)/256, 256>>>(out);
    k_wsim<<<NN/256, 256>>>(ent, out);
    k_segsum<<<(BB*CC*HWDIM)/256, 256>>>(out);
    k_umem<<<MM, 128>>>(keys, out);
    k_gram_mma<<<dim3(MM/128, MM/128), 256, DSMEM>>>(out);
    k_read_mma<<<dim3(CC/128, NN/128), 256, DSMEM>>>(out);
}

// round 7
// speedup vs baseline: 2.3870x; 1.0534x over previous
#include <cuda_runtime.h>
#include <cuda_bf16.h>
#include <cuda_fp16.h>
#include <math.h>
#include <stdint.h>

#define BB 16
#define CC 512
#define HWDIM 1024
#define NN 16384            // B*H*W
#define MM 1024
#define NSPLIT 128
#define UQ_STRIDE (2*CC*HWDIM)          // per-batch stride of updated_query = 1048576

// output offsets (floats)
#define OFF_UQ   ((size_t)0)
#define OFF_UMEM ((size_t)BB*UQ_STRIDE)                  // 16777216
#define OFF_SQ   (OFF_UMEM + (size_t)MM*CC)              // 17301504
#define OFF_SM   (OFF_SQ + (size_t)NN*MM)                // 34078720
#define OFF_DIV  (OFF_SM + (size_t)NN*MM)                // 50855936
#define OFF_SIM  (OFF_DIV + 1)

// ---------------- scratch (static device globals; no runtime alloc) ----------------
__device__ float g_rnacc[NN];
__device__ float g_rowmaxv[NN];
__device__ float g_rrowsum[NN];
__device__ int   g_argm[NN];
__device__ float g_w[NN];
__device__ float g_colmaxv[MM];
__device__ float g_rcolsum[MM];
__device__ float g_keynorm[MM];
__device__ float g_pmax[NSPLIT*MM];
__device__ float g_psum[NSPLIT*MM];
__device__ float g_qupd[MM*CC];
__device__ unsigned g_entmax_bits;
// bf16 split operands (score GEMM, 3-term)
__device__ __nv_bfloat16 g_qhi[(size_t)NN*CC];   // qr [N][C] K-major
__device__ __nv_bfloat16 g_qlo[(size_t)NN*CC];
__device__ __nv_bfloat16 g_khi[(size_t)MM*CC];   // keys [M][C]
__device__ __nv_bfloat16 g_klo[(size_t)MM*CC];
// fp16 operands (read/gram GEMMs, 2-term)
__device__ __half g_kThi[(size_t)CC*MM];         // fp16(keys^T) [C][M]
__device__ __half g_vhi[(size_t)NN*MM];          // v split [N][M]
__device__ __half g_vlo[(size_t)NN*MM];
__device__ __half g_uhi[(size_t)MM*CC];          // updated_memory split
__device__ __half g_ulo[(size_t)MM*CC];

// ---------------- PTX helpers (base sm_103-legal only) ----------------
__device__ __forceinline__ uint32_t smem_u32(const void* p) {
    uint32_t a;
    asm("{ .reg .u64 t; cvta.to.shared.u64 t, %1; cvt.u32.u64 %0, t; }" : "=r"(a) : "l"(p));
    return a;
}
__device__ __forceinline__ void ldm_x4(uint32_t* r, uint32_t a) {
    asm volatile("ldmatrix.sync.aligned.m8n8.x4.shared.b16 {%0,%1,%2,%3}, [%4];"
        : "=r"(r[0]), "=r"(r[1]), "=r"(r[2]), "=r"(r[3]) : "r"(a));
}
__device__ __forceinline__ void mma_bf16(float* c, const uint32_t* a, const uint32_t* b) {
    asm volatile("mma.sync.aligned.m16n8k16.row.col.f32.bf16.bf16.f32 "
        "{%0,%1,%2,%3}, {%4,%5,%6,%7}, {%8,%9}, {%0,%1,%2,%3};"
        : "+f"(c[0]), "+f"(c[1]), "+f"(c[2]), "+f"(c[3])
        : "r"(a[0]), "r"(a[1]), "r"(a[2]), "r"(a[3]), "r"(b[0]), "r"(b[1]));
}
__device__ __forceinline__ void mma_f16(float* c, const uint32_t* a, const uint32_t* b) {
    asm volatile("mma.sync.aligned.m16n8k16.row.col.f32.f16.f16.f32 "
        "{%0,%1,%2,%3}, {%4,%5,%6,%7}, {%8,%9}, {%0,%1,%2,%3};"
        : "+f"(c[0]), "+f"(c[1]), "+f"(c[2]), "+f"(c[3])
        : "r"(a[0]), "r"(a[1]), "r"(a[2]), "r"(a[3]), "r"(b[0]), "r"(b[1]));
}
__device__ __forceinline__ void cpa16(uint32_t dst, const void* src) {
    asm volatile("cp.async.ca.shared.global [%0], [%1], 16;" :: "r"(dst), "l"(src));
}
#define CP_COMMIT asm volatile("cp.async.commit_group;" ::: "memory")
#define CP_WAIT2  asm volatile("cp.async.wait_group 2;" ::: "memory")
#define CP_WAIT1  asm volatile("cp.async.wait_group 1;" ::: "memory")
#define CP_WAIT0  asm volatile("cp.async.wait_group 0;" ::: "memory")

// ---------------- small kernels ----------------

// init scratch + entropy max (atomicMax idempotent across graph replays: start <= max)
__global__ void k_init(const float* __restrict__ ent, float* __restrict__ out) {
    int i = blockIdx.x * blockDim.x + threadIdx.x;
    if (i < MM*CC) g_qupd[i] = 0.f;
    if (i < NN) {
        g_rnacc[i] = 0.f;
        atomicMax(&g_entmax_bits, __float_as_uint(ent[i])); // entropy > 0
    }
    if (i == 0) {
        out[OFF_DIV] = 0.f;
        out[OFF_SIM] = 0.f;
    }
}

__global__ void k_keynorm(const float* __restrict__ keys) {
    int m = blockIdx.x;
    int t = threadIdx.x;   // 128 threads
    float s = 0.f;
    #pragma unroll
    for (int i = 0; i < 4; i++) {
        float v = keys[(size_t)m*CC + t + i*128];
        s += v*v;
    }
    for (int o = 16; o > 0; o >>= 1) s += __shfl_down_sync(0xffffffffu, s, o);
    __shared__ float red[4];
    if ((t & 31) == 0) red[t >> 5] = s;
    __syncthreads();
    if (t == 0) g_keynorm[m] = sqrtf(red[0] + red[1] + red[2] + red[3]);
}

// keys -> bf16 hi/lo split [M][C] AND fp16(keys^T) [C][M]
__global__ void k_keys(const float* __restrict__ keys) {
    __shared__ float t[32][33];
    int m0 = blockIdx.x * 32, c0 = blockIdx.y * 32;
    int tx = threadIdx.x, ty = threadIdx.y;  // 32 x 8
    #pragma unroll
    for (int i = 0; i < 4; i++) {
        int row = ty + i*8;
        size_t o = (size_t)(m0 + row)*CC + c0 + tx;
        float v = keys[o];
        t[row][tx] = v;
        __nv_bfloat16 hi = __float2bfloat16(v);
        g_khi[o] = hi;
        g_klo[o] = __float2bfloat16(v - __bfloat162float(hi));
    }
    __syncthreads();
    #pragma unroll
    for (int i = 0; i < 4; i++) {
        float v = t[tx][ty + i*8];        // = keys[m0+tx][c0+ty+i*8]
        g_kThi[(size_t)(c0 + ty + i*8)*MM + m0 + tx] = __float2half_rn(v);
    }
}

// partial sum-of-squares over 64-channel chunks (grid 64 x 8)
__global__ void k_rnorm_part(const float* __restrict__ q) {
    int n = blockIdx.x * 256 + threadIdx.x;
    int b = n >> 10, hw = n & 1023;
    const float* base = q + (size_t)b*CC*HWDIM + (size_t)(blockIdx.y*64)*HWDIM + hw;
    float s = 0.f;
    #pragma unroll 8
    for (int c = 0; c < 64; c++) {
        float v = base[(size_t)c*HWDIM];
        s += v*v;
    }
    atomicAdd(&g_rnacc[n], s);
}

// normalize q, write fp32 qr into out (BCHW) AND transposed bf16 hi/lo [N][C]
__global__ void k_qsplit(const float* __restrict__ q, float* __restrict__ out) {
    __shared__ float tile[32][33];
    int b  = blockIdx.z;
    int c0 = blockIdx.y * 32, hw0 = blockIdx.x * 32;
    int tx = threadIdx.x, ty = threadIdx.y;   // 32 x 8
    const float* src = q + (size_t)b*CC*HWDIM;
    float* dst = out + (size_t)b*UQ_STRIDE;
    float rn = 1.f / fmaxf(sqrtf(g_rnacc[(b<<10) | (hw0 + tx)]), 1e-12f);
    #pragma unroll
    for (int i = 0; i < 4; i++) {
        int c  = c0 + ty + i*8;
        int hw = hw0 + tx;
        float v = src[(size_t)c*HWDIM + hw] * rn;
        dst[(size_t)c*HWDIM + hw] = v;
        tile[ty + i*8][tx] = v;
    }
    __syncthreads();
    #pragma unroll
    for (int i = 0; i < 4; i++) {
        int hw = hw0 + ty + i*8;
        int n  = (b<<10) | hw;
        float v = tile[tx][ty + i*8];
        __nv_bfloat16 hi = __float2bfloat16(v);
        float lo = v - __bfloat162float(hi);
        g_qhi[(size_t)n*CC + c0 + tx] = hi;
        g_qlo[(size_t)n*CC + c0 + tx] = __float2bfloat16(lo);
    }
}

// ---------------- HMMA score GEMM: v[n,m] = exp(qr . keys^T), bf16 3-term split ----------------
// block 128x128, warp grid 2x4 (warp tile 64x32), stage K=32, ring of 4 buffers
#define GBUF 10240      // 128 rows * 80B (32 bf16 + 16B pad)
#define DSMEM (8*GBUF)  // 4 A bufs + 4 B bufs = 81920

__global__ void __launch_bounds__(256, 2) k_score_mma() {
    extern __shared__ __align__(16) char dsm[];
    int tid = threadIdx.x, l = tid & 31, w = tid >> 5;
    int wr = w >> 2, wc = w & 3;
    int m0 = blockIdx.x * 128, n0 = blockIdx.y * 128;
    const __nv_bfloat16* Ap[3] = {g_qhi, g_qhi, g_qlo};
    const __nv_bfloat16* Bp[3] = {g_khi, g_klo, g_khi};
    uint32_t as0 = smem_u32(dsm);
    uint32_t bs0 = as0 + 4*GBUF;

    float acc[4][4][4];
    #pragma unroll
    for (int i = 0; i < 4; i++)
        #pragma unroll
        for (int j = 0; j < 4; j++)
            #pragma unroll
            for (int k = 0; k < 4; k++) acc[i][j][k] = 0.f;

    int row2 = tid >> 2, ch = tid & 3;
    auto stage = [&](int it, int buf) {
        int seg = it >> 4;
        int k0b = (it & 15) * 64;                       // 32 bf16 = 64B
        const char* Ab = (const char*)Ap[seg] + (size_t)n0*1024 + k0b;
        const char* Bb = (const char*)Bp[seg] + (size_t)m0*1024 + k0b;
        #pragma unroll
        for (int t = 0; t < 2; t++) {
            int r = row2 + t*64;
            cpa16(as0 + buf*GBUF + r*80 + ch*16, Ab + (size_t)r*1024 + ch*16);
            cpa16(bs0 + buf*GBUF + r*80 + ch*16, Bb + (size_t)r*1024 + ch*16);
        }
        CP_COMMIT;
    };

    uint32_t a_off = (uint32_t)((l & 15)*80 + (l >> 4)*16);
    uint32_t b_off = (uint32_t)(((((l >> 4) & 1)*8) + (l & 7))*80 + ((l >> 3) & 1)*16);

    stage(0, 0); stage(1, 1); stage(2, 2);
    const int NIT = 48;
    for (int it = 0; it < NIT; it++) {
        int buf = it & 3;
        int rem = NIT - 1 - it;
        if (rem >= 2) CP_WAIT2; else if (rem == 1) CP_WAIT1; else CP_WAIT0;
        __syncthreads();
        if (it + 3 < NIT) stage(it + 3, (it + 3) & 3);
        #pragma unroll
        for (int h = 0; h < 2; h++) {
            uint32_t a[4][4];
            #pragma unroll
            for (int fi = 0; fi < 4; fi++)
                ldm_x4(a[fi], as0 + buf*GBUF + (wr*64 + fi*16)*80 + h*32 + a_off);
            uint32_t bfr[2][4];
            #pragma unroll
            for (int jp = 0; jp < 2; jp++)
                ldm_x4(bfr[jp], bs0 + buf*GBUF + (wc*32 + jp*16)*80 + h*32 + b_off);
            #pragma unroll
            for (int fi = 0; fi < 4; fi++)
                #pragma unroll
                for (int fj = 0; fj < 4; fj++)
                    mma_bf16(acc[fi][fj], a[fi], &bfr[fj >> 1][(fj & 1)*2]);
        }
    }

    // epilogue: exp + fp16 hi/lo split of v
    int g = l >> 2, t2 = (l & 3)*2;
    #pragma unroll
    for (int fi = 0; fi < 4; fi++) {
        int r0 = n0 + wr*64 + fi*16 + g;
        #pragma unroll
        for (int fj = 0; fj < 4; fj++) {
            int c = m0 + wc*32 + fj*8 + t2;
            float* p = acc[fi][fj];
            #pragma unroll
            for (int hh = 0; hh < 2; hh++) {
                int r = r0 + hh*8;
                float e0 = __expf(p[hh*2 + 0]);
                float e1 = __expf(p[hh*2 + 1]);
                size_t o = (size_t)r*MM + c;
                __half h0 = __float2half_rn(e0);
                __half h1 = __float2half_rn(e1);
                __half2 hv; hv.x = h0; hv.y = h1;
                *(__half2*)(g_vhi + o) = hv;
                __half2 lv;
                lv.x = __float2half_rn(e0 - __half2float(h0));
                lv.y = __float2half_rn(e1 - __half2float(h1));
                *(__half2*)(g_vlo + o) = lv;
            }
        }
    }
}

// ---------------- HMMA read GEMM (fp16, 2-term, co-staged hi/lo) + fused sq/sm write ----------------
// A buffer row: [vhi 64B | vlo 64B] + 16B pad = 144B; B row: 64B + 16 pad = 80B
#define ABUF 18432      // 128 * 144
#define BBUF_R 10240    // 128 * 80
#define DSMEM_R (3*(ABUF + BBUF_R))   // 86016, ring-3

__global__ void __launch_bounds__(256, 2) k_read_mma(float* __restrict__ out) {
    extern __shared__ __align__(16) char dsm[];
    int tid = threadIdx.x, l = tid & 31, w = tid >> 5;
    int wr = w >> 2, wc = w & 3;
    int c0 = blockIdx.x * 128, n0 = blockIdx.y * 128;
    uint32_t as0 = smem_u32(dsm);
    uint32_t bs0 = as0 + 3*ABUF;

    float acc[4][4][4];
    #pragma unroll
    for (int i = 0; i < 4; i++)
        #pragma unroll
        for (int j = 0; j < 4; j++)
            #pragma unroll
            for (int k = 0; k < 4; k++) acc[i][j][k] = 0.f;

    auto stage = [&](int s, int buf) {
        // A: vhi (bytes 0-63) + vlo (64-127) co-staged, m-chunk s*32
        #pragma unroll
        for (int t = 0; t < 4; t++) {
            int idx = tid + t*256;
            int r = idx >> 3, c = idx & 7;
            const char* src = (c < 4)
                ? (const char*)g_vhi + (size_t)(n0 + r)*2048 + s*64 + c*16
                : (const char*)g_vlo + (size_t)(n0 + r)*2048 + s*64 + (c - 4)*16;
            cpa16(as0 + buf*ABUF + r*144 + c*16, src);
        }
        // B: fp16(keys^T) chunk, 64B per channel row
        #pragma unroll
        for (int t = 0; t < 2; t++) {
            int idx = tid + t*256;
            int r = idx >> 2, c = idx & 3;
            cpa16(bs0 + buf*BBUF_R + r*80 + c*16,
                  (const char*)g_kThi + (size_t)(c0 + r)*2048 + s*64 + c*16);
        }
        CP_COMMIT;
    };

    uint32_t a_off = (uint32_t)((l & 15)*144 + (l >> 4)*16);
    uint32_t b_off = (uint32_t)(((((l >> 4) & 1)*8) + (l & 7))*80 + ((l >> 3) & 1)*16);

    stage(0, 0); stage(1, 1);
    const int NIT = 32;               // 1024 m / 32 per stage
    for (int it = 0; it < NIT; it++) {
        int buf = it % 3;
        if (it < NIT - 1) CP_WAIT1; else CP_WAIT0;
        __syncthreads();
        if (it + 2 < NIT) stage(it + 2, (it + 2) % 3);
        #pragma unroll
        for (int h = 0; h < 2; h++) {
            uint32_t bfr[2][4];
            #pragma unroll
            for (int jp = 0; jp < 2; jp++)
                ldm_x4(bfr[jp], bs0 + buf*BBUF_R + (wc*32 + jp*16)*80 + h*32 + b_off);
            #pragma unroll
            for (int part = 0; part < 2; part++) {
                uint32_t a[4][4];
                #pragma unroll
                for (int fi = 0; fi < 4; fi++)
                    ldm_x4(a[fi], as0 + buf*ABUF + (wr*64 + fi*16)*144 + part*64 + h*32 + a_off);
                #pragma unroll
                for (int fi = 0; fi < 4; fi++)
                    #pragma unroll
                    for (int fj = 0; fj < 4; fj++)
                        mma_f16(acc[fi][fj], a[fi], &bfr[fj >> 1][(fj & 1)*2]);
            }
        }
        // fused sq/sm write: each c0-block writes its quarter of the 128 n-rows
        if (tid < 128) {
            int r = (blockIdx.x << 5) + (tid >> 2);
            int c = tid & 3;
            const __half2* hp = (const __half2*)(dsm + buf*ABUF + r*144 + c*16);
            const __half2* lp = (const __half2*)(dsm + buf*ABUF + r*144 + 64 + c*16);
            int n = n0 + r;
            int m = it*32 + c*8;
            float rr = g_rrowsum[n];
            float4 rc0 = *(const float4*)(g_rcolsum + m);
            float4 rc1 = *(const float4*)(g_rcolsum + m + 4);
            float vv[8];
            #pragma unroll
            for (int j = 0; j < 4; j++) {
                float2 hf = __half22float2(hp[j]);
                float2 lf = __half22float2(lp[j]);
                vv[j*2]   = hf.x + lf.x;
                vv[j*2+1] = hf.y + lf.y;
            }
            size_t o = (size_t)n*MM + m;
            float4 sq0 = make_float4(vv[0]*rc0.x, vv[1]*rc0.y, vv[2]*rc0.z, vv[3]*rc0.w);
            float4 sq1 = make_float4(vv[4]*rc1.x, vv[5]*rc1.y, vv[6]*rc1.z, vv[7]*rc1.w);
            *(float4*)(out + OFF_SQ + o)     = sq0;
            *(float4*)(out + OFF_SQ + o + 4) = sq1;
            float4 sm0 = make_float4(vv[0]*rr, vv[1]*rr, vv[2]*rr, vv[3]*rr);
            float4 sm1 = make_float4(vv[4]*rr, vv[5]*rr, vv[6]*rr, vv[7]*rr);
            *(float4*)(out + OFF_SM + o)     = sm0;
            *(float4*)(out + OFF_SM + o + 4) = sm1;
        }
    }

    // epilogue: scale by rrowsum, write BCHW channels [C, 2C)
    int g = l >> 2, t2 = (l & 3)*2;
    int b = n0 >> 10;
    int hwb = n0 & 1023;
    float* obase = out + (size_t)b*UQ_STRIDE;
    #pragma unroll
    for (int fi = 0; fi < 4; fi++) {
        int rl0 = wr*64 + fi*16 + g;
        float rs0 = g_rrowsum[n0 + rl0];
        float rs1 = g_rrowsum[n0 + rl0 + 8];
        #pragma unroll
        for (int fj = 0; fj < 4; fj++) {
            int c = c0 + wc*32 + fj*8 + t2;
            float* p = acc[fi][fj];
            size_t a0 = (size_t)(CC + c)*HWDIM + hwb + rl0;
            obase[a0]              = p[0] * rs0;
            obase[a0 + HWDIM]      = p[1] * rs0;
            obase[a0 + 8]          = p[2] * rs1;
            obase[a0 + HWDIM + 8]  = p[3] * rs1;
        }
    }
}

// ---------------- HMMA gram GEMM (fp16, 2-term): diversity(updated_memory) ----------------
__global__ void __launch_bounds__(256, 2) k_gram_mma(float* __restrict__ out) {
    extern __shared__ __align__(16) char dsm[];
    __shared__ float red[256];
    int tid = threadIdx.x, l = tid & 31, w = tid >> 5;
    int wr = w >> 2, wc = w & 3;
    int j0 = blockIdx.x * 128, i0 = blockIdx.y * 128;
    const __half* Ap[2] = {g_uhi, g_ulo};
    uint32_t as0 = smem_u32(dsm);
    uint32_t bs0 = as0 + 4*GBUF;

    float acc[4][4][4];
    #pragma unroll
    for (int i = 0; i < 4; i++)
        #pragma unroll
        for (int j = 0; j < 4; j++)
            #pragma unroll
            for (int k = 0; k < 4; k++) acc[i][j][k] = 0.f;

    int row2 = tid >> 2, ch = tid & 3;
    auto stage = [&](int it, int buf) {
        int seg = it >> 4;
        int k0b = (it & 15) * 64;
        const char* Ab = (const char*)Ap[seg] + (size_t)i0*1024 + k0b;
        const char* Bb = (const char*)g_uhi + (size_t)j0*1024 + k0b;
        #pragma unroll
        for (int t = 0; t < 2; t++) {
            int r = row2 + t*64;
            cpa16(as0 + buf*GBUF + r*80 + ch*16, Ab + (size_t)r*1024 + ch*16);
            cpa16(bs0 + buf*GBUF + r*80 + ch*16, Bb + (size_t)r*1024 + ch*16);
        }
        CP_COMMIT;
    };

    uint32_t a_off = (uint32_t)((l & 15)*80 + (l >> 4)*16);
    uint32_t b_off = (uint32_t)(((((l >> 4) & 1)*8) + (l & 7))*80 + ((l >> 3) & 1)*16);

    stage(0, 0); stage(1, 1); stage(2, 2);
    const int NIT = 32;
    for (int it = 0; it < NIT; it++) {
        int buf = it & 3;
        int rem = NIT - 1 - it;
        if (rem >= 2) CP_WAIT2; else if (rem == 1) CP_WAIT1; else CP_WAIT0;
        __syncthreads();
        if (it + 3 < NIT) stage(it + 3, (it + 3) & 3);
        #pragma unroll
        for (int h = 0; h < 2; h++) {
            uint32_t a[4][4];
            #pragma unroll
            for (int fi = 0; fi < 4; fi++)
                ldm_x4(a[fi], as0 + buf*GBUF + (wr*64 + fi*16)*80 + h*32 + a_off);
            uint32_t bfr[2][4];
            #pragma unroll
            for (int jp = 0; jp < 2; jp++)
                ldm_x4(bfr[jp], bs0 + buf*GBUF + (wc*32 + jp*16)*80 + h*32 + b_off);
            #pragma unroll
            for (int fi = 0; fi < 4; fi++)
                #pragma unroll
                for (int fj = 0; fj < 4; fj++)
                    mma_f16(acc[fi][fj], a[fi], &bfr[fj >> 1][(fj & 1)*2]);
        }
    }

    // epilogue: sum of squared off-diagonal gram entries
    int g = l >> 2, t2 = (l & 3)*2;
    float local = 0.f;
    #pragma unroll
    for (int fi = 0; fi < 4; fi++) {
        int r0 = i0 + wr*64 + fi*16 + g;
        #pragma unroll
        for (int fj = 0; fj < 4; fj++) {
            int c = j0 + wc*32 + fj*8 + t2;
            float* p = acc[fi][fj];
            if (r0 != c)         local += p[0]*p[0];
            if (r0 != c + 1)     local += p[1]*p[1];
            if (r0 + 8 != c)     local += p[2]*p[2];
            if (r0 + 8 != c + 1) local += p[3]*p[3];
        }
    }
    red[tid] = local;
    __syncthreads();
    for (int o = 128; o > 0; o >>= 1) {
        if (tid < o) red[tid] += red[tid + o];
        __syncthreads();
    }
    if (tid == 0) atomicAdd(out + OFF_DIV, red[0] * (1.f / (float)(MM*MM - MM)));
}

// ---------------- fused reductions over v: row max/argmax/sum + column partials ----------------
__global__ void __launch_bounds__(256) k_vreduce() {
    __shared__ float s_sum[1024];
    __shared__ float s_max[1024];
    int tid = threadIdx.x, l = tid & 31, w = tid >> 5;
    int rbase = blockIdx.x * 128;

    float colsum[8][4], colmax[8][4];
    #pragma unroll
    for (int i = 0; i < 8; i++)
        #pragma unroll
        for (int k = 0; k < 4; k++) { colsum[i][k] = 0.f; colmax[i][k] = 0.f; }

    for (int j = 0; j < 16; j++) {
        int r = rbase + w + j*8;
        const uint2* hp = (const uint2*)(g_vhi + (size_t)r*MM);
        const uint2* lp = (const uint2*)(g_vlo + (size_t)r*MM);
        float rmax = 0.f, rsum = 0.f; int rarg = 0;
        #pragma unroll
        for (int i = 0; i < 8; i++) {
            uint2 hu = hp[i*32 + l];
            uint2 lu = lp[i*32 + l];
            float2 ha = __half22float2(*(__half2*)&hu.x);
            float2 hb = __half22float2(*(__half2*)&hu.y);
            float2 la = __half22float2(*(__half2*)&lu.x);
            float2 lb = __half22float2(*(__half2*)&lu.y);
            float v0 = ha.x + la.x, v1 = ha.y + la.y;
            float v2 = hb.x + lb.x, v3 = hb.y + lb.y;
            int c0 = i*128 + l*4;
            rsum += (v0 + v1) + (v2 + v3);
            if (v0 > rmax) { rmax = v0; rarg = c0; }
            if (v1 > rmax) { rmax = v1; rarg = c0+1; }
            if (v2 > rmax) { rmax = v2; rarg = c0+2; }
            if (v3 > rmax) { rmax = v3; rarg = c0+3; }
            colsum[i][0] += v0; colmax[i][0] = fmaxf(colmax[i][0], v0);
            colsum[i][1] += v1; colmax[i][1] = fmaxf(colmax[i][1], v1);
            colsum[i][2] += v2; colmax[i][2] = fmaxf(colmax[i][2], v2);
            colsum[i][3] += v3; colmax[i][3] = fmaxf(colmax[i][3], v3);
        }
        #pragma unroll
        for (int o = 16; o > 0; o >>= 1) {
            float om = __shfl_down_sync(0xffffffffu, rmax, o);
            int   oi = __shfl_down_sync(0xffffffffu, rarg, o);
            float os = __shfl_down_sync(0xffffffffu, rsum, o);
            rsum += os;
            if (om > rmax || (om == rmax && oi < rarg)) { rmax = om; rarg = oi; }
        }
        if (l == 0) {
            g_rowmaxv[r] = rmax;
            g_argm[r]    = rarg;
            g_rrowsum[r] = 1.f / rsum;
        }
    }

    for (int jj = tid; jj < 1024; jj += 256) { s_sum[jj] = 0.f; s_max[jj] = 0.f; }
    __syncthreads();
    for (int ws = 0; ws < 8; ws++) {
        if (w == ws) {
            #pragma unroll
            for (int i = 0; i < 8; i++)
                #pragma unroll
                for (int k = 0; k < 4; k++) {
                    int idx = i*128 + l*4 + k;
                    s_sum[idx] += colsum[i][k];
                    s_max[idx]  = fmaxf(s_max[idx], colmax[i][k]);
                }
        }
        __syncthreads();
    }
    for (int jj = tid; jj < 1024; jj += 256) {
        g_psum[blockIdx.x*MM + jj] = s_sum[jj];
        g_pmax[blockIdx.x*MM + jj] = s_max[jj];
    }
}

__global__ void k_colmerge() {
    int m = blockIdx.x * 256 + threadIdx.x;
    float mx = 0.f, s = 0.f;
    #pragma unroll 4
    for (int p = 0; p < NSPLIT; p++) {
        mx = fmaxf(mx, g_pmax[p*MM + m]);
        s += g_psum[p*MM + m];
    }
    g_colmaxv[m] = mx;
    g_rcolsum[m] = 1.f / s;
}

// ---------------- w[n] and similarity loss ----------------
__global__ void k_wsim(const float* __restrict__ ent, float* __restrict__ out) {
    int n = blockIdx.x * blockDim.x + threadIdx.x;
    float local = 0.f;
    if (n < NN) {
        int g = g_argm[n];
        float en = ent[n];
        float entmax = __uint_as_float(g_entmax_bits);
        g_w[n] = (g_rowmaxv[n] / g_colmaxv[g]) * (en / entmax);
        float smax = logf(g_rowmaxv[n]);                  // = max score of row n
        float cosv = smax / fmaxf(g_keynorm[g], 1e-8f);   // ||qr|| == 1
        local = (1.f - cosv) * en;
    }
    __shared__ float red[256];
    red[threadIdx.x] = local;
    __syncthreads();
    for (int o = 128; o > 0; o >>= 1) {
        if (threadIdx.x < o) red[threadIdx.x] += red[threadIdx.x + o];
        __syncthreads();
    }
    if (threadIdx.x == 0) atomicAdd(out + OFF_SIM, red[0]);
}

// ---------------- segment-sum: qupd[g[n], c] += w[n]*qr[n,c] ----------------
__global__ void k_segsum(const float* __restrict__ out) {
    int idx = blockIdx.x * blockDim.x + threadIdx.x;
    if (idx >= BB*CC*HWDIM) return;
    int b = idx >> 19;
    int rem = idx & ((CC*HWDIM) - 1);
    int c = rem >> 10;
    int hw = idx & 1023;
    int n = (b << 10) | hw;
    float val = out[(size_t)b*UQ_STRIDE + rem];           // qr in BCHW layout
    atomicAdd(&g_qupd[(size_t)g_argm[n]*CC + c], g_w[n] * val);
}

// ---------------- updated memory: l2norm(qupd + keys), emit fp32 + fp16 split ----------------
__global__ void k_umem(const float* __restrict__ keys, float* __restrict__ out) {
    int m = blockIdx.x;
    int t = threadIdx.x;   // 128
    float vals[4]; float s = 0.f;
    #pragma unroll
    for (int i = 0; i < 4; i++) {
        int c = t + i*128;
        vals[i] = g_qupd[(size_t)m*CC + c] + keys[(size_t)m*CC + c];
        s += vals[i]*vals[i];
    }
    for (int o = 16; o > 0; o >>= 1) s += __shfl_down_sync(0xffffffffu, s, o);
    __shared__ float red[4]; __shared__ float srn;
    if ((t & 31) == 0) red[t >> 5] = s;
    __syncthreads();
    if (t == 0) srn = 1.f / fmaxf(sqrtf(red[0]+red[1]+red[2]+red[3]), 1e-12f);
    __syncthreads();
    float rn = srn;
    #pragma unroll
    for (int i = 0; i < 4; i++) {
        int c = t + i*128;
        float u = vals[i] * rn;
        out[OFF_UMEM + (size_t)m*CC + c] = u;
        __half hi = __float2half_rn(u);
        g_uhi[(size_t)m*CC + c] = hi;
        g_ulo[(size_t)m*CC + c] = __float2half_rn(u - __half2float(hi));
    }
}

// ---------------- launch ----------------
extern "C" void kernel_launch(void* const* d_in, const int* in_sizes, int n_in,
                              void* d_out, int out_size) {
    const float* q    = (const float*)d_in[0];
    const float* keys = (const float*)d_in[1];
    const float* ent  = (const float*)d_in[2];
    float* out = (float*)d_out;

    cudaFuncSetAttribute(k_score_mma, cudaFuncAttributeMaxDynamicSharedMemorySize, DSMEM);
    cudaFuncSetAttribute(k_read_mma,  cudaFuncAttributeMaxDynamicSharedMemorySize, DSMEM_R);
    cudaFuncSetAttribute(k_gram_mma,  cudaFuncAttributeMaxDynamicSharedMemorySize, DSMEM);

    k_init<<<(MM*CC + 255)/256, 256>>>(ent, out);
    k_keynorm<<<MM, 128>>>(keys);
    k_keys<<<dim3(MM/32, CC/32), dim3(32, 8)>>>(keys);
    k_rnorm_part<<<dim3(64, 8), 256>>>(q);
    k_qsplit<<<dim3(HWDIM/32, CC/32, BB), dim3(32, 8)>>>(q, out);
    k_score_mma<<<dim3(MM/128, NN/128), 256, DSMEM>>>();
    k_vreduce<<<NN/128, 256>>>();
    k_colmerge<<<MM/256, 256>>>();
    k_wsim<<<NN/256, 256>>>(ent, out);
    k_segsum<<<(BB*CC*HWDIM)/256, 256>>>(out);
    k_umem<<<MM, 128>>>(keys, out);
    k_gram_mma<<<dim3(MM/128, MM/128), 256, DSMEM>>>(out);
    k_read_mma<<<dim3(CC/128, NN/128), 256, DSMEM_R>>>(out);
}

// round 10
// speedup vs baseline: 2.7981x; 1.1722x over previous
#include <cuda_runtime.h>
#include <cuda_bf16.h>
#include <cuda_fp16.h>
#include <math.h>
#include <stdint.h>

#define BB 16
#define CC 512
#define HWDIM 1024
#define NN 16384            // B*H*W
#define MM 1024
#define UQ_STRIDE (2*CC*HWDIM)          // per-batch stride of updated_query = 1048576

// output offsets (floats)
#define OFF_UQ   ((size_t)0)
#define OFF_UMEM ((size_t)BB*UQ_STRIDE)                  // 16777216
#define OFF_SQ   (OFF_UMEM + (size_t)MM*CC)              // 17301504
#define OFF_SM   (OFF_SQ + (size_t)NN*MM)                // 34078720
#define OFF_DIV  (OFF_SM + (size_t)NN*MM)                // 50855936
#define OFF_SIM  (OFF_DIV + 1)

// ---------------- scratch (static device globals; no runtime alloc) ----------------
__device__ float g_rnacc[NN];
__device__ float g_rowmaxv[NN];
__device__ float g_rrowsum[NN];
__device__ int   g_argm[NN];
__device__ float g_w[NN];
__device__ float g_colmaxv[MM];
__device__ float g_rcolsum[MM];
__device__ float g_keynorm[MM];
__device__ float g_qupd[MM*CC];
__device__ unsigned g_entmax_bits;
// atomic merge targets for fused score reductions
__device__ unsigned long long g_rowkey[NN];   // (float_bits(max) << 32) | ~argmax
__device__ float g_rowsumacc[NN];
__device__ unsigned g_colmaxb[MM];
__device__ float g_colsumacc[MM];
// bf16 split operands (score GEMM, 3-term)
__device__ __nv_bfloat16 g_qhi[(size_t)NN*CC];   // qr [N][C] K-major
__device__ __nv_bfloat16 g_qlo[(size_t)NN*CC];
__device__ __nv_bfloat16 g_khi[(size_t)MM*CC];   // keys [M][C]
__device__ __nv_bfloat16 g_klo[(size_t)MM*CC];
// fp16 operands (read/gram GEMMs, 2-term)
__device__ __half g_kThi[(size_t)CC*MM];         // fp16(keys^T) [C][M]
__device__ __half g_vhi[(size_t)NN*MM];          // v split [N][M]
__device__ __half g_vlo[(size_t)NN*MM];
__device__ __half g_uhi[(size_t)MM*CC];          // updated_memory split
__device__ __half g_ulo[(size_t)MM*CC];

// ---------------- PTX helpers (base sm_103-legal only) ----------------
__device__ __forceinline__ uint32_t smem_u32(const void* p) {
    uint32_t a;
    asm("{ .reg .u64 t; cvta.to.shared.u64 t, %1; cvt.u32.u64 %0, t; }" : "=r"(a) : "l"(p));
    return a;
}
__device__ __forceinline__ void ldm_x4(uint32_t* r, uint32_t a) {
    asm volatile("ldmatrix.sync.aligned.m8n8.x4.shared.b16 {%0,%1,%2,%3}, [%4];"
        : "=r"(r[0]), "=r"(r[1]), "=r"(r[2]), "=r"(r[3]) : "r"(a));
}
__device__ __forceinline__ void mma_bf16(float* c, const uint32_t* a, const uint32_t* b) {
    asm volatile("mma.sync.aligned.m16n8k16.row.col.f32.bf16.bf16.f32 "
        "{%0,%1,%2,%3}, {%4,%5,%6,%7}, {%8,%9}, {%0,%1,%2,%3};"
        : "+f"(c[0]), "+f"(c[1]), "+f"(c[2]), "+f"(c[3])
        : "r"(a[0]), "r"(a[1]), "r"(a[2]), "r"(a[3]), "r"(b[0]), "r"(b[1]));
}
__device__ __forceinline__ void mma_f16(float* c, const uint32_t* a, const uint32_t* b) {
    asm volatile("mma.sync.aligned.m16n8k16.row.col.f32.f16.f16.f32 "
        "{%0,%1,%2,%3}, {%4,%5,%6,%7}, {%8,%9}, {%0,%1,%2,%3};"
        : "+f"(c[0]), "+f"(c[1]), "+f"(c[2]), "+f"(c[3])
        : "r"(a[0]), "r"(a[1]), "r"(a[2]), "r"(a[3]), "r"(b[0]), "r"(b[1]));
}
__device__ __forceinline__ void cpa16(uint32_t dst, const void* src) {
    asm volatile("cp.async.ca.shared.global [%0], [%1], 16;" :: "r"(dst), "l"(src));
}
#define CP_COMMIT asm volatile("cp.async.commit_group;" ::: "memory")
#define CP_WAIT1  asm volatile("cp.async.wait_group 1;" ::: "memory")
#define CP_WAIT0  asm volatile("cp.async.wait_group 0;" ::: "memory")

// ---------------- small kernels ----------------

__global__ void k_init(const float* __restrict__ ent, float* __restrict__ out) {
    int i = blockIdx.x * blockDim.x + threadIdx.x;
    if (i < MM*CC) g_qupd[i] = 0.f;
    if (i < NN) {
        g_rnacc[i] = 0.f;
        g_rowkey[i] = 0ull;
        g_rowsumacc[i] = 0.f;
        atomicMax(&g_entmax_bits, __float_as_uint(ent[i])); // entropy > 0
    }
    if (i < MM) {
        g_colmaxb[i] = 0u;
        g_colsumacc[i] = 0.f;
    }
    if (i == 0) {
        out[OFF_DIV] = 0.f;
        out[OFF_SIM] = 0.f;
    }
}

__global__ void k_keynorm(const float* __restrict__ keys) {
    int m = blockIdx.x;
    int t = threadIdx.x;   // 128 threads
    float s = 0.f;
    #pragma unroll
    for (int i = 0; i < 4; i++) {
        float v = keys[(size_t)m*CC + t + i*128];
        s += v*v;
    }
    for (int o = 16; o > 0; o >>= 1) s += __shfl_down_sync(0xffffffffu, s, o);
    __shared__ float red[4];
    if ((t & 31) == 0) red[t >> 5] = s;
    __syncthreads();
    if (t == 0) g_keynorm[m] = sqrtf(red[0] + red[1] + red[2] + red[3]);
}

// keys -> bf16 hi/lo split [M][C] AND fp16(keys^T) [C][M]
__global__ void k_keys(const float* __restrict__ keys) {
    __shared__ float t[32][33];
    int m0 = blockIdx.x * 32, c0 = blockIdx.y * 32;
    int tx = threadIdx.x, ty = threadIdx.y;  // 32 x 8
    #pragma unroll
    for (int i = 0; i < 4; i++) {
        int row = ty + i*8;
        size_t o = (size_t)(m0 + row)*CC + c0 + tx;
        float v = keys[o];
        t[row][tx] = v;
        __nv_bfloat16 hi = __float2bfloat16(v);
        g_khi[o] = hi;
        g_klo[o] = __float2bfloat16(v - __bfloat162float(hi));
    }
    __syncthreads();
    #pragma unroll
    for (int i = 0; i < 4; i++) {
        float v = t[tx][ty + i*8];        // = keys[m0+tx][c0+ty+i*8]
        g_kThi[(size_t)(c0 + ty + i*8)*MM + m0 + tx] = __float2half_rn(v);
    }
}

// partial sum-of-squares over 64-channel chunks (grid 64 x 8)
__global__ void k_rnorm_part(const float* __restrict__ q) {
    int n = blockIdx.x * 256 + threadIdx.x;
    int b = n >> 10, hw = n & 1023;
    const float* base = q + (size_t)b*CC*HWDIM + (size_t)(blockIdx.y*64)*HWDIM + hw;
    float s = 0.f;
    #pragma unroll 8
    for (int c = 0; c < 64; c++) {
        float v = base[(size_t)c*HWDIM];
        s += v*v;
    }
    atomicAdd(&g_rnacc[n], s);
}

// normalize q, write fp32 qr into out (BCHW) AND transposed bf16 hi/lo [N][C]
__global__ void k_qsplit(const float* __restrict__ q, float* __restrict__ out) {
    __shared__ float tile[32][33];
    int b  = blockIdx.z;
    int c0 = blockIdx.y * 32, hw0 = blockIdx.x * 32;
    int tx = threadIdx.x, ty = threadIdx.y;   // 32 x 8
    const float* src = q + (size_t)b*CC*HWDIM;
    float* dst = out + (size_t)b*UQ_STRIDE;
    float rn = 1.f / fmaxf(sqrtf(g_rnacc[(b<<10) | (hw0 + tx)]), 1e-12f);
    #pragma unroll
    for (int i = 0; i < 4; i++) {
        int c  = c0 + ty + i*8;
        int hw = hw0 + tx;
        float v = src[(size_t)c*HWDIM + hw] * rn;
        dst[(size_t)c*HWDIM + hw] = v;
        tile[ty + i*8][tx] = v;
    }
    __syncthreads();
    #pragma unroll
    for (int i = 0; i < 4; i++) {
        int hw = hw0 + ty + i*8;
        int n  = (b<<10) | hw;
        float v = tile[tx][ty + i*8];
        __nv_bfloat16 hi = __float2bfloat16(v);
        float lo = v - __bfloat162float(hi);
        g_qhi[(size_t)n*CC + c0 + tx] = hi;
        g_qlo[(size_t)n*CC + c0 + tx] = __float2bfloat16(lo);
    }
}

// ---------------- HMMA score GEMM: co-staged bf16 hi/lo, 3 terms per staged chunk ----------------
// A/B buffer row: [hi 64B | lo 64B | pad 16B] = 144B; ring-2, prefetch AFTER consume (race-free)
#define SBUF 18432      // 128 * 144
#define DSMEM_S (4*SBUF)  // 2 A + 2 B = 73728

__global__ void __launch_bounds__(256, 2) k_score_mma() {
    extern __shared__ __align__(16) char dsm[];
    int tid = threadIdx.x, l = tid & 31, w = tid >> 5;
    int wr = w >> 2, wc = w & 3;
    int m0 = blockIdx.x * 128, n0 = blockIdx.y * 128;
    uint32_t as0 = smem_u32(dsm);
    uint32_t bs0 = as0 + 2*SBUF;

    float acc[4][4][4];
    #pragma unroll
    for (int i = 0; i < 4; i++)
        #pragma unroll
        for (int j = 0; j < 4; j++)
            #pragma unroll
            for (int k = 0; k < 4; k++) acc[i][j][k] = 0.f;

    auto stage = [&](int s, int buf) {
        #pragma unroll
        for (int t = 0; t < 4; t++) {
            int idx = tid + t*256;
            int r = idx >> 3, c = idx & 7;
            const char* srcA = (c < 4)
                ? (const char*)g_qhi + (size_t)(n0 + r)*1024 + s*64 + c*16
                : (const char*)g_qlo + (size_t)(n0 + r)*1024 + s*64 + (c-4)*16;
            cpa16(as0 + buf*SBUF + r*144 + c*16, srcA);
            const char* srcB = (c < 4)
                ? (const char*)g_khi + (size_t)(m0 + r)*1024 + s*64 + c*16
                : (const char*)g_klo + (size_t)(m0 + r)*1024 + s*64 + (c-4)*16;
            cpa16(bs0 + buf*SBUF + r*144 + c*16, srcB);
        }
        CP_COMMIT;
    };

    uint32_t a_off = (uint32_t)((l & 15)*144 + (l >> 4)*16);
    uint32_t b_off = (uint32_t)(((((l >> 4) & 1)*8) + (l & 7))*144 + ((l >> 3) & 1)*16);

    stage(0, 0); stage(1, 1);
    const int NIT = 16;
    for (int it = 0; it < NIT; it++) {
        int buf = it & 1;
        if (it < NIT - 1) CP_WAIT1; else CP_WAIT0;
        __syncthreads();
        #pragma unroll
        for (int h = 0; h < 2; h++) {
            uint32_t afr[4][4], b0f[2][4], b1f[2][4];
            // A-hi, B-hi
            #pragma unroll
            for (int fi = 0; fi < 4; fi++)
                ldm_x4(afr[fi], as0 + buf*SBUF + (wr*64 + fi*16)*144 + h*32 + a_off);
            #pragma unroll
            for (int jp = 0; jp < 2; jp++)
                ldm_x4(b0f[jp], bs0 + buf*SBUF + (wc*32 + jp*16)*144 + h*32 + b_off);
            #pragma unroll
            for (int fi = 0; fi < 4; fi++)
                #pragma unroll
                for (int fj = 0; fj < 4; fj++)
                    mma_bf16(acc[fi][fj], afr[fi], &b0f[fj >> 1][(fj & 1)*2]);   // hi*hi
            // B-lo (A-hi still live)
            #pragma unroll
            for (int jp = 0; jp < 2; jp++)
                ldm_x4(b1f[jp], bs0 + buf*SBUF + (wc*32 + jp*16)*144 + 64 + h*32 + b_off);
            #pragma unroll
            for (int fi = 0; fi < 4; fi++)
                #pragma unroll
                for (int fj = 0; fj < 4; fj++)
                    mma_bf16(acc[fi][fj], afr[fi], &b1f[fj >> 1][(fj & 1)*2]);   // hi*lo
            // A-lo (reuse B-hi)
            #pragma unroll
            for (int fi = 0; fi < 4; fi++)
                ldm_x4(afr[fi], as0 + buf*SBUF + (wr*64 + fi*16)*144 + 64 + h*32 + a_off);
            #pragma unroll
            for (int fi = 0; fi < 4; fi++)
                #pragma unroll
                for (int fj = 0; fj < 4; fj++)
                    mma_bf16(acc[fi][fj], afr[fi], &b0f[fj >> 1][(fj & 1)*2]);   // lo*hi
        }
        __syncthreads();   // all reads of buf done before refill
        if (it + 2 < NIT) stage(it + 2, buf);
    }

    // ---- epilogue: exp, fp16 split of v, fused row/col reductions ----
    int g = l >> 2, t2 = (l & 3)*2;
    float rsum[8], rmaxv[8]; int rargm[8];
    float csum[8], cmaxv[8];
    #pragma unroll
    for (int i = 0; i < 8; i++) { rsum[i]=0.f; rmaxv[i]=0.f; rargm[i]=0; csum[i]=0.f; cmaxv[i]=0.f; }

    #pragma unroll
    for (int fi = 0; fi < 4; fi++) {
        int r0 = n0 + wr*64 + fi*16 + g;
        #pragma unroll
        for (int fj = 0; fj < 4; fj++) {
            int c = m0 + wc*32 + fj*8 + t2;
            float* p = acc[fi][fj];
            #pragma unroll
            for (int hh = 0; hh < 2; hh++) {
                int r = r0 + hh*8;
                int ridx = fi*2 + hh;
                float e0 = __expf(p[hh*2 + 0]);
                float e1 = __expf(p[hh*2 + 1]);
                size_t o = (size_t)r*MM + c;
                __half h0 = __float2half_rn(e0);
                __half h1 = __float2half_rn(e1);
                __half2 hv; hv.x = h0; hv.y = h1;
                *(__half2*)(g_vhi + o) = hv;
                __half2 lv;
                lv.x = __float2half_rn(e0 - __half2float(h0));
                lv.y = __float2half_rn(e1 - __half2float(h1));
                *(__half2*)(g_vlo + o) = lv;
                rsum[ridx] += e0 + e1;
                if (e0 > rmaxv[ridx]) { rmaxv[ridx] = e0; rargm[ridx] = c; }
                if (e1 > rmaxv[ridx]) { rmaxv[ridx] = e1; rargm[ridx] = c + 1; }
                int cidx = fj*2;
                csum[cidx]   += e0; cmaxv[cidx]   = fmaxf(cmaxv[cidx],   e0);
                csum[cidx+1] += e1; cmaxv[cidx+1] = fmaxf(cmaxv[cidx+1], e1);
            }
        }
    }
    // row reduce across lanes sharing the row (xor 1,2 within lane quad)
    #pragma unroll
    for (int o = 1; o <= 2; o <<= 1) {
        #pragma unroll
        for (int i = 0; i < 8; i++) {
            float os = __shfl_xor_sync(0xffffffffu, rsum[i], o);
            float om = __shfl_xor_sync(0xffffffffu, rmaxv[i], o);
            int   oa = __shfl_xor_sync(0xffffffffu, rargm[i], o);
            rsum[i] += os;
            if (om > rmaxv[i] || (om == rmaxv[i] && oa < rargm[i])) { rmaxv[i] = om; rargm[i] = oa; }
        }
    }
    // col reduce across lanes sharing the col (xor 4,8,16)
    #pragma unroll
    for (int o = 4; o <= 16; o <<= 1) {
        #pragma unroll
        for (int i = 0; i < 8; i++) {
            csum[i]  += __shfl_xor_sync(0xffffffffu, csum[i], o);
            cmaxv[i]  = fmaxf(cmaxv[i], __shfl_xor_sync(0xffffffffu, cmaxv[i], o));
        }
    }
    // smem merge (reuse pipeline smem)
    float* s_rs = (float*)dsm;
    float* s_rm = s_rs + 128;
    int*   s_ra = (int*)(s_rm + 128);
    float* s_cs = (float*)(s_ra + 128);
    float* s_cm = s_cs + 128;
    __syncthreads();
    for (int ws = 0; ws < 4; ws++) {          // stage over wc; wr rows disjoint
        if (wc == ws && (l & 3) == 0) {
            #pragma unroll
            for (int i = 0; i < 8; i++) {
                int r = wr*64 + (i >> 1)*16 + (i & 1)*8 + g;
                if (ws == 0) { s_rs[r] = rsum[i]; s_rm[r] = rmaxv[i]; s_ra[r] = rargm[i]; }
                else {
                    s_rs[r] += rsum[i];
                    if (rmaxv[i] > s_rm[r] || (rmaxv[i] == s_rm[r] && rargm[i] < s_ra[r])) {
                        s_rm[r] = rmaxv[i]; s_ra[r] = rargm[i];
                    }
                }
            }
        }
        __syncthreads();
    }
    for (int ws = 0; ws < 2; ws++) {          // stage over wr; wc cols disjoint
        if (wr == ws && l < 4) {
            #pragma unroll
            for (int i = 0; i < 8; i++) {
                int cl = wc*32 + (i >> 1)*8 + t2 + (i & 1);
                if (ws == 0) { s_cs[cl] = csum[i]; s_cm[cl] = cmaxv[i]; }
                else { s_cs[cl] += csum[i]; s_cm[cl] = fmaxf(s_cm[cl], cmaxv[i]); }
            }
        }
        __syncthreads();
    }
    if (tid < 128) {
        int n = n0 + tid;
        atomicAdd(&g_rowsumacc[n], s_rs[tid]);
        unsigned long long key =
            ((unsigned long long)__float_as_uint(s_rm[tid]) << 32) | (unsigned)(~(unsigned)s_ra[tid]);
        atomicMax(&g_rowkey[n], key);
        int m = m0 + tid;
        atomicAdd(&g_colsumacc[m], s_cs[tid]);
        atomicMax(&g_colmaxb[m], __float_as_uint(s_cm[tid]));
    }
}

// ---------------- finalize reductions: unpack argmax, reciprocals ----------------
__global__ void k_fin() {
    int n = blockIdx.x * blockDim.x + threadIdx.x;
    if (n < NN) {
        unsigned long long key = g_rowkey[n];
        g_rowmaxv[n] = __uint_as_float((unsigned)(key >> 32));
        g_argm[n]    = (int)(~(unsigned)key);
        g_rrowsum[n] = 1.f / g_rowsumacc[n];
    }
    if (n < MM) {
        g_colmaxv[n] = __uint_as_float(g_colmaxb[n]);
        g_rcolsum[n] = 1.f / g_colsumacc[n];
    }
}

// ---------------- HMMA read GEMM (fp16, 2-term, co-staged hi/lo) + fused sq/sm write ----------------
#define ABUF 18432      // 128 * 144
#define BBUF_R 10240    // 128 * 80
#define DSMEM_R (3*(ABUF + BBUF_R))   // 86016, ring-3

__global__ void __launch_bounds__(256, 2) k_read_mma(float* __restrict__ out) {
    extern __shared__ __align__(16) char dsm[];
    int tid = threadIdx.x, l = tid & 31, w = tid >> 5;
    int wr = w >> 2, wc = w & 3;
    int c0 = blockIdx.x * 128, n0 = blockIdx.y * 128;
    uint32_t as0 = smem_u32(dsm);
    uint32_t bs0 = as0 + 3*ABUF;

    float acc[4][4][4];
    #pragma unroll
    for (int i = 0; i < 4; i++)
        #pragma unroll
        for (int j = 0; j < 4; j++)
            #pragma unroll
            for (int k = 0; k < 4; k++) acc[i][j][k] = 0.f;

    auto stage = [&](int s, int buf) {
        #pragma unroll
        for (int t = 0; t < 4; t++) {
            int idx = tid + t*256;
            int r = idx >> 3, c = idx & 7;
            const char* src = (c < 4)
                ? (const char*)g_vhi + (size_t)(n0 + r)*2048 + s*64 + c*16
                : (const char*)g_vlo + (size_t)(n0 + r)*2048 + s*64 + (c - 4)*16;
            cpa16(as0 + buf*ABUF + r*144 + c*16, src);
        }
        #pragma unroll
        for (int t = 0; t < 2; t++) {
            int idx = tid + t*256;
            int r = idx >> 2, c = idx & 3;
            cpa16(bs0 + buf*BBUF_R + r*80 + c*16,
                  (const char*)g_kThi + (size_t)(c0 + r)*2048 + s*64 + c*16);
        }
        CP_COMMIT;
    };

    uint32_t a_off = (uint32_t)((l & 15)*144 + (l >> 4)*16);
    uint32_t b_off = (uint32_t)(((((l >> 4) & 1)*8) + (l & 7))*80 + ((l >> 3) & 1)*16);

    stage(0, 0); stage(1, 1);
    const int NIT = 32;               // 1024 m / 32 per stage
    for (int it = 0; it < NIT; it++) {
        int buf = it % 3;
        if (it < NIT - 1) CP_WAIT1; else CP_WAIT0;
        __syncthreads();
        if (it + 2 < NIT) stage(it + 2, (it + 2) % 3);
        #pragma unroll
        for (int h = 0; h < 2; h++) {
            uint32_t bfr[2][4];
            #pragma unroll
            for (int jp = 0; jp < 2; jp++)
                ldm_x4(bfr[jp], bs0 + buf*BBUF_R + (wc*32 + jp*16)*80 + h*32 + b_off);
            #pragma unroll
            for (int part = 0; part < 2; part++) {
                uint32_t a[4][4];
                #pragma unroll
                for (int fi = 0; fi < 4; fi++)
                    ldm_x4(a[fi], as0 + buf*ABUF + (wr*64 + fi*16)*144 + part*64 + h*32 + a_off);
                #pragma unroll
                for (int fi = 0; fi < 4; fi++)
                    #pragma unroll
                    for (int fj = 0; fj < 4; fj++)
                        mma_f16(acc[fi][fj], a[fi], &bfr[fj >> 1][(fj & 1)*2]);
            }
        }
        // fused sq/sm write: each c0-block writes its quarter of the 128 n-rows
        if (tid < 128) {
            int r = (blockIdx.x << 5) + (tid >> 2);
            int c = tid & 3;
            const __half2* hp = (const __half2*)(dsm + buf*ABUF + r*144 + c*16);
            const __half2* lp = (const __half2*)(dsm + buf*ABUF + r*144 + 64 + c*16);
            int n = n0 + r;
            int m = it*32 + c*8;
            float rr = g_rrowsum[n];
            float4 rc0 = *(const float4*)(g_rcolsum + m);
            float4 rc1 = *(const float4*)(g_rcolsum + m + 4);
            float vv[8];
            #pragma unroll
            for (int j = 0; j < 4; j++) {
                float2 hf = __half22float2(hp[j]);
                float2 lf = __half22float2(lp[j]);
                vv[j*2]   = hf.x + lf.x;
                vv[j*2+1] = hf.y + lf.y;
            }
            size_t o = (size_t)n*MM + m;
            float4 sq0 = make_float4(vv[0]*rc0.x, vv[1]*rc0.y, vv[2]*rc0.z, vv[3]*rc0.w);
            float4 sq1 = make_float4(vv[4]*rc1.x, vv[5]*rc1.y, vv[6]*rc1.z, vv[7]*rc1.w);
            *(float4*)(out + OFF_SQ + o)     = sq0;
            *(float4*)(out + OFF_SQ + o + 4) = sq1;
            float4 sm0 = make_float4(vv[0]*rr, vv[1]*rr, vv[2]*rr, vv[3]*rr);
            float4 sm1 = make_float4(vv[4]*rr, vv[5]*rr, vv[6]*rr, vv[7]*rr);
            *(float4*)(out + OFF_SM + o)     = sm0;
            *(float4*)(out + OFF_SM + o + 4) = sm1;
        }
    }

    // epilogue: scale by rrowsum, write BCHW channels [C, 2C)
    int g = l >> 2, t2 = (l & 3)*2;
    int b = n0 >> 10;
    int hwb = n0 & 1023;
    float* obase = out + (size_t)b*UQ_STRIDE;
    #pragma unroll
    for (int fi = 0; fi < 4; fi++) {
        int rl0 = wr*64 + fi*16 + g;
        float rs0 = g_rrowsum[n0 + rl0];
        float rs1 = g_rrowsum[n0 + rl0 + 8];
        #pragma unroll
        for (int fj = 0; fj < 4; fj++) {
            int c = c0 + wc*32 + fj*8 + t2;
            float* p = acc[fi][fj];
            size_t a0 = (size_t)(CC + c)*HWDIM + hwb + rl0;
            obase[a0]              = p[0] * rs0;
            obase[a0 + HWDIM]      = p[1] * rs0;
            obase[a0 + 8]          = p[2] * rs1;
            obase[a0 + HWDIM + 8]  = p[3] * rs1;
        }
    }
}

// ---------------- HMMA gram GEMM (fp16, 2-term): diversity(updated_memory) ----------------
#define GBUF 10240      // 128 rows * 80B
#define DSMEM_G (8*GBUF)

__global__ void __launch_bounds__(256, 2) k_gram_mma(float* __restrict__ out) {
    extern __shared__ __align__(16) char dsm[];
    __shared__ float red[256];
    int tid = threadIdx.x, l = tid & 31, w = tid >> 5;
    int wr = w >> 2, wc = w & 3;
    int j0 = blockIdx.x * 128, i0 = blockIdx.y * 128;
    const __half* Ap[2] = {g_uhi, g_ulo};
    uint32_t as0 = smem_u32(dsm);
    uint32_t bs0 = as0 + 4*GBUF;

    float acc[4][4][4];
    #pragma unroll
    for (int i = 0; i < 4; i++)
        #pragma unroll
        for (int j = 0; j < 4; j++)
            #pragma unroll
            for (int k = 0; k < 4; k++) acc[i][j][k] = 0.f;

    int row2 = tid >> 2, ch = tid & 3;
    auto stage = [&](int it, int buf) {
        int seg = it >> 4;
        int k0b = (it & 15) * 64;
        const char* Ab = (const char*)Ap[seg] + (size_t)i0*1024 + k0b;
        const char* Bb = (const char*)g_uhi + (size_t)j0*1024 + k0b;
        #pragma unroll
        for (int t = 0; t < 2; t++) {
            int r = row2 + t*64;
            cpa16(as0 + buf*GBUF + r*80 + ch*16, Ab + (size_t)r*1024 + ch*16);
            cpa16(bs0 + buf*GBUF + r*80 + ch*16, Bb + (size_t)r*1024 + ch*16);
        }
        CP_COMMIT;
    };

    uint32_t a_off = (uint32_t)((l & 15)*80 + (l >> 4)*16);
    uint32_t b_off = (uint32_t)(((((l >> 4) & 1)*8) + (l & 7))*80 + ((l >> 3) & 1)*16);

    stage(0, 0); stage(1, 1);
    const int NIT = 32;
    for (int it = 0; it < NIT; it++) {
        int buf = it & 3;
        if (it < NIT - 1) CP_WAIT1; else CP_WAIT0;
        __syncthreads();
        if (it + 2 < NIT) stage(it + 2, (it + 2) & 3);
        #pragma unroll
        for (int h = 0; h < 2; h++) {
            uint32_t a[4][4];
            #pragma unroll
            for (int fi = 0; fi < 4; fi++)
                ldm_x4(a[fi], as0 + buf*GBUF + (wr*64 + fi*16)*80 + h*32 + a_off);
            uint32_t bfr[2][4];
            #pragma unroll
            for (int jp = 0; jp < 2; jp++)
                ldm_x4(bfr[jp], bs0 + buf*GBUF + (wc*32 + jp*16)*80 + h*32 + b_off);
            #pragma unroll
            for (int fi = 0; fi < 4; fi++)
                #pragma unroll
                for (int fj = 0; fj < 4; fj++)
                    mma_f16(acc[fi][fj], a[fi], &bfr[fj >> 1][(fj & 1)*2]);
        }
    }

    int g = l >> 2, t2 = (l & 3)*2;
    float local = 0.f;
    #pragma unroll
    for (int fi = 0; fi < 4; fi++) {
        int r0 = i0 + wr*64 + fi*16 + g;
        #pragma unroll
        for (int fj = 0; fj < 4; fj++) {
            int c = j0 + wc*32 + fj*8 + t2;
            float* p = acc[fi][fj];
            if (r0 != c)         local += p[0]*p[0];
            if (r0 != c + 1)     local += p[1]*p[1];
            if (r0 + 8 != c)     local += p[2]*p[2];
            if (r0 + 8 != c + 1) local += p[3]*p[3];
        }
    }
    red[tid] = local;
    __syncthreads();
    for (int o = 128; o > 0; o >>= 1) {
        if (tid < o) red[tid] += red[tid + o];
        __syncthreads();
    }
    if (tid == 0) atomicAdd(out + OFF_DIV, red[0] * (1.f / (float)(MM*MM - MM)));
}

// ---------------- w[n] and similarity loss ----------------
__global__ void k_wsim(const float* __restrict__ ent, float* __restrict__ out) {
    int n = blockIdx.x * blockDim.x + threadIdx.x;
    float local = 0.f;
    if (n < NN) {
        int g = g_argm[n];
        float en = ent[n];
        float entmax = __uint_as_float(g_entmax_bits);
        g_w[n] = (g_rowmaxv[n] / g_colmaxv[g]) * (en / entmax);
        float smax = logf(g_rowmaxv[n]);                  // = max score of row n
        float cosv = smax / fmaxf(g_keynorm[g], 1e-8f);   // ||qr|| == 1
        local = (1.f - cosv) * en;
    }
    __shared__ float red[256];
    red[threadIdx.x] = local;
    __syncthreads();
    for (int o = 128; o > 0; o >>= 1) {
        if (threadIdx.x < o) red[threadIdx.x] += red[threadIdx.x + o];
        __syncthreads();
    }
    if (threadIdx.x == 0) atomicAdd(out + OFF_SIM, red[0]);
}

// ---------------- segment-sum: qupd[g[n], c] += w[n]*qr[n,c] ----------------
__global__ void k_segsum(const float* __restrict__ out) {
    int idx = blockIdx.x * blockDim.x + threadIdx.x;
    if (idx >= BB*CC*HWDIM) return;
    int b = idx >> 19;
    int rem = idx & ((CC*HWDIM) - 1);
    int c = rem >> 10;
    int hw = idx & 1023;
    int n = (b << 10) | hw;
    float val = out[(size_t)b*UQ_STRIDE + rem];           // qr in BCHW layout
    atomicAdd(&g_qupd[(size_t)g_argm[n]*CC + c], g_w[n] * val);
}

// ---------------- updated memory: l2norm(qupd + keys), emit fp32 + fp16 split ----------------
__global__ void k_umem(const float* __restrict__ keys, float* __restrict__ out) {
    int m = blockIdx.x;
    int t = threadIdx.x;   // 128
    float vals[4]; float s = 0.f;
    #pragma unroll
    for (int i = 0; i < 4; i++) {
        int c = t + i*128;
        vals[i] = g_qupd[(size_t)m*CC + c] + keys[(size_t)m*CC + c];
        s += vals[i]*vals[i];
    }
    for (int o = 16; o > 0; o >>= 1) s += __shfl_down_sync(0xffffffffu, s, o);
    __shared__ float red[4]; __shared__ float srn;
    if ((t & 31) == 0) red[t >> 5] = s;
    __syncthreads();
    if (t == 0) srn = 1.f / fmaxf(sqrtf(red[0]+red[1]+red[2]+red[3]), 1e-12f);
    __syncthreads();
    float rn = srn;
    #pragma unroll
    for (int i = 0; i < 4; i++) {
        int c = t + i*128;
        float u = vals[i] * rn;
        out[OFF_UMEM + (size_t)m*CC + c] = u;
        __half hi = __float2half_rn(u);
        g_uhi[(size_t)m*CC + c] = hi;
        g_ulo[(size_t)m*CC + c] = __float2half_rn(u - __half2float(hi));
    }
}

// ---------------- launch ----------------
extern "C" void kernel_launch(void* const* d_in, const int* in_sizes, int n_in,
                              void* d_out, int out_size) {
    const float* q    = (const float*)d_in[0];
    const float* keys = (const float*)d_in[1];
    const float* ent  = (const float*)d_in[2];
    float* out = (float*)d_out;

    cudaFuncSetAttribute(k_score_mma, cudaFuncAttributeMaxDynamicSharedMemorySize, DSMEM_S);
    cudaFuncSetAttribute(k_read_mma,  cudaFuncAttributeMaxDynamicSharedMemorySize, DSMEM_R);
    cudaFuncSetAttribute(k_gram_mma,  cudaFuncAttributeMaxDynamicSharedMemorySize, DSMEM_G);

    k_init<<<(MM*CC + 255)/256, 256>>>(ent, out);
    k_keynorm<<<MM, 128>>>(keys);
    k_keys<<<dim3(MM/32, CC/32), dim3(32, 8)>>>(keys);
    k_rnorm_part<<<dim3(64, 8), 256>>>(q);
    k_qsplit<<<dim3(HWDIM/32, CC/32, BB), dim3(32, 8)>>>(q, out);
    k_score_mma<<<dim3(MM/128, NN/128), 256, DSMEM_S>>>();
    k_fin<<<NN/256, 256>>>();
    k_wsim<<<NN/256, 256>>>(ent, out);
    k_segsum<<<(BB*CC*HWDIM)/256, 256>>>(out);
    k_umem<<<MM, 128>>>(keys, out);
    k_gram_mma<<<dim3(MM/128, MM/128), 256, DSMEM_G>>>(out);
    k_read_mma<<<dim3(CC/128, NN/128), 256, DSMEM_R>>>(out);
}

// round 11
// speedup vs baseline: 3.2274x; 1.1534x over previous
#include <cuda_runtime.h>
#include <cuda_bf16.h>
#include <cuda_fp16.h>
#include <math.h>
#include <stdint.h>

#define BB 16
#define CC 512
#define HWDIM 1024
#define NN 16384            // B*H*W
#define MM 1024
#define UQ_STRIDE (2*CC*HWDIM)          // per-batch stride of updated_query = 1048576

// output offsets (floats)
#define OFF_UQ   ((size_t)0)
#define OFF_UMEM ((size_t)BB*UQ_STRIDE)                  // 16777216
#define OFF_SQ   (OFF_UMEM + (size_t)MM*CC)              // 17301504
#define OFF_SM   (OFF_SQ + (size_t)NN*MM)                // 34078720
#define OFF_DIV  (OFF_SM + (size_t)NN*MM)                // 50855936
#define OFF_SIM  (OFF_DIV + 1)

// ---------------- scratch (static device globals; no runtime alloc) ----------------
__device__ float g_rowmaxv[NN];
__device__ float g_rrowsum[NN];
__device__ int   g_argm[NN];
__device__ float g_w[NN];
__device__ float g_colmaxv[MM];
__device__ float g_rcolsum[MM];
__device__ float g_keynorm[MM];
__device__ float g_qupd[MM*CC];
__device__ unsigned g_entmax_bits;
// atomic merge targets for fused score reductions
__device__ unsigned long long g_rowkey[NN];   // (float_bits(max) << 32) | ~argmax
__device__ float g_rowsumacc[NN];
__device__ unsigned g_colmaxb[MM];
__device__ float g_colsumacc[MM];
// bf16 split operands (score GEMM, 3-term)
__device__ __nv_bfloat16 g_qhi[(size_t)NN*CC];   // qr [N][C] K-major
__device__ __nv_bfloat16 g_qlo[(size_t)NN*CC];
__device__ __nv_bfloat16 g_khi[(size_t)MM*CC];   // keys [M][C]
__device__ __nv_bfloat16 g_klo[(size_t)MM*CC];
// fp16 operands (read/gram GEMMs)
__device__ __half g_kThi[(size_t)CC*MM];         // fp16(keys^T) [C][M]
__device__ __half g_vhi[(size_t)NN*MM];          // fp16(v) [N][M]
__device__ __half g_uhi[(size_t)MM*CC];          // updated_memory split
__device__ __half g_ulo[(size_t)MM*CC];

// ---------------- PTX helpers (base sm_103-legal only) ----------------
__device__ __forceinline__ uint32_t smem_u32(const void* p) {
    uint32_t a;
    asm("{ .reg .u64 t; cvta.to.shared.u64 t, %1; cvt.u32.u64 %0, t; }" : "=r"(a) : "l"(p));
    return a;
}
__device__ __forceinline__ void ldm_x4(uint32_t* r, uint32_t a) {
    asm volatile("ldmatrix.sync.aligned.m8n8.x4.shared.b16 {%0,%1,%2,%3}, [%4];"
        : "=r"(r[0]), "=r"(r[1]), "=r"(r[2]), "=r"(r[3]) : "r"(a));
}
__device__ __forceinline__ void mma_bf16(float* c, const uint32_t* a, const uint32_t* b) {
    asm volatile("mma.sync.aligned.m16n8k16.row.col.f32.bf16.bf16.f32 "
        "{%0,%1,%2,%3}, {%4,%5,%6,%7}, {%8,%9}, {%0,%1,%2,%3};"
        : "+f"(c[0]), "+f"(c[1]), "+f"(c[2]), "+f"(c[3])
        : "r"(a[0]), "r"(a[1]), "r"(a[2]), "r"(a[3]), "r"(b[0]), "r"(b[1]));
}
__device__ __forceinline__ void mma_f16(float* c, const uint32_t* a, const uint32_t* b) {
    asm volatile("mma.sync.aligned.m16n8k16.row.col.f32.f16.f16.f32 "
        "{%0,%1,%2,%3}, {%4,%5,%6,%7}, {%8,%9}, {%0,%1,%2,%3};"
        : "+f"(c[0]), "+f"(c[1]), "+f"(c[2]), "+f"(c[3])
        : "r"(a[0]), "r"(a[1]), "r"(a[2]), "r"(a[3]), "r"(b[0]), "r"(b[1]));
}
__device__ __forceinline__ void cpa16(uint32_t dst, const void* src) {
    asm volatile("cp.async.ca.shared.global [%0], [%1], 16;" :: "r"(dst), "l"(src));
}
#define CP_COMMIT asm volatile("cp.async.commit_group;" ::: "memory")
#define CP_WAIT1  asm volatile("cp.async.wait_group 1;" ::: "memory")
#define CP_WAIT0  asm volatile("cp.async.wait_group 0;" ::: "memory")

// ---------------- small kernels ----------------

__global__ void k_init(const float* __restrict__ ent, float* __restrict__ out) {
    int i = blockIdx.x * blockDim.x + threadIdx.x;
    if (i < MM*CC) g_qupd[i] = 0.f;
    if (i < NN) {
        g_rowkey[i] = 0ull;
        g_rowsumacc[i] = 0.f;
        atomicMax(&g_entmax_bits, __float_as_uint(ent[i])); // entropy > 0
    }
    if (i < MM) {
        g_colmaxb[i] = 0u;
        g_colsumacc[i] = 0.f;
    }
    if (i == 0) {
        out[OFF_DIV] = 0.f;
        out[OFF_SIM] = 0.f;
    }
}

__global__ void k_keynorm(const float* __restrict__ keys) {
    int m = blockIdx.x;
    int t = threadIdx.x;   // 128 threads
    float s = 0.f;
    #pragma unroll
    for (int i = 0; i < 4; i++) {
        float v = keys[(size_t)m*CC + t + i*128];
        s += v*v;
    }
    for (int o = 16; o > 0; o >>= 1) s += __shfl_down_sync(0xffffffffu, s, o);
    __shared__ float red[4];
    if ((t & 31) == 0) red[t >> 5] = s;
    __syncthreads();
    if (t == 0) g_keynorm[m] = sqrtf(red[0] + red[1] + red[2] + red[3]);
}

// keys -> bf16 hi/lo split [M][C] AND fp16(keys^T) [C][M]
__global__ void k_keys(const float* __restrict__ keys) {
    __shared__ float t[32][33];
    int m0 = blockIdx.x * 32, c0 = blockIdx.y * 32;
    int tx = threadIdx.x, ty = threadIdx.y;  // 32 x 8
    #pragma unroll
    for (int i = 0; i < 4; i++) {
        int row = ty + i*8;
        size_t o = (size_t)(m0 + row)*CC + c0 + tx;
        float v = keys[o];
        t[row][tx] = v;
        __nv_bfloat16 hi = __float2bfloat16(v);
        g_khi[o] = hi;
        g_klo[o] = __float2bfloat16(v - __bfloat162float(hi));
    }
    __syncthreads();
    #pragma unroll
    for (int i = 0; i < 4; i++) {
        float v = t[tx][ty + i*8];        // = keys[m0+tx][c0+ty+i*8]
        g_kThi[(size_t)(c0 + ty + i*8)*MM + m0 + tx] = __float2half_rn(v);
    }
}

// ---------------- fused: load q column-block, compute norms, write qr + bf16 split ----------------
#define QPITCH 36
#define QSMEM (512*QPITCH*4 + 128)

__global__ void __launch_bounds__(256) k_qnorm(const float* __restrict__ q, float* __restrict__ out) {
    extern __shared__ float qs[];          // [512][QPITCH] + rn[32]
    float* rn = qs + 512*QPITCH;
    int b = blockIdx.y;
    int hw0 = blockIdx.x * 32;
    int tid = threadIdx.x;
    int col = tid & 31, r0 = tid >> 5;     // 8 row-groups
    const float* src = q + (size_t)b*CC*HWDIM + hw0;
    #pragma unroll 8
    for (int i = 0; i < 64; i++) {
        int row = r0 + i*8;
        qs[row*QPITCH + col] = src[(size_t)row*HWDIM + col];
    }
    __syncthreads();
    // norms: 8 warps x 4 hw; 8 lanes per hw
    int w = tid >> 5, l = tid & 31;
    {
        int hwl = w*4 + (l >> 3);
        int cb = l & 7;
        float s = 0.f;
        #pragma unroll 8
        for (int k = 0; k < 64; k++) {
            float v = qs[(cb + k*8)*QPITCH + hwl];
            s += v*v;
        }
        s += __shfl_xor_sync(0xffffffffu, s, 1);
        s += __shfl_xor_sync(0xffffffffu, s, 2);
        s += __shfl_xor_sync(0xffffffffu, s, 4);
        if (cb == 0) rn[hwl] = 1.f / fmaxf(sqrtf(s), 1e-12f);
    }
    __syncthreads();
    // write fp32 qr (BCHW layout)
    float* dst = out + (size_t)b*UQ_STRIDE + hw0;
    float rcol = rn[col];
    #pragma unroll 8
    for (int i = 0; i < 64; i++) {
        int row = r0 + i*8;
        dst[(size_t)row*HWDIM + col] = qs[row*QPITCH + col] * rcol;
    }
    // write transposed bf16 hi/lo [n][c]: warp per hw, lanes over c
    #pragma unroll
    for (int i = 0; i < 4; i++) {
        int hwl = w + i*8;
        int n = (b << 10) | (hw0 + hwl);
        float rr = rn[hwl];
        #pragma unroll
        for (int cb = l; cb < 512; cb += 32) {
            float v = qs[cb*QPITCH + hwl] * rr;
            __nv_bfloat16 hi = __float2bfloat16(v);
            g_qhi[(size_t)n*CC + cb] = hi;
            g_qlo[(size_t)n*CC + cb] = __float2bfloat16(v - __bfloat162float(hi));
        }
    }
}

// ---------------- HMMA score GEMM: co-staged bf16 hi/lo, 3 terms per staged chunk ----------------
// A/B buffer row: [hi 64B | lo 64B | pad 16B] = 144B; ring-2, prefetch AFTER consume (race-free)
#define SBUF 18432      // 128 * 144
#define DSMEM_S (4*SBUF)  // 2 A + 2 B = 73728

__global__ void __launch_bounds__(256, 2) k_score_mma() {
    extern __shared__ __align__(16) char dsm[];
    int tid = threadIdx.x, l = tid & 31, w = tid >> 5;
    int wr = w >> 2, wc = w & 3;
    int m0 = blockIdx.x * 128, n0 = blockIdx.y * 128;
    uint32_t as0 = smem_u32(dsm);
    uint32_t bs0 = as0 + 2*SBUF;

    float acc[4][4][4];
    #pragma unroll
    for (int i = 0; i < 4; i++)
        #pragma unroll
        for (int j = 0; j < 4; j++)
            #pragma unroll
            for (int k = 0; k < 4; k++) acc[i][j][k] = 0.f;

    auto stage = [&](int s, int buf) {
        #pragma unroll
        for (int t = 0; t < 4; t++) {
            int idx = tid + t*256;
            int r = idx >> 3, c = idx & 7;
            const char* srcA = (c < 4)
                ? (const char*)g_qhi + (size_t)(n0 + r)*1024 + s*64 + c*16
                : (const char*)g_qlo + (size_t)(n0 + r)*1024 + s*64 + (c-4)*16;
            cpa16(as0 + buf*SBUF + r*144 + c*16, srcA);
            const char* srcB = (c < 4)
                ? (const char*)g_khi + (size_t)(m0 + r)*1024 + s*64 + c*16
                : (const char*)g_klo + (size_t)(m0 + r)*1024 + s*64 + (c-4)*16;
            cpa16(bs0 + buf*SBUF + r*144 + c*16, srcB);
        }
        CP_COMMIT;
    };

    uint32_t a_off = (uint32_t)((l & 15)*144 + (l >> 4)*16);
    uint32_t b_off = (uint32_t)(((((l >> 4) & 1)*8) + (l & 7))*144 + ((l >> 3) & 1)*16);

    stage(0, 0); stage(1, 1);
    const int NIT = 16;
    for (int it = 0; it < NIT; it++) {
        int buf = it & 1;
        if (it < NIT - 1) CP_WAIT1; else CP_WAIT0;
        __syncthreads();
        #pragma unroll
        for (int h = 0; h < 2; h++) {
            uint32_t afr[4][4], b0f[2][4], b1f[2][4];
            // A-hi, B-hi
            #pragma unroll
            for (int fi = 0; fi < 4; fi++)
                ldm_x4(afr[fi], as0 + buf*SBUF + (wr*64 + fi*16)*144 + h*32 + a_off);
            #pragma unroll
            for (int jp = 0; jp < 2; jp++)
                ldm_x4(b0f[jp], bs0 + buf*SBUF + (wc*32 + jp*16)*144 + h*32 + b_off);
            #pragma unroll
            for (int fi = 0; fi < 4; fi++)
                #pragma unroll
                for (int fj = 0; fj < 4; fj++)
                    mma_bf16(acc[fi][fj], afr[fi], &b0f[fj >> 1][(fj & 1)*2]);   // hi*hi
            // B-lo (A-hi still live)
            #pragma unroll
            for (int jp = 0; jp < 2; jp++)
                ldm_x4(b1f[jp], bs0 + buf*SBUF + (wc*32 + jp*16)*144 + 64 + h*32 + b_off);
            #pragma unroll
            for (int fi = 0; fi < 4; fi++)
                #pragma unroll
                for (int fj = 0; fj < 4; fj++)
                    mma_bf16(acc[fi][fj], afr[fi], &b1f[fj >> 1][(fj & 1)*2]);   // hi*lo
            // A-lo (reuse B-hi)
            #pragma unroll
            for (int fi = 0; fi < 4; fi++)
                ldm_x4(afr[fi], as0 + buf*SBUF + (wr*64 + fi*16)*144 + 64 + h*32 + a_off);
            #pragma unroll
            for (int fi = 0; fi < 4; fi++)
                #pragma unroll
                for (int fj = 0; fj < 4; fj++)
                    mma_bf16(acc[fi][fj], afr[fi], &b0f[fj >> 1][(fj & 1)*2]);   // lo*hi
        }
        __syncthreads();   // all reads of buf done before refill
        if (it + 2 < NIT) stage(it + 2, buf);
    }

    // ---- epilogue: exp, fp16 v, fused row/col reductions ----
    int g = l >> 2, t2 = (l & 3)*2;
    float rsum[8], rmaxv[8]; int rargm[8];
    float csum[8], cmaxv[8];
    #pragma unroll
    for (int i = 0; i < 8; i++) { rsum[i]=0.f; rmaxv[i]=0.f; rargm[i]=0; csum[i]=0.f; cmaxv[i]=0.f; }

    #pragma unroll
    for (int fi = 0; fi < 4; fi++) {
        int r0 = n0 + wr*64 + fi*16 + g;
        #pragma unroll
        for (int fj = 0; fj < 4; fj++) {
            int c = m0 + wc*32 + fj*8 + t2;
            float* p = acc[fi][fj];
            #pragma unroll
            for (int hh = 0; hh < 2; hh++) {
                int r = r0 + hh*8;
                int ridx = fi*2 + hh;
                float e0 = __expf(p[hh*2 + 0]);
                float e1 = __expf(p[hh*2 + 1]);
                size_t o = (size_t)r*MM + c;
                __half2 hv; hv.x = __float2half_rn(e0); hv.y = __float2half_rn(e1);
                *(__half2*)(g_vhi + o) = hv;
                rsum[ridx] += e0 + e1;
                if (e0 > rmaxv[ridx]) { rmaxv[ridx] = e0; rargm[ridx] = c; }
                if (e1 > rmaxv[ridx]) { rmaxv[ridx] = e1; rargm[ridx] = c + 1; }
                int cidx = fj*2;
                csum[cidx]   += e0; cmaxv[cidx]   = fmaxf(cmaxv[cidx],   e0);
                csum[cidx+1] += e1; cmaxv[cidx+1] = fmaxf(cmaxv[cidx+1], e1);
            }
        }
    }
    // row reduce across lanes sharing the row (xor 1,2 within lane quad)
    #pragma unroll
    for (int o = 1; o <= 2; o <<= 1) {
        #pragma unroll
        for (int i = 0; i < 8; i++) {
            float os = __shfl_xor_sync(0xffffffffu, rsum[i], o);
            float om = __shfl_xor_sync(0xffffffffu, rmaxv[i], o);
            int   oa = __shfl_xor_sync(0xffffffffu, rargm[i], o);
            rsum[i] += os;
            if (om > rmaxv[i] || (om == rmaxv[i] && oa < rargm[i])) { rmaxv[i] = om; rargm[i] = oa; }
        }
    }
    // col reduce across lanes sharing the col (xor 4,8,16)
    #pragma unroll
    for (int o = 4; o <= 16; o <<= 1) {
        #pragma unroll
        for (int i = 0; i < 8; i++) {
            csum[i]  += __shfl_xor_sync(0xffffffffu, csum[i], o);
            cmaxv[i]  = fmaxf(cmaxv[i], __shfl_xor_sync(0xffffffffu, cmaxv[i], o));
        }
    }
    // smem merge (reuse pipeline smem)
    float* s_rs = (float*)dsm;
    float* s_rm = s_rs + 128;
    int*   s_ra = (int*)(s_rm + 128);
    float* s_cs = (float*)(s_ra + 128);
    float* s_cm = s_cs + 128;
    __syncthreads();
    for (int ws = 0; ws < 4; ws++) {          // stage over wc; wr rows disjoint
        if (wc == ws && (l & 3) == 0) {
            #pragma unroll
            for (int i = 0; i < 8; i++) {
                int r = wr*64 + (i >> 1)*16 + (i & 1)*8 + g;
                if (ws == 0) { s_rs[r] = rsum[i]; s_rm[r] = rmaxv[i]; s_ra[r] = rargm[i]; }
                else {
                    s_rs[r] += rsum[i];
                    if (rmaxv[i] > s_rm[r] || (rmaxv[i] == s_rm[r] && rargm[i] < s_ra[r])) {
                        s_rm[r] = rmaxv[i]; s_ra[r] = rargm[i];
                    }
                }
            }
        }
        __syncthreads();
    }
    for (int ws = 0; ws < 2; ws++) {          // stage over wr; wc cols disjoint
        if (wr == ws && l < 4) {
            #pragma unroll
            for (int i = 0; i < 8; i++) {
                int cl = wc*32 + (i >> 1)*8 + t2 + (i & 1);
                if (ws == 0) { s_cs[cl] = csum[i]; s_cm[cl] = cmaxv[i]; }
                else { s_cs[cl] += csum[i]; s_cm[cl] = fmaxf(s_cm[cl], cmaxv[i]); }
            }
        }
        __syncthreads();
    }
    if (tid < 128) {
        int n = n0 + tid;
        atomicAdd(&g_rowsumacc[n], s_rs[tid]);
        unsigned long long key =
            ((unsigned long long)__float_as_uint(s_rm[tid]) << 32) | (unsigned)(~(unsigned)s_ra[tid]);
        atomicMax(&g_rowkey[n], key);
        int m = m0 + tid;
        atomicAdd(&g_colsumacc[m], s_cs[tid]);
        atomicMax(&g_colmaxb[m], __float_as_uint(s_cm[tid]));
    }
}

// ---------------- finalize reductions: unpack argmax, reciprocals ----------------
__global__ void k_fin() {
    int n = blockIdx.x * blockDim.x + threadIdx.x;
    if (n < NN) {
        unsigned long long key = g_rowkey[n];
        g_rowmaxv[n] = __uint_as_float((unsigned)(key >> 32));
        g_argm[n]    = (int)(~(unsigned)key);
        g_rrowsum[n] = 1.f / g_rowsumacc[n];
    }
    if (n < MM) {
        g_colmaxv[n] = __uint_as_float(g_colmaxb[n]);
        g_rcolsum[n] = 1.f / g_colsumacc[n];
    }
}

// ---------------- HMMA read GEMM (fp16, 1-term) + fused sq/sm write ----------------
#define RBUF 10240      // 128 * 80
#define DSMEM_R (6*RBUF)   // 3 A + 3 B = 61440, ring-3

__global__ void __launch_bounds__(256, 2) k_read_mma(float* __restrict__ out) {
    extern __shared__ __align__(16) char dsm[];
    int tid = threadIdx.x, l = tid & 31, w = tid >> 5;
    int wr = w >> 2, wc = w & 3;
    int c0 = blockIdx.x * 128, n0 = blockIdx.y * 128;
    uint32_t as0 = smem_u32(dsm);
    uint32_t bs0 = as0 + 3*RBUF;

    float acc[4][4][4];
    #pragma unroll
    for (int i = 0; i < 4; i++)
        #pragma unroll
        for (int j = 0; j < 4; j++)
            #pragma unroll
            for (int k = 0; k < 4; k++) acc[i][j][k] = 0.f;

    auto stage = [&](int s, int buf) {
        #pragma unroll
        for (int t = 0; t < 2; t++) {
            int idx = tid + t*256;
            int r = idx >> 2, c = idx & 3;
            cpa16(as0 + buf*RBUF + r*80 + c*16,
                  (const char*)g_vhi + (size_t)(n0 + r)*2048 + s*64 + c*16);
            cpa16(bs0 + buf*RBUF + r*80 + c*16,
                  (const char*)g_kThi + (size_t)(c0 + r)*2048 + s*64 + c*16);
        }
        CP_COMMIT;
    };

    uint32_t a_off = (uint32_t)((l & 15)*80 + (l >> 4)*16);
    uint32_t b_off = (uint32_t)(((((l >> 4) & 1)*8) + (l & 7))*80 + ((l >> 3) & 1)*16);

    stage(0, 0); stage(1, 1);
    const int NIT = 32;               // 1024 m / 32 per stage
    for (int it = 0; it < NIT; it++) {
        int buf = it % 3;
        if (it < NIT - 1) CP_WAIT1; else CP_WAIT0;
        __syncthreads();
        if (it + 2 < NIT) stage(it + 2, (it + 2) % 3);
        #pragma unroll
        for (int h = 0; h < 2; h++) {
            uint32_t a[4][4], bfr[2][4];
            #pragma unroll
            for (int jp = 0; jp < 2; jp++)
                ldm_x4(bfr[jp], bs0 + buf*RBUF + (wc*32 + jp*16)*80 + h*32 + b_off);
            #pragma unroll
            for (int fi = 0; fi < 4; fi++)
                ldm_x4(a[fi], as0 + buf*RBUF + (wr*64 + fi*16)*80 + h*32 + a_off);
            #pragma unroll
            for (int fi = 0; fi < 4; fi++)
                #pragma unroll
                for (int fj = 0; fj < 4; fj++)
                    mma_f16(acc[fi][fj], a[fi], &bfr[fj >> 1][(fj & 1)*2]);
        }
        // fused sq/sm write: each c0-block writes its quarter of the 128 n-rows
        if (tid < 128) {
            int r = (blockIdx.x << 5) + (tid >> 2);
            int c = tid & 3;
            const __half2* hp = (const __half2*)(dsm + buf*RBUF + r*80 + c*16);
            int n = n0 + r;
            int m = it*32 + c*8;
            float rr = g_rrowsum[n];
            float4 rc0 = *(const float4*)(g_rcolsum + m);
            float4 rc1 = *(const float4*)(g_rcolsum + m + 4);
            float vv[8];
            #pragma unroll
            for (int j = 0; j < 4; j++) {
                float2 hf = __half22float2(hp[j]);
                vv[j*2]   = hf.x;
                vv[j*2+1] = hf.y;
            }
            size_t o = (size_t)n*MM + m;
            float4 sq0 = make_float4(vv[0]*rc0.x, vv[1]*rc0.y, vv[2]*rc0.z, vv[3]*rc0.w);
            float4 sq1 = make_float4(vv[4]*rc1.x, vv[5]*rc1.y, vv[6]*rc1.z, vv[7]*rc1.w);
            *(float4*)(out + OFF_SQ + o)     = sq0;
            *(float4*)(out + OFF_SQ + o + 4) = sq1;
            float4 sm0 = make_float4(vv[0]*rr, vv[1]*rr, vv[2]*rr, vv[3]*rr);
            float4 sm1 = make_float4(vv[4]*rr, vv[5]*rr, vv[6]*rr, vv[7]*rr);
            *(float4*)(out + OFF_SM + o)     = sm0;
            *(float4*)(out + OFF_SM + o + 4) = sm1;
        }
    }

    // epilogue: scale by rrowsum, write BCHW channels [C, 2C)
    int g = l >> 2, t2 = (l & 3)*2;
    int b = n0 >> 10;
    int hwb = n0 & 1023;
    float* obase = out + (size_t)b*UQ_STRIDE;
    #pragma unroll
    for (int fi = 0; fi < 4; fi++) {
        int rl0 = wr*64 + fi*16 + g;
        float rs0 = g_rrowsum[n0 + rl0];
        float rs1 = g_rrowsum[n0 + rl0 + 8];
        #pragma unroll
        for (int fj = 0; fj < 4; fj++) {
            int c = c0 + wc*32 + fj*8 + t2;
            float* p = acc[fi][fj];
            size_t a0 = (size_t)(CC + c)*HWDIM + hwb + rl0;
            obase[a0]              = p[0] * rs0;
            obase[a0 + HWDIM]      = p[1] * rs0;
            obase[a0 + 8]          = p[2] * rs1;
            obase[a0 + HWDIM + 8]  = p[3] * rs1;
        }
    }
}

// ---------------- HMMA gram GEMM (fp16, 2-term): diversity(updated_memory) ----------------
#define GBUF 10240      // 128 rows * 80B
#define DSMEM_G (8*GBUF)

__global__ void __launch_bounds__(256, 2) k_gram_mma(float* __restrict__ out) {
    extern __shared__ __align__(16) char dsm[];
    __shared__ float red[256];
    int tid = threadIdx.x, l = tid & 31, w = tid >> 5;
    int wr = w >> 2, wc = w & 3;
    int j0 = blockIdx.x * 128, i0 = blockIdx.y * 128;
    const __half* Ap[2] = {g_uhi, g_ulo};
    uint32_t as0 = smem_u32(dsm);
    uint32_t bs0 = as0 + 4*GBUF;

    float acc[4][4][4];
    #pragma unroll
    for (int i = 0; i < 4; i++)
        #pragma unroll
        for (int j = 0; j < 4; j++)
            #pragma unroll
            for (int k = 0; k < 4; k++) acc[i][j][k] = 0.f;

    int row2 = tid >> 2, ch = tid & 3;
    auto stage = [&](int it, int buf) {
        int seg = it >> 4;
        int k0b = (it & 15) * 64;
        const char* Ab = (const char*)Ap[seg] + (size_t)i0*1024 + k0b;
        const char* Bb = (const char*)g_uhi + (size_t)j0*1024 + k0b;
        #pragma unroll
        for (int t = 0; t < 2; t++) {
            int r = row2 + t*64;
            cpa16(as0 + buf*GBUF + r*80 + ch*16, Ab + (size_t)r*1024 + ch*16);
            cpa16(bs0 + buf*GBUF + r*80 + ch*16, Bb + (size_t)r*1024 + ch*16);
        }
        CP_COMMIT;
    };

    uint32_t a_off = (uint32_t)((l & 15)*80 + (l >> 4)*16);
    uint32_t b_off = (uint32_t)(((((l >> 4) & 1)*8) + (l & 7))*80 + ((l >> 3) & 1)*16);

    stage(0, 0); stage(1, 1);
    const int NIT = 32;
    for (int it = 0; it < NIT; it++) {
        int buf = it & 3;
        if (it < NIT - 1) CP_WAIT1; else CP_WAIT0;
        __syncthreads();
        if (it + 2 < NIT) stage(it + 2, (it + 2) & 3);
        #pragma unroll
        for (int h = 0; h < 2; h++) {
            uint32_t a[4][4];
            #pragma unroll
            for (int fi = 0; fi < 4; fi++)
                ldm_x4(a[fi], as0 + buf*GBUF + (wr*64 + fi*16)*80 + h*32 + a_off);
            uint32_t bfr[2][4];
            #pragma unroll
            for (int jp = 0; jp < 2; jp++)
                ldm_x4(bfr[jp], bs0 + buf*GBUF + (wc*32 + jp*16)*80 + h*32 + b_off);
            #pragma unroll
            for (int fi = 0; fi < 4; fi++)
                #pragma unroll
                for (int fj = 0; fj < 4; fj++)
                    mma_f16(acc[fi][fj], a[fi], &bfr[fj >> 1][(fj & 1)*2]);
        }
    }

    int g = l >> 2, t2 = (l & 3)*2;
    float local = 0.f;
    #pragma unroll
    for (int fi = 0; fi < 4; fi++) {
        int r0 = i0 + wr*64 + fi*16 + g;
        #pragma unroll
        for (int fj = 0; fj < 4; fj++) {
            int c = j0 + wc*32 + fj*8 + t2;
            float* p = acc[fi][fj];
            if (r0 != c)         local += p[0]*p[0];
            if (r0 != c + 1)     local += p[1]*p[1];
            if (r0 + 8 != c)     local += p[2]*p[2];
            if (r0 + 8 != c + 1) local += p[3]*p[3];
        }
    }
    red[tid] = local;
    __syncthreads();
    for (int o = 128; o > 0; o >>= 1) {
        if (tid < o) red[tid] += red[tid + o];
        __syncthreads();
    }
    if (tid == 0) atomicAdd(out + OFF_DIV, red[0] * (1.f / (float)(MM*MM - MM)));
}

// ---------------- w[n] and similarity loss ----------------
__global__ void k_wsim(const float* __restrict__ ent, float* __restrict__ out) {
    int n = blockIdx.x * blockDim.x + threadIdx.x;
    float local = 0.f;
    if (n < NN) {
        int g = g_argm[n];
        float en = ent[n];
        float entmax = __uint_as_float(g_entmax_bits);
        g_w[n] = (g_rowmaxv[n] / g_colmaxv[g]) * (en / entmax);
        float smax = logf(g_rowmaxv[n]);                  // = max score of row n
        float cosv = smax / fmaxf(g_keynorm[g], 1e-8f);   // ||qr|| == 1
        local = (1.f - cosv) * en;
    }
    __shared__ float red[256];
    red[threadIdx.x] = local;
    __syncthreads();
    for (int o = 128; o > 0; o >>= 1) {
        if (threadIdx.x < o) red[threadIdx.x] += red[threadIdx.x + o];
        __syncthreads();
    }
    if (threadIdx.x == 0) atomicAdd(out + OFF_SIM, red[0]);
}

// ---------------- segment-sum: qupd[g[n], c] += w[n]*qr[n,c] ----------------
__global__ void k_segsum(const float* __restrict__ out) {
    int idx = blockIdx.x * blockDim.x + threadIdx.x;
    if (idx >= BB*CC*HWDIM) return;
    int b = idx >> 19;
    int rem = idx & ((CC*HWDIM) - 1);
    int c = rem >> 10;
    int hw = idx & 1023;
    int n = (b << 10) | hw;
    float val = out[(size_t)b*UQ_STRIDE + rem];           // qr in BCHW layout
    atomicAdd(&g_qupd[(size_t)g_argm[n]*CC + c], g_w[n] * val);
}

// ---------------- updated memory: l2norm(qupd + keys), emit fp32 + fp16 split ----------------
__global__ void k_umem(const float* __restrict__ keys, float* __restrict__ out) {
    int m = blockIdx.x;
    int t = threadIdx.x;   // 128
    float vals[4]; float s = 0.f;
    #pragma unroll
    for (int i = 0; i < 4; i++) {
        int c = t + i*128;
        vals[i] = g_qupd[(size_t)m*CC + c] + keys[(size_t)m*CC + c];
        s += vals[i]*vals[i];
    }
    for (int o = 16; o > 0; o >>= 1) s += __shfl_down_sync(0xffffffffu, s, o);
    __shared__ float red[4]; __shared__ float srn;
    if ((t & 31) == 0) red[t >> 5] = s;
    __syncthreads();
    if (t == 0) srn = 1.f / fmaxf(sqrtf(red[0]+red[1]+red[2]+red[3]), 1e-12f);
    __syncthreads();
    float rn = srn;
    #pragma unroll
    for (int i = 0; i < 4; i++) {
        int c = t + i*128;
        float u = vals[i] * rn;
        out[OFF_UMEM + (size_t)m*CC + c] = u;
        __half hi = __float2half_rn(u);
        g_uhi[(size_t)m*CC + c] = hi;
        g_ulo[(size_t)m*CC + c] = __float2half_rn(u - __half2float(hi));
    }
}

// ---------------- launch ----------------
extern "C" void kernel_launch(void* const* d_in, const int* in_sizes, int n_in,
                              void* d_out, int out_size) {
    const float* q    = (const float*)d_in[0];
    const float* keys = (const float*)d_in[1];
    const float* ent  = (const float*)d_in[2];
    float* out = (float*)d_out;

    cudaFuncSetAttribute(k_qnorm,     cudaFuncAttributeMaxDynamicSharedMemorySize, QSMEM);
    cudaFuncSetAttribute(k_score_mma, cudaFuncAttributeMaxDynamicSharedMemorySize, DSMEM_S);
    cudaFuncSetAttribute(k_read_mma,  cudaFuncAttributeMaxDynamicSharedMemorySize, DSMEM_R);
    cudaFuncSetAttribute(k_gram_mma,  cudaFuncAttributeMaxDynamicSharedMemorySize, DSMEM_G);

    k_init<<<(MM*CC + 255)/256, 256>>>(ent, out);
    k_keynorm<<<MM, 128>>>(keys);
    k_keys<<<dim3(MM/32, CC/32), dim3(32, 8)>>>(keys);
    k_qnorm<<<dim3(HWDIM/32, BB), 256, QSMEM>>>(q, out);
    k_score_mma<<<dim3(MM/128, NN/128), 256, DSMEM_S>>>();
    k_fin<<<NN/256, 256>>>();
    k_wsim<<<NN/256, 256>>>(ent, out);
    k_segsum<<<(BB*CC*HWDIM)/256, 256>>>(out);
    k_umem<<<MM, 128>>>(keys, out);
    k_gram_mma<<<dim3(MM/128, MM/128), 256, DSMEM_G>>>(out);
    k_read_mma<<<dim3(CC/128, NN/128), 256, DSMEM_R>>>(out);
}